// round 2
// baseline (speedup 1.0000x reference)
#include <cuda_runtime.h>
#include <math.h>

#define B_SI 4.1491f
#define B_O  5.803f
#define CUTOFF 3.5f
#define PI_F 3.14159274101257324f   // (float)M_PI

#define TI 128
#define TJ 512

// ---------------- device globals (scratch; no allocations allowed) ----------------
__device__ float  g_inv[9];
__device__ float  g_cellm[9];
__device__ float  g_rho, g_meanb, g_r0, g_dr;
__device__ double g_hist[256];
__device__ double g_qsum, g_vfsum;

// ---------------- prep: inverse cell, det, mean b, zero accumulators --------------
__global__ void prep_kernel(const float* __restrict__ cell,
                            const float* __restrict__ rbins,
                            const int*   __restrict__ species, int n) {
    int t = threadIdx.x;
    for (int k = t; k < 256; k += 256) g_hist[k] = 0.0;
    if (t == 0) {
        g_qsum = 0.0; g_vfsum = 0.0;
        float a[9];
        #pragma unroll
        for (int k = 0; k < 9; k++) { a[k] = cell[k]; g_cellm[k] = cell[k]; }
        float c00 = a[4]*a[8] - a[5]*a[7];
        float c01 = a[5]*a[6] - a[3]*a[8];
        float c02 = a[3]*a[7] - a[4]*a[6];
        float det = a[0]*c00 + a[1]*c01 + a[2]*c02;
        float id  = 1.0f / det;
        g_inv[0] = c00*id;
        g_inv[3] = c01*id;
        g_inv[6] = c02*id;
        g_inv[1] = (a[2]*a[7] - a[1]*a[8])*id;
        g_inv[4] = (a[0]*a[8] - a[2]*a[6])*id;
        g_inv[7] = (a[1]*a[6] - a[0]*a[7])*id;
        g_inv[2] = (a[1]*a[5] - a[2]*a[4])*id;
        g_inv[5] = (a[2]*a[3] - a[0]*a[5])*id;
        g_inv[8] = (a[0]*a[4] - a[1]*a[3])*id;
        g_rho = (float)n / fabsf(det);
        g_r0  = rbins[0];
        g_dr  = rbins[1] - rbins[0];
    }
    __shared__ float sb[256];
    float s = 0.0f;
    for (int i = t; i < n; i += 256) s += (species[i] == 0) ? B_SI : B_O;
    sb[t] = s; __syncthreads();
    for (int o = 128; o > 0; o >>= 1) { if (t < o) sb[t] += sb[t + o]; __syncthreads(); }
    if (t == 0) g_meanb = sb[0] / (float)n;
}

// ---------------- pair histogram: upper triangle (j>i), weight x2 -----------------
__global__ void __launch_bounds__(256)
pair_kernel(const float* __restrict__ pos, const int* __restrict__ species,
            int n, int nbins) {
    int iBase = blockIdx.x * TI;
    int jBase = blockIdx.y * TJ;
    // tile contains pairs with j > i only if max j in tile exceeds min i in tile
    if (jBase + TJ - 1 <= iBase) return;

    __shared__ float4 fj[TJ];        // (fx, fy, fz, b)
    __shared__ float  sh_hist[256];

    int t = threadIdx.x;
    for (int k = t; k < 256; k += 256) sh_hist[k] = 0.0f;

    const float i0v = g_inv[0], i1v = g_inv[1], i2v = g_inv[2];
    const float i3v = g_inv[3], i4v = g_inv[4], i5v = g_inv[5];
    const float i6v = g_inv[6], i7v = g_inv[7], i8v = g_inv[8];
    const float c0 = g_cellm[0], c1 = g_cellm[1], c2 = g_cellm[2];
    const float c3 = g_cellm[3], c4 = g_cellm[4], c5 = g_cellm[5];
    const float c6 = g_cellm[6], c7 = g_cellm[7], c8 = g_cellm[8];
    const float r0 = g_r0, dr = g_dr;
    const float rmax = r0 + (float)(nbins - 1) * dr;
    const float d2max = rmax * rmax + 0.01f;   // safe over-cover of the valid window
    const float invdr = 1.0f / dr;

    for (int k = t; k < TJ; k += 256) {
        int j = jBase + k;
        float4 v;
        if (j < n) {
            float px = pos[3*j], py = pos[3*j+1], pz = pos[3*j+2];
            v.x = px*i0v + py*i3v + pz*i6v;
            v.y = px*i1v + py*i4v + pz*i7v;
            v.z = px*i2v + py*i5v + pz*i8v;
            v.w = (species[j] == 0) ? B_SI : B_O;
        } else { v.x = 1e18f; v.y = 1e18f; v.z = 1e18f; v.w = 0.0f; }
        fj[k] = v;
    }
    __syncthreads();

    int ii = t & (TI - 1);
    int jg = t >> 7;                 // 0..1, each covers 256 of 512 j's
    int i  = iBase + ii;
    float fix = 0.f, fiy = 0.f, fiz = 0.f, bi = 0.f;
    bool iok = (i < n);
    if (iok) {
        float px = pos[3*i], py = pos[3*i+1], pz = pos[3*i+2];
        fix = px*i0v + py*i3v + pz*i6v;
        fiy = px*i1v + py*i4v + pz*i7v;
        fiz = px*i2v + py*i5v + pz*i8v;
        bi  = (species[i] == 0) ? B_SI : B_O;
    }

    if (iok) {
        for (int k = jg; k < TJ; k += 2) {
            int j = jBase + k;
            if (j >= n || j <= i) continue;
            float4 pj = fj[k];
            float fx = fix - pj.x;
            float fy = fiy - pj.y;
            float fz = fiz - pj.z;
            fx -= rintf(fx); fy -= rintf(fy); fz -= rintf(fz);
            float dx = fx*c0 + fy*c3 + fz*c6;
            float dy = fx*c1 + fy*c4 + fz*c7;
            float dz = fx*c2 + fy*c5 + fz*c8;
            float d2 = dx*dx + dy*dy + dz*dz;
            if (d2 < d2max) {
                float dist = sqrtf(d2);
                float x  = (dist - r0) * invdr;
                float xf = floorf(x);
                int   b0 = (int)xf;
                if (b0 >= 0 && b0 < nbins - 1) {
                    float f = x - xf;
                    float w = 2.0f * bi * pj.w;     // x2 for (i,j)+(j,i)
                    atomicAdd(&sh_hist[b0],     w * (1.0f - f));
                    atomicAdd(&sh_hist[b0 + 1], w * f);
                }
            }
        }
    }
    __syncthreads();
    for (int k = t; k < nbins; k += 256)
        if (sh_hist[k] != 0.0f) atomicAdd(&g_hist[k], (double)sh_hist[k]);
}

// ---------------- tetrahedral order parameter: one warp per atom ------------------
__global__ void __launch_bounds__(256)
qtet_kernel(const float* __restrict__ pos, const int* __restrict__ species, int n) {
    int gw   = (blockIdx.x * blockDim.x + threadIdx.x) >> 5;
    int lane = threadIdx.x & 31;
    if (gw >= n) return;
    int i = gw;
    if (species[i] != 0) return;     // only Si centres contribute

    const float i0v = g_inv[0], i1v = g_inv[1], i2v = g_inv[2];
    const float i3v = g_inv[3], i4v = g_inv[4], i5v = g_inv[5];
    const float i6v = g_inv[6], i7v = g_inv[7], i8v = g_inv[8];
    const float c0 = g_cellm[0], c1 = g_cellm[1], c2 = g_cellm[2];
    const float c3 = g_cellm[3], c4 = g_cellm[4], c5 = g_cellm[5];
    const float c6 = g_cellm[6], c7 = g_cellm[7], c8 = g_cellm[8];

    float pix = pos[3*i], piy = pos[3*i+1], piz = pos[3*i+2];

    const float INF = 3.402823466e38f;
    float bd2[4] = {INF, INF, INF, INF};
    int   bj [4] = {0x7fffffff, 0x7fffffff, 0x7fffffff, 0x7fffffff};

    for (int j = lane; j < n; j += 32) {
        if (j == i || species[j] == 0) continue;     // O neighbours only
        float dx0 = pix - pos[3*j];
        float dy0 = piy - pos[3*j+1];
        float dz0 = piz - pos[3*j+2];
        float fx = dx0*i0v + dy0*i3v + dz0*i6v;
        float fy = dx0*i1v + dy0*i4v + dz0*i7v;
        float fz = dx0*i2v + dy0*i5v + dz0*i8v;
        fx -= rintf(fx); fy -= rintf(fy); fz -= rintf(fz);
        float dx = fx*c0 + fy*c3 + fz*c6;
        float dy = fx*c1 + fy*c4 + fz*c7;
        float dz = fx*c2 + fy*c5 + fz*c8;
        float d2 = dx*dx + dy*dy + dz*dz;
        if (d2 < bd2[3]) {
            float dd = d2; int jj = j;
            #pragma unroll
            for (int k = 0; k < 4; k++) {
                if (dd < bd2[k]) {
                    float td = bd2[k]; bd2[k] = dd; dd = td;
                    int   tj = bj[k];  bj[k]  = jj; jj = tj;
                }
            }
        }
    }

    // merge per-lane top-4 into warp top-4 (4 rounds of arg-min, index tie-break)
    int ptr = 0;
    float seld2[4]; int selj[4];
    #pragma unroll
    for (int r = 0; r < 4; r++) {
        float mv = (ptr < 4) ? bd2[ptr] : INF;
        int   mj = (ptr < 4) ? bj[ptr]  : 0x7fffffff;
        int   ml = lane;
        #pragma unroll
        for (int o = 16; o > 0; o >>= 1) {
            float ov = __shfl_down_sync(0xffffffffu, mv, o);
            int   oj = __shfl_down_sync(0xffffffffu, mj, o);
            int   ol = __shfl_down_sync(0xffffffffu, ml, o);
            if (ov < mv || (ov == mv && oj < mj)) { mv = ov; mj = oj; ml = ol; }
        }
        mv = __shfl_sync(0xffffffffu, mv, 0);
        mj = __shfl_sync(0xffffffffu, mj, 0);
        ml = __shfl_sync(0xffffffffu, ml, 0);
        if (lane == ml) ptr++;
        seld2[r] = mv; selj[r] = mj;
    }

    if (lane == 0) {
        float ux[4], uy[4], uz[4], d4[4];
        #pragma unroll
        for (int k = 0; k < 4; k++) {
            int j = selj[k];
            float dx0 = pix - pos[3*j];
            float dy0 = piy - pos[3*j+1];
            float dz0 = piz - pos[3*j+2];
            float fx = dx0*i0v + dy0*i3v + dz0*i6v;
            float fy = dx0*i1v + dy0*i4v + dz0*i7v;
            float fz = dx0*i2v + dy0*i5v + dz0*i8v;
            fx -= rintf(fx); fy -= rintf(fy); fz -= rintf(fz);
            float dx = fx*c0 + fy*c3 + fz*c6;
            float dy = fx*c1 + fy*c4 + fz*c7;
            float dz = fx*c2 + fy*c5 + fz*c8;
            float dist = sqrtf(seld2[k]);
            d4[k] = dist;
            ux[k] = dx / dist; uy[k] = dy / dist; uz[k] = dz / dist;
        }
        float s = 0.0f;
        #pragma unroll
        for (int k = 0; k < 4; k++)
            #pragma unroll
            for (int l = k + 1; l < 4; l++) {
                float c  = ux[k]*ux[l] + uy[k]*uy[l] + uz[k]*uz[l];
                float tt = c + (1.0f / 3.0f);
                s += tt * tt;
            }
        float qi = 1.0f - 0.375f * s;
        if (d4[3] < CUTOFF) {
            atomicAdd(&g_qsum, (double)qi);
            atomicAdd(&g_vfsum, 1.0);
        }
    }
}

// ---------------- finalize: G(r), T(r), S(Q), q_tet -> d_out ----------------------
__global__ void __launch_bounds__(512)
finalize_kernel(const float* __restrict__ rbins, const float* __restrict__ qbins,
                float* __restrict__ out, int n, int nbins, int nq) {
    __shared__ float integ[256];
    __shared__ float sr[256];
    int t = threadIdx.x;
    float rho = g_rho, dr = g_dr, mb = g_meanb;

    if (t < nbins) {
        float r     = rbins[t];
        float shell = 4.0f * PI_F * r * r * dr;
        float hv    = (float)g_hist[t] / (mb * mb);
        float G     = hv / ((float)n * rho * shell);
        out[t]          = G;
        out[nbins + t]  = 4.0f * PI_F * rho * r * G;
        integ[t] = r * r * (G - 1.0f);
        sr[t]    = r;
    }
    __syncthreads();
    if (t < nq) {
        float q = qbins[t];
        float s = 0.0f;
        for (int k = 0; k < nbins; k++) {
            float qr = q * sr[k];
            float x  = qr / PI_F;          // mimic jnp.sinc(qr/pi)
            float px = PI_F * x;
            float sc = (px == 0.0f) ? 1.0f : (sinf(px) / px);
            s += integ[k] * sc;
        }
        out[2 * nbins + t] = 1.0f + 4.0f * PI_F * rho * dr * s;
    }
    if (t == 0) {
        double denom = g_vfsum > 1.0 ? g_vfsum : 1.0;
        out[2 * nbins + nq] = (float)(g_qsum / denom);
    }
}

// ---------------- launch ----------------------------------------------------------
extern "C" void kernel_launch(void* const* d_in, const int* in_sizes, int n_in,
                              void* d_out, int out_size) {
    const float* pos     = (const float*)d_in[0];
    const float* cell    = (const float*)d_in[1];
    const float* rbins   = (const float*)d_in[2];
    const float* qbins   = (const float*)d_in[3];
    const int*   species = (const int*)  d_in[4];
    int n     = in_sizes[0] / 3;
    int nbins = in_sizes[2];
    int nq    = in_sizes[3];

    prep_kernel<<<1, 256>>>(cell, rbins, species, n);

    dim3 grid((n + TI - 1) / TI, (n + TJ - 1) / TJ);
    pair_kernel<<<grid, 256>>>(pos, species, n, nbins);

    int nwarps  = n;
    int nblocks = (nwarps * 32 + 255) / 256;
    qtet_kernel<<<nblocks, 256>>>(pos, species, n);

    finalize_kernel<<<1, 512>>>(rbins, qbins, (float*)d_out, n, nbins, nq);
}

// round 3
// speedup vs baseline: 1.0002x; 1.0002x over previous
#include <cuda_runtime.h>
#include <math.h>

#define B_SI 4.1491f
#define B_O  5.803f
#define CUTOFF 3.5f
#define PI_F 3.14159274101257324f   // (float)M_PI

#define TI 128
#define TJ 512

// ---------------- device globals (scratch; no allocations allowed) ----------------
__device__ float  g_inv[9];
__device__ float  g_cellm[9];
__device__ float  g_rho, g_meanb, g_r0, g_dr;
__device__ double g_hist[256];
__device__ double g_qsum, g_vfsum;

// ---------------- prep: inverse cell, det, mean b, zero accumulators --------------
__global__ void prep_kernel(const float* __restrict__ cell,
                            const float* __restrict__ rbins,
                            const int*   __restrict__ species, int n) {
    int t = threadIdx.x;
    for (int k = t; k < 256; k += 256) g_hist[k] = 0.0;
    if (t == 0) {
        g_qsum = 0.0; g_vfsum = 0.0;
        float a[9];
        #pragma unroll
        for (int k = 0; k < 9; k++) { a[k] = cell[k]; g_cellm[k] = cell[k]; }
        float c00 = a[4]*a[8] - a[5]*a[7];
        float c01 = a[5]*a[6] - a[3]*a[8];
        float c02 = a[3]*a[7] - a[4]*a[6];
        float det = a[0]*c00 + a[1]*c01 + a[2]*c02;
        float id  = 1.0f / det;
        g_inv[0] = c00*id;
        g_inv[3] = c01*id;
        g_inv[6] = c02*id;
        g_inv[1] = (a[2]*a[7] - a[1]*a[8])*id;
        g_inv[4] = (a[0]*a[8] - a[2]*a[6])*id;
        g_inv[7] = (a[1]*a[6] - a[0]*a[7])*id;
        g_inv[2] = (a[1]*a[5] - a[2]*a[4])*id;
        g_inv[5] = (a[2]*a[3] - a[0]*a[5])*id;
        g_inv[8] = (a[0]*a[4] - a[1]*a[3])*id;
        g_rho = (float)n / fabsf(det);
        g_r0  = rbins[0];
        g_dr  = rbins[1] - rbins[0];
    }
    __shared__ float sb[256];
    float s = 0.0f;
    for (int i = t; i < n; i += 256) s += (species[i] == 0) ? B_SI : B_O;
    sb[t] = s; __syncthreads();
    for (int o = 128; o > 0; o >>= 1) { if (t < o) sb[t] += sb[t + o]; __syncthreads(); }
    if (t == 0) g_meanb = sb[0] / (float)n;
}

// ---------------- pair histogram: upper triangle (j>i), weight x2 -----------------
__global__ void __launch_bounds__(256)
pair_kernel(const float* __restrict__ pos, const int* __restrict__ species,
            int n, int nbins) {
    int iBase = blockIdx.x * TI;
    int jBase = blockIdx.y * TJ;
    // tile contains pairs with j > i only if max j in tile exceeds min i in tile
    if (jBase + TJ - 1 <= iBase) return;

    __shared__ float4 fj[TJ];        // (fx, fy, fz, b)
    __shared__ float  sh_hist[256];

    int t = threadIdx.x;
    for (int k = t; k < 256; k += 256) sh_hist[k] = 0.0f;

    const float i0v = g_inv[0], i1v = g_inv[1], i2v = g_inv[2];
    const float i3v = g_inv[3], i4v = g_inv[4], i5v = g_inv[5];
    const float i6v = g_inv[6], i7v = g_inv[7], i8v = g_inv[8];
    const float c0 = g_cellm[0], c1 = g_cellm[1], c2 = g_cellm[2];
    const float c3 = g_cellm[3], c4 = g_cellm[4], c5 = g_cellm[5];
    const float c6 = g_cellm[6], c7 = g_cellm[7], c8 = g_cellm[8];
    const float r0 = g_r0, dr = g_dr;
    const float rmax = r0 + (float)(nbins - 1) * dr;
    const float d2max = rmax * rmax + 0.01f;   // safe over-cover of the valid window
    const float invdr = 1.0f / dr;

    for (int k = t; k < TJ; k += 256) {
        int j = jBase + k;
        float4 v;
        if (j < n) {
            float px = pos[3*j], py = pos[3*j+1], pz = pos[3*j+2];
            v.x = px*i0v + py*i3v + pz*i6v;
            v.y = px*i1v + py*i4v + pz*i7v;
            v.z = px*i2v + py*i5v + pz*i8v;
            v.w = (species[j] == 0) ? B_SI : B_O;
        } else { v.x = 1e18f; v.y = 1e18f; v.z = 1e18f; v.w = 0.0f; }
        fj[k] = v;
    }
    __syncthreads();

    int ii = t & (TI - 1);
    int jg = t >> 7;                 // 0..1, each covers 256 of 512 j's
    int i  = iBase + ii;
    float fix = 0.f, fiy = 0.f, fiz = 0.f, bi = 0.f;
    bool iok = (i < n);
    if (iok) {
        float px = pos[3*i], py = pos[3*i+1], pz = pos[3*i+2];
        fix = px*i0v + py*i3v + pz*i6v;
        fiy = px*i1v + py*i4v + pz*i7v;
        fiz = px*i2v + py*i5v + pz*i8v;
        bi  = (species[i] == 0) ? B_SI : B_O;
    }

    if (iok) {
        for (int k = jg; k < TJ; k += 2) {
            int j = jBase + k;
            if (j >= n || j <= i) continue;
            float4 pj = fj[k];
            float fx = fix - pj.x;
            float fy = fiy - pj.y;
            float fz = fiz - pj.z;
            fx -= rintf(fx); fy -= rintf(fy); fz -= rintf(fz);
            float dx = fx*c0 + fy*c3 + fz*c6;
            float dy = fx*c1 + fy*c4 + fz*c7;
            float dz = fx*c2 + fy*c5 + fz*c8;
            float d2 = dx*dx + dy*dy + dz*dz;
            if (d2 < d2max) {
                float dist = sqrtf(d2);
                float x  = (dist - r0) * invdr;
                float xf = floorf(x);
                int   b0 = (int)xf;
                if (b0 >= 0 && b0 < nbins - 1) {
                    float f = x - xf;
                    float w = 2.0f * bi * pj.w;     // x2 for (i,j)+(j,i)
                    atomicAdd(&sh_hist[b0],     w * (1.0f - f));
                    atomicAdd(&sh_hist[b0 + 1], w * f);
                }
            }
        }
    }
    __syncthreads();
    for (int k = t; k < nbins; k += 256)
        if (sh_hist[k] != 0.0f) atomicAdd(&g_hist[k], (double)sh_hist[k]);
}

// ---------------- tetrahedral order parameter: one warp per atom ------------------
__global__ void __launch_bounds__(256)
qtet_kernel(const float* __restrict__ pos, const int* __restrict__ species, int n) {
    int gw   = (blockIdx.x * blockDim.x + threadIdx.x) >> 5;
    int lane = threadIdx.x & 31;
    if (gw >= n) return;
    int i = gw;
    if (species[i] != 0) return;     // only Si centres contribute

    const float i0v = g_inv[0], i1v = g_inv[1], i2v = g_inv[2];
    const float i3v = g_inv[3], i4v = g_inv[4], i5v = g_inv[5];
    const float i6v = g_inv[6], i7v = g_inv[7], i8v = g_inv[8];
    const float c0 = g_cellm[0], c1 = g_cellm[1], c2 = g_cellm[2];
    const float c3 = g_cellm[3], c4 = g_cellm[4], c5 = g_cellm[5];
    const float c6 = g_cellm[6], c7 = g_cellm[7], c8 = g_cellm[8];

    float pix = pos[3*i], piy = pos[3*i+1], piz = pos[3*i+2];

    const float INF = 3.402823466e38f;
    float bd2[4] = {INF, INF, INF, INF};
    int   bj [4] = {0x7fffffff, 0x7fffffff, 0x7fffffff, 0x7fffffff};

    for (int j = lane; j < n; j += 32) {
        if (j == i || species[j] == 0) continue;     // O neighbours only
        float dx0 = pix - pos[3*j];
        float dy0 = piy - pos[3*j+1];
        float dz0 = piz - pos[3*j+2];
        float fx = dx0*i0v + dy0*i3v + dz0*i6v;
        float fy = dx0*i1v + dy0*i4v + dz0*i7v;
        float fz = dx0*i2v + dy0*i5v + dz0*i8v;
        fx -= rintf(fx); fy -= rintf(fy); fz -= rintf(fz);
        float dx = fx*c0 + fy*c3 + fz*c6;
        float dy = fx*c1 + fy*c4 + fz*c7;
        float dz = fx*c2 + fy*c5 + fz*c8;
        float d2 = dx*dx + dy*dy + dz*dz;
        if (d2 < bd2[3]) {
            float dd = d2; int jj = j;
            #pragma unroll
            for (int k = 0; k < 4; k++) {
                if (dd < bd2[k]) {
                    float td = bd2[k]; bd2[k] = dd; dd = td;
                    int   tj = bj[k];  bj[k]  = jj; jj = tj;
                }
            }
        }
    }

    // merge per-lane top-4 into warp top-4 (4 rounds of arg-min, index tie-break)
    int ptr = 0;
    float seld2[4]; int selj[4];
    #pragma unroll
    for (int r = 0; r < 4; r++) {
        float mv = (ptr < 4) ? bd2[ptr] : INF;
        int   mj = (ptr < 4) ? bj[ptr]  : 0x7fffffff;
        int   ml = lane;
        #pragma unroll
        for (int o = 16; o > 0; o >>= 1) {
            float ov = __shfl_down_sync(0xffffffffu, mv, o);
            int   oj = __shfl_down_sync(0xffffffffu, mj, o);
            int   ol = __shfl_down_sync(0xffffffffu, ml, o);
            if (ov < mv || (ov == mv && oj < mj)) { mv = ov; mj = oj; ml = ol; }
        }
        mv = __shfl_sync(0xffffffffu, mv, 0);
        mj = __shfl_sync(0xffffffffu, mj, 0);
        ml = __shfl_sync(0xffffffffu, ml, 0);
        if (lane == ml) ptr++;
        seld2[r] = mv; selj[r] = mj;
    }

    if (lane == 0) {
        float ux[4], uy[4], uz[4], d4[4];
        #pragma unroll
        for (int k = 0; k < 4; k++) {
            int j = selj[k];
            float dx0 = pix - pos[3*j];
            float dy0 = piy - pos[3*j+1];
            float dz0 = piz - pos[3*j+2];
            float fx = dx0*i0v + dy0*i3v + dz0*i6v;
            float fy = dx0*i1v + dy0*i4v + dz0*i7v;
            float fz = dx0*i2v + dy0*i5v + dz0*i8v;
            fx -= rintf(fx); fy -= rintf(fy); fz -= rintf(fz);
            float dx = fx*c0 + fy*c3 + fz*c6;
            float dy = fx*c1 + fy*c4 + fz*c7;
            float dz = fx*c2 + fy*c5 + fz*c8;
            float dist = sqrtf(seld2[k]);
            d4[k] = dist;
            ux[k] = dx / dist; uy[k] = dy / dist; uz[k] = dz / dist;
        }
        float s = 0.0f;
        #pragma unroll
        for (int k = 0; k < 4; k++)
            #pragma unroll
            for (int l = k + 1; l < 4; l++) {
                float c  = ux[k]*ux[l] + uy[k]*uy[l] + uz[k]*uz[l];
                float tt = c + (1.0f / 3.0f);
                s += tt * tt;
            }
        float qi = 1.0f - 0.375f * s;
        if (d4[3] < CUTOFF) {
            atomicAdd(&g_qsum, (double)qi);
            atomicAdd(&g_vfsum, 1.0);
        }
    }
}

// ---------------- finalize: G(r), T(r), S(Q), q_tet -> d_out ----------------------
__global__ void __launch_bounds__(512)
finalize_kernel(const float* __restrict__ rbins, const float* __restrict__ qbins,
                float* __restrict__ out, int n, int nbins, int nq) {
    __shared__ float integ[256];
    __shared__ float sr[256];
    int t = threadIdx.x;
    float rho = g_rho, dr = g_dr, mb = g_meanb;

    if (t < nbins) {
        float r     = rbins[t];
        float shell = 4.0f * PI_F * r * r * dr;
        float hv    = (float)g_hist[t] / (mb * mb);
        float G     = hv / ((float)n * rho * shell);
        out[t]          = G;
        out[nbins + t]  = 4.0f * PI_F * rho * r * G;
        integ[t] = r * r * (G - 1.0f);
        sr[t]    = r;
    }
    __syncthreads();
    if (t < nq) {
        float q = qbins[t];
        float s = 0.0f;
        for (int k = 0; k < nbins; k++) {
            float qr = q * sr[k];
            float x  = qr / PI_F;          // mimic jnp.sinc(qr/pi)
            float px = PI_F * x;
            float sc = (px == 0.0f) ? 1.0f : (sinf(px) / px);
            s += integ[k] * sc;
        }
        out[2 * nbins + t] = 1.0f + 4.0f * PI_F * rho * dr * s;
    }
    if (t == 0) {
        double denom = g_vfsum > 1.0 ? g_vfsum : 1.0;
        out[2 * nbins + nq] = (float)(g_qsum / denom);
    }
}

// ---------------- launch ----------------------------------------------------------
extern "C" void kernel_launch(void* const* d_in, const int* in_sizes, int n_in,
                              void* d_out, int out_size) {
    const float* pos     = (const float*)d_in[0];
    const float* cell    = (const float*)d_in[1];
    const float* rbins   = (const float*)d_in[2];
    const float* qbins   = (const float*)d_in[3];
    const int*   species = (const int*)  d_in[4];
    int n     = in_sizes[0] / 3;
    int nbins = in_sizes[2];
    int nq    = in_sizes[3];

    prep_kernel<<<1, 256>>>(cell, rbins, species, n);

    dim3 grid((n + TI - 1) / TI, (n + TJ - 1) / TJ);
    pair_kernel<<<grid, 256>>>(pos, species, n, nbins);

    int nwarps  = n;
    int nblocks = (nwarps * 32 + 255) / 256;
    qtet_kernel<<<nblocks, 256>>>(pos, species, n);

    finalize_kernel<<<1, 512>>>(rbins, qbins, (float*)d_out, n, nbins, nq);
}

// round 4
// speedup vs baseline: 1.3147x; 1.3145x over previous
#include <cuda_runtime.h>
#include <math.h>

#define B_SI 4.1491f
#define B_O  5.803f
#define CUTOFF 3.5f
#define PI_F 3.14159274101257324f   // (float)M_PI

#define TI 128
#define TJ 512

// ---------------- device globals (scratch; no allocations allowed) ----------------
__device__ float  g_inv[9];
__device__ float  g_cellm[9];
__device__ float  g_rho, g_meanb, g_r0, g_dr;
__device__ int    g_diag;
__device__ double g_hist[256];
__device__ double g_qsum, g_vfsum;
__device__ float  g_integ[256];

// ---------------- prep: inverse cell, det, mean b, zero accumulators --------------
__global__ void prep_kernel(const float* __restrict__ cell,
                            const float* __restrict__ rbins,
                            const int*   __restrict__ species, int n) {
    int t = threadIdx.x;
    for (int k = t; k < 256; k += 256) g_hist[k] = 0.0;
    if (t == 0) {
        g_qsum = 0.0; g_vfsum = 0.0;
        float a[9];
        #pragma unroll
        for (int k = 0; k < 9; k++) { a[k] = cell[k]; g_cellm[k] = cell[k]; }
        float c00 = a[4]*a[8] - a[5]*a[7];
        float c01 = a[5]*a[6] - a[3]*a[8];
        float c02 = a[3]*a[7] - a[4]*a[6];
        float det = a[0]*c00 + a[1]*c01 + a[2]*c02;
        float id  = 1.0f / det;
        g_inv[0] = c00*id;
        g_inv[3] = c01*id;
        g_inv[6] = c02*id;
        g_inv[1] = (a[2]*a[7] - a[1]*a[8])*id;
        g_inv[4] = (a[0]*a[8] - a[2]*a[6])*id;
        g_inv[7] = (a[1]*a[6] - a[0]*a[7])*id;
        g_inv[2] = (a[1]*a[5] - a[2]*a[4])*id;
        g_inv[5] = (a[2]*a[3] - a[0]*a[5])*id;
        g_inv[8] = (a[0]*a[4] - a[1]*a[3])*id;
        g_rho = (float)n / fabsf(det);
        g_r0  = rbins[0];
        g_dr  = rbins[1] - rbins[0];
        g_diag = (a[1] == 0.0f && a[2] == 0.0f && a[3] == 0.0f &&
                  a[5] == 0.0f && a[6] == 0.0f && a[7] == 0.0f) ? 1 : 0;
    }
    __shared__ float sb[256];
    float s = 0.0f;
    for (int i = t; i < n; i += 256) s += (species[i] == 0) ? B_SI : B_O;
    sb[t] = s; __syncthreads();
    for (int o = 128; o > 0; o >>= 1) { if (t < o) sb[t] += sb[t + o]; __syncthreads(); }
    if (t == 0) g_meanb = sb[0] / (float)n;
}

// ---------------- pair histogram: upper triangle (j>i), weight x2 -----------------
__global__ void __launch_bounds__(256)
pair_kernel(const float* __restrict__ pos, const int* __restrict__ species,
            int n, int nbins) {
    int iBase = blockIdx.x * TI;
    int jBase = blockIdx.y * TJ;
    if (jBase + TJ - 1 <= iBase) return;

    __shared__ float4 fj[TJ];        // (fx, fy, fz, b) fractional coords
    __shared__ float  sh_hist[256];

    int t = threadIdx.x;
    sh_hist[t] = 0.0f;

    const float i0v = g_inv[0], i1v = g_inv[1], i2v = g_inv[2];
    const float i3v = g_inv[3], i4v = g_inv[4], i5v = g_inv[5];
    const float i6v = g_inv[6], i7v = g_inv[7], i8v = g_inv[8];
    const float c0 = g_cellm[0], c1 = g_cellm[1], c2 = g_cellm[2];
    const float c3 = g_cellm[3], c4 = g_cellm[4], c5 = g_cellm[5];
    const float c6 = g_cellm[6], c7 = g_cellm[7], c8 = g_cellm[8];
    const int   diag = g_diag;
    const float r0 = g_r0, dr = g_dr;
    const float rmax = r0 + (float)(nbins - 1) * dr;
    const float d2max = rmax * rmax + 0.01f;
    const float invdr = 1.0f / dr;

    for (int k = t; k < TJ; k += 256) {
        int j = jBase + k;
        float4 v;
        if (j < n) {
            float px = pos[3*j], py = pos[3*j+1], pz = pos[3*j+2];
            v.x = px*i0v + py*i3v + pz*i6v;
            v.y = px*i1v + py*i4v + pz*i7v;
            v.z = px*i2v + py*i5v + pz*i8v;
            v.w = (species[j] == 0) ? B_SI : B_O;
        } else { v.x = 1e18f; v.y = 1e18f; v.z = 1e18f; v.w = 0.0f; }
        fj[k] = v;
    }
    __syncthreads();

    int ii = t & (TI - 1);
    int jg = t >> 7;                 // 0..1, each covers alternate j slots
    int i  = iBase + ii;
    if (i < n) {
        float px = pos[3*i], py = pos[3*i+1], pz = pos[3*i+2];
        float fix = px*i0v + py*i3v + pz*i6v;
        float fiy = px*i1v + py*i4v + pz*i7v;
        float fiz = px*i2v + py*i5v + pz*i8v;
        float bi2 = 2.0f * ((species[i] == 0) ? B_SI : B_O);

        // loop bounds encode j>i and j<n (no per-slot compares)
        int kmin = i - jBase + 1;
        if (kmin < jg) kmin = jg;
        kmin += (kmin ^ jg) & 1;     // align parity to jg
        int kmax = n - jBase; if (kmax > TJ) kmax = TJ;

        if (diag) {
            for (int k = kmin; k < kmax; k += 2) {
                float4 pj = fj[k];
                float fx = fix - pj.x; fx -= rintf(fx);
                float fy = fiy - pj.y; fy -= rintf(fy);
                float fz = fiz - pj.z; fz -= rintf(fz);
                float dx = fx*c0, dy = fy*c4, dz = fz*c8;
                float d2 = dx*dx + dy*dy + dz*dz;
                if (d2 < d2max) {
                    float dist = sqrtf(d2);
                    float x  = (dist - r0) * invdr;
                    float xf = floorf(x);
                    int   b0 = (int)xf;
                    if (b0 >= 0 && b0 < nbins - 1) {
                        float f = x - xf;
                        float w = bi2 * pj.w;
                        atomicAdd(&sh_hist[b0],     w * (1.0f - f));
                        atomicAdd(&sh_hist[b0 + 1], w * f);
                    }
                }
            }
        } else {
            for (int k = kmin; k < kmax; k += 2) {
                float4 pj = fj[k];
                float fx = fix - pj.x; fx -= rintf(fx);
                float fy = fiy - pj.y; fy -= rintf(fy);
                float fz = fiz - pj.z; fz -= rintf(fz);
                float dx = fx*c0 + fy*c3 + fz*c6;
                float dy = fx*c1 + fy*c4 + fz*c7;
                float dz = fx*c2 + fy*c5 + fz*c8;
                float d2 = dx*dx + dy*dy + dz*dz;
                if (d2 < d2max) {
                    float dist = sqrtf(d2);
                    float x  = (dist - r0) * invdr;
                    float xf = floorf(x);
                    int   b0 = (int)xf;
                    if (b0 >= 0 && b0 < nbins - 1) {
                        float f = x - xf;
                        float w = bi2 * pj.w;
                        atomicAdd(&sh_hist[b0],     w * (1.0f - f));
                        atomicAdd(&sh_hist[b0 + 1], w * f);
                    }
                }
            }
        }
    }
    __syncthreads();
    if (t < nbins && sh_hist[t] != 0.0f) atomicAdd(&g_hist[t], (double)sh_hist[t]);
}

// ---------------- tetrahedral order parameter: one warp per atom ------------------
__global__ void __launch_bounds__(256)
qtet_kernel(const float* __restrict__ pos, const int* __restrict__ species, int n) {
    int gw   = (blockIdx.x * blockDim.x + threadIdx.x) >> 5;
    int lane = threadIdx.x & 31;
    int wib  = threadIdx.x >> 5;

    bool active = (gw < n) && (species[min(gw, n - 1)] == 0);
    int i = gw;

    const float i0v = g_inv[0], i1v = g_inv[1], i2v = g_inv[2];
    const float i3v = g_inv[3], i4v = g_inv[4], i5v = g_inv[5];
    const float i6v = g_inv[6], i7v = g_inv[7], i8v = g_inv[8];
    const float c0 = g_cellm[0], c1 = g_cellm[1], c2 = g_cellm[2];
    const float c3 = g_cellm[3], c4 = g_cellm[4], c5 = g_cellm[5];
    const float c6 = g_cellm[6], c7 = g_cellm[7], c8 = g_cellm[8];
    const int diag = g_diag;

    float qi = 0.0f;
    int   vf = 0;

    if (active) {
        float pix = pos[3*i], piy = pos[3*i+1], piz = pos[3*i+2];

        const float INF = 3.402823466e38f;
        float bd2[4] = {INF, INF, INF, INF};
        int   bj [4] = {0x7fffffff, 0x7fffffff, 0x7fffffff, 0x7fffffff};

        for (int j = lane; j < n; j += 32) {
            if (j == i || species[j] == 0) continue;     // O neighbours only
            float dx0 = pix - pos[3*j];
            float dy0 = piy - pos[3*j+1];
            float dz0 = piz - pos[3*j+2];
            float fx, fy, fz, dx, dy, dz;
            if (diag) {
                fx = dx0*i0v; fy = dy0*i4v; fz = dz0*i8v;
                fx -= rintf(fx); fy -= rintf(fy); fz -= rintf(fz);
                dx = fx*c0; dy = fy*c4; dz = fz*c8;
            } else {
                fx = dx0*i0v + dy0*i3v + dz0*i6v;
                fy = dx0*i1v + dy0*i4v + dz0*i7v;
                fz = dx0*i2v + dy0*i5v + dz0*i8v;
                fx -= rintf(fx); fy -= rintf(fy); fz -= rintf(fz);
                dx = fx*c0 + fy*c3 + fz*c6;
                dy = fx*c1 + fy*c4 + fz*c7;
                dz = fx*c2 + fy*c5 + fz*c8;
            }
            float d2 = dx*dx + dy*dy + dz*dz;
            if (d2 < bd2[3]) {
                float dd = d2; int jj = j;
                #pragma unroll
                for (int k = 0; k < 4; k++) {
                    if (dd < bd2[k]) {
                        float td = bd2[k]; bd2[k] = dd; dd = td;
                        int   tj = bj[k];  bj[k]  = jj; jj = tj;
                    }
                }
            }
        }

        // merge per-lane top-4 into warp top-4 (4 rounds of arg-min, index tie-break)
        int ptr = 0;
        float seld2[4]; int selj[4];
        #pragma unroll
        for (int r = 0; r < 4; r++) {
            float mv = (ptr < 4) ? bd2[ptr] : INF;
            int   mj = (ptr < 4) ? bj[ptr]  : 0x7fffffff;
            int   ml = lane;
            #pragma unroll
            for (int o = 16; o > 0; o >>= 1) {
                float ov = __shfl_down_sync(0xffffffffu, mv, o);
                int   oj = __shfl_down_sync(0xffffffffu, mj, o);
                int   ol = __shfl_down_sync(0xffffffffu, ml, o);
                if (ov < mv || (ov == mv && oj < mj)) { mv = ov; mj = oj; ml = ol; }
            }
            mv = __shfl_sync(0xffffffffu, mv, 0);
            mj = __shfl_sync(0xffffffffu, mj, 0);
            ml = __shfl_sync(0xffffffffu, ml, 0);
            if (lane == ml) ptr++;
            seld2[r] = mv; selj[r] = mj;
        }

        if (lane == 0) {
            float ux[4], uy[4], uz[4], d4[4];
            #pragma unroll
            for (int k = 0; k < 4; k++) {
                int j = selj[k];
                float dx0 = pix - pos[3*j];
                float dy0 = piy - pos[3*j+1];
                float dz0 = piz - pos[3*j+2];
                float fx = dx0*i0v + dy0*i3v + dz0*i6v;
                float fy = dx0*i1v + dy0*i4v + dz0*i7v;
                float fz = dx0*i2v + dy0*i5v + dz0*i8v;
                fx -= rintf(fx); fy -= rintf(fy); fz -= rintf(fz);
                float dx = fx*c0 + fy*c3 + fz*c6;
                float dy = fx*c1 + fy*c4 + fz*c7;
                float dz = fx*c2 + fy*c5 + fz*c8;
                float dist = sqrtf(seld2[k]);
                d4[k] = dist;
                ux[k] = dx / dist; uy[k] = dy / dist; uz[k] = dz / dist;
            }
            float s = 0.0f;
            #pragma unroll
            for (int k = 0; k < 4; k++)
                #pragma unroll
                for (int l = k + 1; l < 4; l++) {
                    float c  = ux[k]*ux[l] + uy[k]*uy[l] + uz[k]*uz[l];
                    float tt = c + (1.0f / 3.0f);
                    s += tt * tt;
                }
            if (d4[3] < CUTOFF) { qi = 1.0f - 0.375f * s; vf = 1; }
        }
    }

    // block-level reduction of (qi, vf) from each warp's lane 0, one atomic per block
    __shared__ double s_q[8];
    __shared__ int    s_v[8];
    if (lane == 0) { s_q[wib] = (double)qi; s_v[wib] = vf; }
    __syncthreads();
    if (threadIdx.x == 0) {
        double qs = 0.0; int vs = 0;
        #pragma unroll
        for (int k = 0; k < 8; k++) { qs += s_q[k]; vs += s_v[k]; }
        if (vs > 0) {
            atomicAdd(&g_qsum, qs);
            atomicAdd(&g_vfsum, (double)vs);
        }
    }
}

// ---------------- finalize A: G(r), T(r), integrand, q_tet ------------------------
__global__ void __launch_bounds__(256)
finalizeA_kernel(const float* __restrict__ rbins, float* __restrict__ out,
                 int n, int nbins, int nq) {
    int t = threadIdx.x;
    float rho = g_rho, dr = g_dr, mb = g_meanb;
    if (t < nbins) {
        float r     = rbins[t];
        float shell = 4.0f * PI_F * r * r * dr;
        float hv    = (float)g_hist[t] / (mb * mb);
        float G     = hv / ((float)n * rho * shell);
        out[t]          = G;
        out[nbins + t]  = 4.0f * PI_F * rho * r * G;
        g_integ[t] = r * r * (G - 1.0f);
    }
    if (t == 0) {
        double denom = g_vfsum > 1.0 ? g_vfsum : 1.0;
        out[2 * nbins + nq] = (float)(g_qsum / denom);
    }
}

// ---------------- finalize B: S(Q), one warp per q-value --------------------------
__global__ void __launch_bounds__(256)
sq_kernel(const float* __restrict__ rbins, const float* __restrict__ qbins,
          float* __restrict__ out, int nbins, int nq) {
    int warp = (blockIdx.x * blockDim.x + threadIdx.x) >> 5;
    int lane = threadIdx.x & 31;
    if (warp >= nq) return;
    float q   = qbins[warp];
    float rho = g_rho, dr = g_dr;
    float s = 0.0f;
    for (int k = lane; k < nbins; k += 32) {
        float qr = q * rbins[k];
        float x  = qr / PI_F;              // mimic jnp.sinc(qr/pi)
        float px = PI_F * x;
        float sc = (px == 0.0f) ? 1.0f : (sinf(px) / px);
        s += g_integ[k] * sc;
    }
    #pragma unroll
    for (int o = 16; o > 0; o >>= 1) s += __shfl_down_sync(0xffffffffu, s, o);
    if (lane == 0) out[2 * nbins + warp] = 1.0f + 4.0f * PI_F * rho * dr * s;
}

// ---------------- launch ----------------------------------------------------------
extern "C" void kernel_launch(void* const* d_in, const int* in_sizes, int n_in,
                              void* d_out, int out_size) {
    const float* pos     = (const float*)d_in[0];
    const float* cell    = (const float*)d_in[1];
    const float* rbins   = (const float*)d_in[2];
    const float* qbins   = (const float*)d_in[3];
    const int*   species = (const int*)  d_in[4];
    int n     = in_sizes[0] / 3;
    int nbins = in_sizes[2];
    int nq    = in_sizes[3];

    prep_kernel<<<1, 256>>>(cell, rbins, species, n);

    dim3 grid((n + TI - 1) / TI, (n + TJ - 1) / TJ);
    pair_kernel<<<grid, 256>>>(pos, species, n, nbins);

    int nblocks = (n * 32 + 255) / 256;
    qtet_kernel<<<nblocks, 256>>>(pos, species, n);

    finalizeA_kernel<<<1, 256>>>(rbins, (float*)d_out, n, nbins, nq);

    int sqblocks = (nq * 32 + 255) / 256;
    sq_kernel<<<sqblocks, 256>>>(rbins, qbins, (float*)d_out, nbins, nq);
}

// round 5
// speedup vs baseline: 3.1045x; 2.3613x over previous
#include <cuda_runtime.h>
#include <math.h>

#define B_SI 4.1491f
#define B_O  5.803f
#define CUTOFF 3.5f
#define PI_F 3.14159274101257324f   // (float)M_PI

#define CDIM   8
#define NCELLS 512                  // CDIM^3
#define NMAX   8192

// ---------------- device globals (scratch; no allocations allowed) ----------------
__device__ float  g_inv[9];
__device__ float  g_cellm[9];
__device__ float  g_rho, g_meanb, g_r0, g_dr, g_rsafe;
__device__ int    g_diag, g_cellok;
__device__ double g_hist[256];
__device__ double g_qsum, g_vfsum;
__device__ float  g_integ[256];

__device__ float4 g_fracA[NMAX];    // per ORIGINAL atom: wrapped frac xyz + b
__device__ int    g_cellOf[NMAX];
__device__ float4 g_sfrac[NMAX];    // cell-sorted copy
__device__ int    g_sorig[NMAX];
__device__ int    g_cellCnt[NCELLS];
__device__ int    g_cellStart[NCELLS];
__device__ int    g_cellFill[NCELLS];

// ---------------- helpers ----------------------------------------------------------
__device__ __forceinline__ void insert4(float bd2[4], int bj[4], float dd, int jj) {
    if (dd < bd2[3]) {
        #pragma unroll
        for (int k = 0; k < 4; k++) {
            if (dd < bd2[k]) {
                float td = bd2[k]; bd2[k] = dd; dd = td;
                int   tj = bj[k];  bj[k]  = jj; jj = tj;
            }
        }
    }
}

__device__ __forceinline__ void warp_merge_top4(float bd2[4], int bj[4], int lane,
                                                float seld2[4], int selj[4]) {
    const float INF = 3.402823466e38f;
    int ptr = 0;
    #pragma unroll
    for (int r = 0; r < 4; r++) {
        float mv = (ptr < 4) ? bd2[ptr] : INF;
        int   mj = (ptr < 4) ? bj[ptr]  : 0x7fffffff;
        int   ml = lane;
        #pragma unroll
        for (int o = 16; o > 0; o >>= 1) {
            float ov = __shfl_down_sync(0xffffffffu, mv, o);
            int   oj = __shfl_down_sync(0xffffffffu, mj, o);
            int   ol = __shfl_down_sync(0xffffffffu, ml, o);
            if (ov < mv || (ov == mv && oj < mj)) { mv = ov; mj = oj; ml = ol; }
        }
        mv = __shfl_sync(0xffffffffu, mv, 0);
        mj = __shfl_sync(0xffffffffu, mj, 0);
        ml = __shfl_sync(0xffffffffu, ml, 0);
        if (lane == ml) ptr++;
        seld2[r] = mv; selj[r] = mj;
    }
}

// ---------------- prep --------------------------------------------------------------
__global__ void prep_kernel(const float* __restrict__ cell,
                            const float* __restrict__ rbins,
                            const int*   __restrict__ species, int n, int nbins) {
    int t = threadIdx.x;
    for (int k = t; k < 256; k += 256) g_hist[k] = 0.0;
    for (int k = t; k < NCELLS; k += 256) g_cellCnt[k] = 0;
    if (t == 0) {
        g_qsum = 0.0; g_vfsum = 0.0;
        float a[9];
        #pragma unroll
        for (int k = 0; k < 9; k++) { a[k] = cell[k]; g_cellm[k] = cell[k]; }
        float c00 = a[4]*a[8] - a[5]*a[7];
        float c01 = a[5]*a[6] - a[3]*a[8];
        float c02 = a[3]*a[7] - a[4]*a[6];
        float det = a[0]*c00 + a[1]*c01 + a[2]*c02;
        float id  = 1.0f / det;
        g_inv[0] = c00*id;  g_inv[3] = c01*id;  g_inv[6] = c02*id;
        g_inv[1] = (a[2]*a[7] - a[1]*a[8])*id;
        g_inv[4] = (a[0]*a[8] - a[2]*a[6])*id;
        g_inv[7] = (a[1]*a[6] - a[0]*a[7])*id;
        g_inv[2] = (a[1]*a[5] - a[2]*a[4])*id;
        g_inv[5] = (a[2]*a[3] - a[0]*a[5])*id;
        g_inv[8] = (a[0]*a[4] - a[1]*a[3])*id;
        float adet = fabsf(det);
        g_rho = (float)n / adet;
        float r0 = rbins[0], dr = rbins[1] - rbins[0];
        g_r0 = r0; g_dr = dr;
        g_diag = (a[1] == 0.0f && a[2] == 0.0f && a[3] == 0.0f &&
                  a[5] == 0.0f && a[6] == 0.0f && a[7] == 0.0f) ? 1 : 0;
        // perpendicular widths of the cell
        float n1 = sqrtf(c00*c00 + (a[5]*a[6]-a[3]*a[8])*(a[5]*a[6]-a[3]*a[8])
                                 + (a[3]*a[7]-a[4]*a[6])*(a[3]*a[7]-a[4]*a[6]));
        float x31x = a[7]*a[2]-a[8]*a[1], x31y = a[8]*a[0]-a[6]*a[2], x31z = a[6]*a[1]-a[7]*a[0];
        float n2 = sqrtf(x31x*x31x + x31y*x31y + x31z*x31z);
        float x12x = a[1]*a[5]-a[2]*a[4], x12y = a[2]*a[3]-a[0]*a[5], x12z = a[0]*a[4]-a[1]*a[3];
        float n3 = sqrtf(x12x*x12x + x12y*x12y + x12z*x12z);
        float p1 = adet/n1, p2 = adet/n2, p3 = adet/n3;
        float pmin = fminf(p1, fminf(p2, p3));
        float rmax = r0 + (float)(nbins - 1) * dr;
        g_cellok = (rmax * (float)CDIM * 0.5f <= pmin) ? 1 : 0;  // +/-2 cells cover rmax
        g_rsafe  = pmin / (float)CDIM;                            // +/-1 cells complete radius
    }
    __shared__ float sb[256];
    float s = 0.0f;
    for (int i = t; i < n; i += 256) s += (species[i] == 0) ? B_SI : B_O;
    sb[t] = s; __syncthreads();
    for (int o = 128; o > 0; o >>= 1) { if (t < o) sb[t] += sb[t + o]; __syncthreads(); }
    if (t == 0) g_meanb = sb[0] / (float)n;
}

// ---------------- count: frac coords + cell assignment ------------------------------
__global__ void __launch_bounds__(256)
count_kernel(const float* __restrict__ pos, const int* __restrict__ species, int n) {
    int i = blockIdx.x * blockDim.x + threadIdx.x;
    if (i >= n) return;
    float px = pos[3*i], py = pos[3*i+1], pz = pos[3*i+2];
    float fx = px*g_inv[0] + py*g_inv[3] + pz*g_inv[6];
    float fy = px*g_inv[1] + py*g_inv[4] + pz*g_inv[7];
    float fz = px*g_inv[2] + py*g_inv[5] + pz*g_inv[8];
    fx -= floorf(fx); fy -= floorf(fy); fz -= floorf(fz);
    int cx = min((int)(fx * (float)CDIM), CDIM - 1);
    int cy = min((int)(fy * (float)CDIM), CDIM - 1);
    int cz = min((int)(fz * (float)CDIM), CDIM - 1);
    int c  = cx | (cy << 3) | (cz << 6);
    float4 v; v.x = fx; v.y = fy; v.z = fz;
    v.w = (species[i] == 0) ? B_SI : B_O;
    g_fracA[i]  = v;
    g_cellOf[i] = c;
    atomicAdd(&g_cellCnt[c], 1);
}

// ---------------- scan: exclusive prefix over 512 cell counts -----------------------
__global__ void __launch_bounds__(512)
scan_kernel() {
    __shared__ int sc[NCELLS];
    int t = threadIdx.x;
    int cnt = g_cellCnt[t];
    sc[t] = cnt; __syncthreads();
    for (int off = 1; off < NCELLS; off <<= 1) {
        int v = (t >= off) ? sc[t - off] : 0;
        __syncthreads();
        sc[t] += v;
        __syncthreads();
    }
    int ex = sc[t] - cnt;
    g_cellStart[t] = ex;
    g_cellFill[t]  = ex;
}

// ---------------- scatter into cell-sorted order ------------------------------------
__global__ void __launch_bounds__(256)
scatter_kernel(int n) {
    int i = blockIdx.x * blockDim.x + threadIdx.x;
    if (i >= n) return;
    int c = g_cellOf[i];
    int s = atomicAdd(&g_cellFill[c], 1);
    g_sfrac[s] = g_fracA[i];
    g_sorig[s] = i;
}

// ---------------- pair histogram via cell lists (half neighborhood) -----------------
__global__ void __launch_bounds__(128)
pair_cells_kernel(int n, int nbins) {
    __shared__ float4 sbuf[512];       // cell path: [0..63] = center atoms; brute: j tile
    __shared__ float  shist[256];
    __shared__ int    nbS[63], nbC[63], nbCum[64], cslot[64];

    int t = threadIdx.x;
    shist[t] = 0.0f; shist[t + 128] = 0.0f;

    const float c0 = g_cellm[0], c1 = g_cellm[1], c2 = g_cellm[2];
    const float c3 = g_cellm[3], c4 = g_cellm[4], c5 = g_cellm[5];
    const float c6 = g_cellm[6], c7 = g_cellm[7], c8 = g_cellm[8];
    const int   diag = g_diag;
    const float r0 = g_r0, dr = g_dr;
    const float rmax = r0 + (float)(nbins - 1) * dr;
    const float d2max = rmax * rmax + 0.01f;
    const float invdr = 1.0f / dr;

    if (g_cellok) {
        int c = blockIdx.x;
        if (c < NCELLS) {
            int cx = c & 7, cy = (c >> 3) & 7, cz = c >> 6;
            if (t < 63) {
                int tt = 62 + t;                       // t=0 -> self, t>0 -> positive half
                int ox = tt % 5 - 2, oy = (tt / 5) % 5 - 2, oz = tt / 25 - 2;
                int nc = ((cx + ox) & 7) | (((cy + oy) & 7) << 3) | (((cz + oz) & 7) << 6);
                nbS[t] = g_cellStart[nc];
                nbC[t] = g_cellCnt[nc];
            }
            __syncthreads();
            if (t == 0) {
                int cum = 0;
                for (int k = 0; k < 63; k++) { nbCum[k] = cum; cum += nbC[k]; }
                nbCum[63] = cum;
            }
            __syncthreads();
            int total     = nbCum[63];
            int selfStart = nbS[0];
            int nC        = nbC[0];

            for (int ibase = 0; ibase < nC; ibase += 64) {
                int m = min(64, nC - ibase);
                if (t < m) {
                    sbuf[t]  = g_sfrac[selfStart + ibase + t];
                    cslot[t] = selfStart + ibase + t;
                }
                __syncthreads();

                #define PAIR_BODY(DCOMP)                                                \
                for (int jj = t; jj < total; jj += 128) {                               \
                    int lo = 0;                                                         \
                    if (nbCum[lo + 32] <= jj) lo += 32;                                 \
                    if (nbCum[lo + 16] <= jj) lo += 16;                                 \
                    if (nbCum[lo +  8] <= jj) lo +=  8;                                 \
                    if (nbCum[lo +  4] <= jj) lo +=  4;                                 \
                    if (nbCum[lo +  2] <= jj) lo +=  2;                                 \
                    if (nbCum[lo +  1] <= jj) lo +=  1;                                 \
                    int slot = nbS[lo] + (jj - nbCum[lo]);                              \
                    float4 pj = g_sfrac[slot];                                          \
                    bool self = (lo == 0);                                              \
                    for (int ii = 0; ii < m; ii++) {                                    \
                        if (self && slot <= cslot[ii]) continue;                        \
                        float4 pi = sbuf[ii];                                           \
                        float fx = pi.x - pj.x; fx -= rintf(fx);                        \
                        float fy = pi.y - pj.y; fy -= rintf(fy);                        \
                        float fz = pi.z - pj.z; fz -= rintf(fz);                        \
                        DCOMP                                                           \
                        float d2 = dx*dx + dy*dy + dz*dz;                               \
                        if (d2 < d2max) {                                               \
                            float dist = sqrtf(d2);                                     \
                            float x  = (dist - r0) * invdr;                             \
                            float xf = floorf(x);                                       \
                            int   b0 = (int)xf;                                         \
                            if (b0 >= 0 && b0 < nbins - 1) {                            \
                                float f = x - xf;                                       \
                                float w = 2.0f * pi.w * pj.w;                           \
                                atomicAdd(&shist[b0],     w * (1.0f - f));              \
                                atomicAdd(&shist[b0 + 1], w * f);                       \
                            }                                                           \
                        }                                                               \
                    }                                                                   \
                }

                if (diag) {
                    PAIR_BODY(float dx = fx*c0; float dy = fy*c4; float dz = fz*c8;)
                } else {
                    PAIR_BODY(float dx = fx*c0 + fy*c3 + fz*c6;
                              float dy = fx*c1 + fy*c4 + fz*c7;
                              float dz = fx*c2 + fy*c5 + fz*c8;)
                }
                #undef PAIR_BODY
                __syncthreads();
            }
        }
    } else {
        // ---- brute fallback (general safety; unused for orthorhombic L>=40) ----
        int tilesJ = (n + 511) >> 9;
        int ib = blockIdx.x / tilesJ;
        int jb = blockIdx.x % tilesJ;
        int iBase = ib * 128, jBase = jb * 512;
        bool work = (iBase < n) && (jBase + 511 > iBase) && (ib * tilesJ + jb == (int)blockIdx.x);
        if (work) {
            for (int k = t; k < 512; k += 128) {
                int j = jBase + k;
                float4 v;
                if (j < n) v = g_fracA[j];
                else { v.x = 1e18f; v.y = 1e18f; v.z = 1e18f; v.w = 0.0f; }
                sbuf[k] = v;
            }
            __syncthreads();
            int i = iBase + t;
            if (i < n) {
                float4 pi = g_fracA[i];
                int kmin = i - jBase + 1; if (kmin < 0) kmin = 0;
                int kmax = n - jBase; if (kmax > 512) kmax = 512;
                for (int k = kmin; k < kmax; k++) {
                    float4 pj = sbuf[k];
                    float fx = pi.x - pj.x; fx -= rintf(fx);
                    float fy = pi.y - pj.y; fy -= rintf(fy);
                    float fz = pi.z - pj.z; fz -= rintf(fz);
                    float dx = fx*c0 + fy*c3 + fz*c6;
                    float dy = fx*c1 + fy*c4 + fz*c7;
                    float dz = fx*c2 + fy*c5 + fz*c8;
                    float d2 = dx*dx + dy*dy + dz*dz;
                    if (d2 < d2max) {
                        float dist = sqrtf(d2);
                        float x  = (dist - r0) * invdr;
                        float xf = floorf(x);
                        int   b0 = (int)xf;
                        if (b0 >= 0 && b0 < nbins - 1) {
                            float f = x - xf;
                            float w = 2.0f * pi.w * pj.w;
                            atomicAdd(&shist[b0],     w * (1.0f - f));
                            atomicAdd(&shist[b0 + 1], w * f);
                        }
                    }
                }
            }
            __syncthreads();
        }
    }
    __syncthreads();
    for (int k = t; k < nbins; k += 128)
        if (shist[k] != 0.0f) atomicAdd(&g_hist[k], (double)shist[k]);
}

// ---------------- tetrahedral order parameter: warp/atom, cell-restricted -----------
__global__ void __launch_bounds__(256)
qtet_kernel(const float* __restrict__ pos, const int* __restrict__ species, int n) {
    int gw   = (blockIdx.x * blockDim.x + threadIdx.x) >> 5;
    int lane = threadIdx.x & 31;
    int wib  = threadIdx.x >> 5;

    bool active = (gw < n) && (species[min(gw, n - 1)] == 0);
    int i = gw;

    const float i0v = g_inv[0], i1v = g_inv[1], i2v = g_inv[2];
    const float i3v = g_inv[3], i4v = g_inv[4], i5v = g_inv[5];
    const float i6v = g_inv[6], i7v = g_inv[7], i8v = g_inv[8];
    const float c0 = g_cellm[0], c1 = g_cellm[1], c2 = g_cellm[2];
    const float c3 = g_cellm[3], c4 = g_cellm[4], c5 = g_cellm[5];
    const float c6 = g_cellm[6], c7 = g_cellm[7], c8 = g_cellm[8];
    const float rsafe  = g_rsafe;
    const int   cellok = g_cellok;
    const float INF = 3.402823466e38f;

    float qi = 0.0f;
    int   vf = 0;

    if (active) {
        float pix = pos[3*i], piy = pos[3*i+1], piz = pos[3*i+2];
        float seld2[4]; int selj[4];
        bool valid = false;

        if (cellok) {
            float4 fi = g_fracA[i];
            int c  = g_cellOf[i];
            int cx = c & 7, cy = (c >> 3) & 7, cz = c >> 6;
            float bd2[4] = {INF, INF, INF, INF};
            int   bj [4] = {0x7fffffff, 0x7fffffff, 0x7fffffff, 0x7fffffff};
            int found = 0;
            if (lane < 27) {
                int ox = lane % 3 - 1, oy = (lane / 3) % 3 - 1, oz = lane / 9 - 1;
                int nc = ((cx + ox) & 7) | (((cy + oy) & 7) << 3) | (((cz + oz) & 7) << 6);
                int st = g_cellStart[nc], cnt = g_cellCnt[nc];
                for (int s = st; s < st + cnt; s++) {
                    float4 fj = g_sfrac[s];
                    if (fj.w == B_SI) continue;        // O neighbours only
                    int jo = g_sorig[s];
                    if (jo == i) continue;
                    float fx = fi.x - fj.x; fx -= rintf(fx);
                    float fy = fi.y - fj.y; fy -= rintf(fy);
                    float fz = fi.z - fj.z; fz -= rintf(fz);
                    float dx = fx*c0 + fy*c3 + fz*c6;
                    float dy = fx*c1 + fy*c4 + fz*c7;
                    float dz = fx*c2 + fy*c5 + fz*c8;
                    float d2 = dx*dx + dy*dy + dz*dz;
                    found++;
                    insert4(bd2, bj, d2, jo);
                }
            }
            int foundTot = __reduce_add_sync(0xffffffffu, found);
            warp_merge_top4(bd2, bj, lane, seld2, selj);
            int v = 0;
            if (lane == 0 && foundTot >= 4 && selj[3] < n) {
                float dmax = 0.0f;
                #pragma unroll
                for (int k = 0; k < 4; k++) {
                    int j = selj[k];
                    float dx0 = pix - pos[3*j];
                    float dy0 = piy - pos[3*j+1];
                    float dz0 = piz - pos[3*j+2];
                    float fx = dx0*i0v + dy0*i3v + dz0*i6v;
                    float fy = dx0*i1v + dy0*i4v + dz0*i7v;
                    float fz = dx0*i2v + dy0*i5v + dz0*i8v;
                    fx -= rintf(fx); fy -= rintf(fy); fz -= rintf(fz);
                    float dx = fx*c0 + fy*c3 + fz*c6;
                    float dy = fx*c1 + fy*c4 + fz*c7;
                    float dz = fx*c2 + fy*c5 + fz*c8;
                    dmax = fmaxf(dmax, dx*dx + dy*dy + dz*dz);
                }
                v = (dmax < rsafe * rsafe) ? 1 : 0;
            }
            valid = __shfl_sync(0xffffffffu, v, 0) != 0;
        }

        if (!valid) {
            // full scan fallback (exact)
            float bd2[4] = {INF, INF, INF, INF};
            int   bj [4] = {0x7fffffff, 0x7fffffff, 0x7fffffff, 0x7fffffff};
            for (int j = lane; j < n; j += 32) {
                if (j == i || species[j] == 0) continue;
                float dx0 = pix - pos[3*j];
                float dy0 = piy - pos[3*j+1];
                float dz0 = piz - pos[3*j+2];
                float fx = dx0*i0v + dy0*i3v + dz0*i6v;
                float fy = dx0*i1v + dy0*i4v + dz0*i7v;
                float fz = dx0*i2v + dy0*i5v + dz0*i8v;
                fx -= rintf(fx); fy -= rintf(fy); fz -= rintf(fz);
                float dx = fx*c0 + fy*c3 + fz*c6;
                float dy = fx*c1 + fy*c4 + fz*c7;
                float dz = fx*c2 + fy*c5 + fz*c8;
                float d2 = dx*dx + dy*dy + dz*dz;
                insert4(bd2, bj, d2, j);
            }
            warp_merge_top4(bd2, bj, lane, seld2, selj);
        }

        if (lane == 0 && selj[3] < n) {
            float ux[4], uy[4], uz[4], dmax = 0.0f;
            #pragma unroll
            for (int k = 0; k < 4; k++) {
                int j = selj[k];
                float dx0 = pix - pos[3*j];
                float dy0 = piy - pos[3*j+1];
                float dz0 = piz - pos[3*j+2];
                float fx = dx0*i0v + dy0*i3v + dz0*i6v;
                float fy = dx0*i1v + dy0*i4v + dz0*i7v;
                float fz = dx0*i2v + dy0*i5v + dz0*i8v;
                fx -= rintf(fx); fy -= rintf(fy); fz -= rintf(fz);
                float dx = fx*c0 + fy*c3 + fz*c6;
                float dy = fx*c1 + fy*c4 + fz*c7;
                float dz = fx*c2 + fy*c5 + fz*c8;
                float dist = sqrtf(seld2[k]);
                dmax = fmaxf(dmax, dist);
                ux[k] = dx / dist; uy[k] = dy / dist; uz[k] = dz / dist;
            }
            float s = 0.0f;
            #pragma unroll
            for (int k = 0; k < 4; k++)
                #pragma unroll
                for (int l = k + 1; l < 4; l++) {
                    float cc = ux[k]*ux[l] + uy[k]*uy[l] + uz[k]*uz[l];
                    float tt = cc + (1.0f / 3.0f);
                    s += tt * tt;
                }
            if (dmax < CUTOFF) { qi = 1.0f - 0.375f * s; vf = 1; }
        }
    }

    __shared__ double s_q[8];
    __shared__ int    s_v[8];
    if (lane == 0) { s_q[wib] = (double)qi; s_v[wib] = vf; }
    __syncthreads();
    if (threadIdx.x == 0) {
        double qs = 0.0; int vs = 0;
        #pragma unroll
        for (int k = 0; k < 8; k++) { qs += s_q[k]; vs += s_v[k]; }
        if (vs > 0) {
            atomicAdd(&g_qsum, qs);
            atomicAdd(&g_vfsum, (double)vs);
        }
    }
}

// ---------------- finalize A: G(r), T(r), integrand, q_tet --------------------------
__global__ void __launch_bounds__(256)
finalizeA_kernel(const float* __restrict__ rbins, float* __restrict__ out,
                 int n, int nbins, int nq) {
    int t = threadIdx.x;
    float rho = g_rho, dr = g_dr, mb = g_meanb;
    if (t < nbins) {
        float r     = rbins[t];
        float shell = 4.0f * PI_F * r * r * dr;
        float hv    = (float)g_hist[t] / (mb * mb);
        float G     = hv / ((float)n * rho * shell);
        out[t]          = G;
        out[nbins + t]  = 4.0f * PI_F * rho * r * G;
        g_integ[t] = r * r * (G - 1.0f);
    }
    if (t == 0) {
        double denom = g_vfsum > 1.0 ? g_vfsum : 1.0;
        out[2 * nbins + nq] = (float)(g_qsum / denom);
    }
}

// ---------------- finalize B: S(Q), one warp per q-value ----------------------------
__global__ void __launch_bounds__(256)
sq_kernel(const float* __restrict__ rbins, const float* __restrict__ qbins,
          float* __restrict__ out, int nbins, int nq) {
    int warp = (blockIdx.x * blockDim.x + threadIdx.x) >> 5;
    int lane = threadIdx.x & 31;
    if (warp >= nq) return;
    float q   = qbins[warp];
    float rho = g_rho, dr = g_dr;
    float s = 0.0f;
    for (int k = lane; k < nbins; k += 32) {
        float qr = q * rbins[k];
        float x  = qr / PI_F;              // mimic jnp.sinc(qr/pi)
        float px = PI_F * x;
        float sc = (px == 0.0f) ? 1.0f : (sinf(px) / px);
        s += g_integ[k] * sc;
    }
    #pragma unroll
    for (int o = 16; o > 0; o >>= 1) s += __shfl_down_sync(0xffffffffu, s, o);
    if (lane == 0) out[2 * nbins + warp] = 1.0f + 4.0f * PI_F * rho * dr * s;
}

// ---------------- launch ------------------------------------------------------------
extern "C" void kernel_launch(void* const* d_in, const int* in_sizes, int n_in,
                              void* d_out, int out_size) {
    const float* pos     = (const float*)d_in[0];
    const float* cell    = (const float*)d_in[1];
    const float* rbins   = (const float*)d_in[2];
    const float* qbins   = (const float*)d_in[3];
    const int*   species = (const int*)  d_in[4];
    int n     = in_sizes[0] / 3;
    int nbins = in_sizes[2];
    int nq    = in_sizes[3];

    prep_kernel<<<1, 256>>>(cell, rbins, species, n, nbins);
    count_kernel<<<(n + 255) / 256, 256>>>(pos, species, n);
    scan_kernel<<<1, 512>>>();
    scatter_kernel<<<(n + 255) / 256, 256>>>(n);

    int tilesI = (n + 127) / 128, tilesJ = (n + 511) / 512;
    int gridPair = tilesI * tilesJ;
    if (gridPair < NCELLS) gridPair = NCELLS;
    pair_cells_kernel<<<gridPair, 128>>>(n, nbins);

    qtet_kernel<<<(n * 32 + 255) / 256, 256>>>(pos, species, n);

    finalizeA_kernel<<<1, 256>>>(rbins, (float*)d_out, n, nbins, nq);
    sq_kernel<<<(nq * 32 + 255) / 256, 256>>>(rbins, qbins, (float*)d_out, nbins, nq);
}

// round 6
// speedup vs baseline: 4.0858x; 1.3161x over previous
#include <cuda_runtime.h>
#include <math.h>

#define B_SI 4.1491f
#define B_O  5.803f
#define CUTOFF 3.5f
#define PI_F 3.14159274101257324f   // (float)M_PI

#define CDIM   8
#define NCELLS 512                  // CDIM^3
#define NMAX   8192

// ---------------- device globals (scratch; no allocations allowed) ----------------
__device__ float  g_inv[9];
__device__ float  g_cellm[9];
__device__ float  g_rho, g_meanb, g_r0, g_dr, g_rsafe;
__device__ int    g_cellok, g_nSi;
__device__ double g_hist[256];
__device__ double g_qsum, g_vfsum;

__device__ float4 g_fracA[NMAX];        // per ORIGINAL atom: wrapped frac xyz + b
__device__ int    g_cellOf[NMAX];
__device__ float4 g_scart[NMAX];        // cell-sorted cartesian (wrapped) + b
__device__ int    g_sorig[NMAX];
__device__ int    g_siSlot[NMAX];       // sorted slots of Si atoms
__device__ int    g_siCell[NMAX];
__device__ int    g_cellStart[NCELLS + 1];

// ---------------- helpers ----------------------------------------------------------
__device__ __forceinline__ void insert4(float bd2[4], int bj[4], float dd, int jj) {
    if (dd < bd2[3]) {
        #pragma unroll
        for (int k = 0; k < 4; k++) {
            if (dd < bd2[k]) {
                float td = bd2[k]; bd2[k] = dd; dd = td;
                int   tj = bj[k];  bj[k]  = jj; jj = tj;
            }
        }
    }
}

__device__ __forceinline__ void warp_merge_top4(float bd2[4], int bj[4], int lane,
                                                float seld2[4], int selj[4]) {
    const float INF = 3.402823466e38f;
    int ptr = 0;
    #pragma unroll
    for (int r = 0; r < 4; r++) {
        float mv = (ptr < 4) ? bd2[ptr] : INF;
        int   mj = (ptr < 4) ? bj[ptr]  : 0x7fffffff;
        int   ml = lane;
        #pragma unroll
        for (int o = 16; o > 0; o >>= 1) {
            float ov = __shfl_down_sync(0xffffffffu, mv, o);
            int   oj = __shfl_down_sync(0xffffffffu, mj, o);
            int   ol = __shfl_down_sync(0xffffffffu, ml, o);
            if (ov < mv || (ov == mv && oj < mj)) { mv = ov; mj = oj; ml = ol; }
        }
        mv = __shfl_sync(0xffffffffu, mv, 0);
        mj = __shfl_sync(0xffffffffu, mj, 0);
        ml = __shfl_sync(0xffffffffu, ml, 0);
        if (lane == ml) ptr++;
        seld2[r] = mv; selj[r] = mj;
    }
}

// ---------------- build: prep + cell assign + scan + scatter + Si list (1 block) ---
__global__ void __launch_bounds__(512)
build_kernel(const float* __restrict__ pos, const float* __restrict__ cell,
             const float* __restrict__ rbins, const int* __restrict__ species,
             int n, int nbins) {
    __shared__ int   scnt[NCELLS];
    __shared__ int   sfill[NCELLS];
    __shared__ int   sscan[NCELLS];
    __shared__ int   smax[512];
    __shared__ float sred[512];
    __shared__ int   sSi;
    __shared__ float s_inv[9], s_cell[9];

    int t = threadIdx.x;
    if (t < NCELLS) scnt[t] = 0;
    for (int k = t; k < 256; k += 512) g_hist[k] = 0.0;
    if (t == 0) {
        sSi = 0;
        g_qsum = 0.0; g_vfsum = 0.0;
        float a[9];
        #pragma unroll
        for (int k = 0; k < 9; k++) { a[k] = cell[k]; g_cellm[k] = a[k]; s_cell[k] = a[k]; }
        float c00 = a[4]*a[8] - a[5]*a[7];
        float c01 = a[5]*a[6] - a[3]*a[8];
        float c02 = a[3]*a[7] - a[4]*a[6];
        float det = a[0]*c00 + a[1]*c01 + a[2]*c02;
        float id  = 1.0f / det;
        float iv[9];
        iv[0] = c00*id;  iv[3] = c01*id;  iv[6] = c02*id;
        iv[1] = (a[2]*a[7] - a[1]*a[8])*id;
        iv[4] = (a[0]*a[8] - a[2]*a[6])*id;
        iv[7] = (a[1]*a[6] - a[0]*a[7])*id;
        iv[2] = (a[1]*a[5] - a[2]*a[4])*id;
        iv[5] = (a[2]*a[3] - a[0]*a[5])*id;
        iv[8] = (a[0]*a[4] - a[1]*a[3])*id;
        #pragma unroll
        for (int k = 0; k < 9; k++) { g_inv[k] = iv[k]; s_inv[k] = iv[k]; }
        float adet = fabsf(det);
        g_rho = (float)n / adet;
        float r0 = rbins[0], dr = rbins[1] - rbins[0];
        g_r0 = r0; g_dr = dr;
        // perpendicular widths
        float n1 = sqrtf(c00*c00 + (a[5]*a[6]-a[3]*a[8])*(a[5]*a[6]-a[3]*a[8])
                                 + (a[3]*a[7]-a[4]*a[6])*(a[3]*a[7]-a[4]*a[6]));
        float x31x = a[7]*a[2]-a[8]*a[1], x31y = a[8]*a[0]-a[6]*a[2], x31z = a[6]*a[1]-a[7]*a[0];
        float n2 = sqrtf(x31x*x31x + x31y*x31y + x31z*x31z);
        float x12x = a[1]*a[5]-a[2]*a[4], x12y = a[2]*a[3]-a[0]*a[5], x12z = a[0]*a[4]-a[1]*a[3];
        float n3 = sqrtf(x12x*x12x + x12y*x12y + x12z*x12z);
        float pmin = fminf(adet/n1, fminf(adet/n2, adet/n3));
        float rmax = r0 + (float)(nbins - 1) * dr;
        g_cellok = (rmax * (float)CDIM * 0.5f <= pmin) ? 1 : 0;
        g_rsafe  = pmin / (float)CDIM;
    }
    __syncthreads();

    float bsum = 0.0f;
    for (int i = t; i < n; i += 512) {
        float px = pos[3*i], py = pos[3*i+1], pz = pos[3*i+2];
        float fx = px*s_inv[0] + py*s_inv[3] + pz*s_inv[6];
        float fy = px*s_inv[1] + py*s_inv[4] + pz*s_inv[7];
        float fz = px*s_inv[2] + py*s_inv[5] + pz*s_inv[8];
        fx -= floorf(fx); fy -= floorf(fy); fz -= floorf(fz);
        int cx = min((int)(fx * (float)CDIM), CDIM - 1);
        int cy = min((int)(fy * (float)CDIM), CDIM - 1);
        int cz = min((int)(fz * (float)CDIM), CDIM - 1);
        int c  = cx | (cy << 3) | (cz << 6);
        float b = (species[i] == 0) ? B_SI : B_O;
        float4 fr; fr.x = fx; fr.y = fy; fr.z = fz; fr.w = b;
        g_fracA[i]  = fr;
        g_cellOf[i] = c;
        bsum += b;
        atomicAdd(&scnt[c], 1);
    }
    sred[t] = bsum; __syncthreads();
    for (int o = 256; o > 0; o >>= 1) { if (t < o) sred[t] += sred[t + o]; __syncthreads(); }
    if (t == 0) g_meanb = sred[0] / (float)n;

    // scan over 512 cells
    int cnt = scnt[t];
    sscan[t] = cnt; __syncthreads();
    for (int off = 1; off < NCELLS; off <<= 1) {
        int v = (t >= off) ? sscan[t - off] : 0;
        __syncthreads();
        sscan[t] += v;
        __syncthreads();
    }
    int ex = sscan[t] - cnt;
    g_cellStart[t] = ex;
    sfill[t] = ex;
    if (t == NCELLS - 1) g_cellStart[NCELLS] = sscan[t];
    // degenerate guard: any cell with >256 atoms -> brute path
    smax[t] = cnt; __syncthreads();
    for (int o = 256; o > 0; o >>= 1) { if (t < o) smax[t] = max(smax[t], smax[t + o]); __syncthreads(); }
    if (t == 0 && smax[0] > 256) g_cellok = 0;
    __syncthreads();

    // scatter + Si list
    for (int i = t; i < n; i += 512) {
        int c = g_cellOf[i];
        int s = atomicAdd(&sfill[c], 1);
        float4 fr = g_fracA[i];
        float4 cc;
        cc.x = fr.x*s_cell[0] + fr.y*s_cell[3] + fr.z*s_cell[6];
        cc.y = fr.x*s_cell[1] + fr.y*s_cell[4] + fr.z*s_cell[7];
        cc.z = fr.x*s_cell[2] + fr.y*s_cell[5] + fr.z*s_cell[8];
        cc.w = fr.w;
        g_scart[s] = cc;
        g_sorig[s] = i;
        if (species[i] == 0) {
            int k = atomicAdd(&sSi, 1);
            g_siSlot[k] = s;
            g_siCell[k] = c;
        }
    }
    __syncthreads();
    if (t == 0) g_nSi = sSi;
}

// ---------------- main: pair histogram (blocks < pairBlocks) + qtet (rest) ---------
__global__ void __launch_bounds__(128)
main_kernel(const float* __restrict__ pos, const int* __restrict__ species,
            int n, int nbins, int pairBlocks) {
    int bx = blockIdx.x;
    int t  = threadIdx.x;

    if (bx < pairBlocks) {
        // ===================== pair histogram =====================
        const int cellok = g_cellok;
        if (cellok && bx >= NCELLS) return;

        __shared__ float4 scen[256];
        __shared__ float4 sj[512];
        __shared__ float  shist[256];
        __shared__ int    nbS[63];
        __shared__ int    nbCum[64];
        __shared__ float  shx[63], shy[63], shz[63];

        shist[t] = 0.0f; shist[t + 128] = 0.0f;

        const float r0 = g_r0, dr = g_dr;
        const float rmax  = r0 + (float)(nbins - 1) * dr;
        const float d2max = rmax * rmax + 0.01f;
        const float invdr = 1.0f / dr;

        if (cellok) {
            int c  = bx;
            int cx = c & 7, cy = (c >> 3) & 7, cz = c >> 6;
            int myCnt = 0;
            if (t < 63) {
                int tt = 62 + t;                    // t=0 -> self, t>0 -> positive half
                int ox = tt % 5 - 2, oy = (tt / 5) % 5 - 2, oz = tt / 25 - 2;
                int ucx = cx + ox, ucy = cy + oy, ucz = cz + oz;
                int nc = (ucx & 7) | ((ucy & 7) << 3) | ((ucz & 7) << 6);
                int st = g_cellStart[nc];
                nbS[t] = st;
                myCnt  = g_cellStart[nc + 1] - st;
                float wx = (float)((ucx < 0) ? -1 : (ucx >= CDIM ? 1 : 0));
                float wy = (float)((ucy < 0) ? -1 : (ucy >= CDIM ? 1 : 0));
                float wz = (float)((ucz < 0) ? -1 : (ucz >= CDIM ? 1 : 0));
                shx[t] = wx*g_cellm[0] + wy*g_cellm[3] + wz*g_cellm[6];
                shy[t] = wx*g_cellm[1] + wy*g_cellm[4] + wz*g_cellm[7];
                shz[t] = wx*g_cellm[2] + wy*g_cellm[5] + wz*g_cellm[8];
                nbCum[t] = myCnt;       // temp: counts
            }
            __syncthreads();
            if (t == 0) {
                int cum = 0;
                #pragma unroll 1
                for (int k = 0; k < 63; k++) { int v = nbCum[k]; nbCum[k] = cum; cum += v; }
                nbCum[63] = cum;
            }
            __syncthreads();
            int total     = nbCum[63];
            int selfStart = nbS[0];
            int nC        = nbCum[1] - nbCum[0];   // self count

            // stage center atoms (shift 0), pre-double weight
            for (int k = t; k < nC; k += 128) {
                float4 v = g_scart[selfStart + k];
                v.w *= 2.0f;
                scen[k] = v;
            }

            for (int base = 0; base < total; base += 512) {
                int lim = min(512, total - base);
                // stage chunk of neighborhood with shifts applied
                for (int k = t; k < lim; k += 128) {
                    int gj = base + k;
                    int lo = 0;
                    if (nbCum[lo + 32] <= gj) lo += 32;
                    if (nbCum[lo + 16] <= gj) lo += 16;
                    if (nbCum[lo +  8] <= gj) lo +=  8;
                    if (nbCum[lo +  4] <= gj) lo +=  4;
                    if (nbCum[lo +  2] <= gj) lo +=  2;
                    if (nbCum[lo +  1] <= gj) lo +=  1;
                    float4 p = g_scart[nbS[lo] + (gj - nbCum[lo])];
                    p.x += shx[lo]; p.y += shy[lo]; p.z += shz[lo];
                    sj[k] = p;
                }
                __syncthreads();
                // evaluate: center atom ii vs neighborhood atom gj, ii < min(gj, nC)
                for (int k = t; k < lim; k += 128) {
                    float4 pj = sj[k];
                    int gj = base + k;
                    int ilim = min(gj, nC);
                    for (int ii = 0; ii < ilim; ii++) {
                        float4 pi = scen[ii];
                        float dx = pi.x - pj.x;
                        float dy = pi.y - pj.y;
                        float dz = pi.z - pj.z;
                        float d2 = dx*dx + dy*dy + dz*dz;
                        if (d2 < d2max) {
                            float dist;
                            asm("sqrt.approx.f32 %0, %1;" : "=f"(dist) : "f"(d2));
                            float x  = (dist - r0) * invdr;
                            float xf = floorf(x);
                            int   b0 = (int)xf;
                            if (b0 >= 0 && b0 < nbins - 1) {
                                float f = x - xf;
                                float w = pi.w * pj.w;      // pi.w pre-doubled
                                atomicAdd(&shist[b0],     w * (1.0f - f));
                                atomicAdd(&shist[b0 + 1], w * f);
                            }
                        }
                    }
                }
                __syncthreads();
            }
        } else {
            // ---- brute fallback (general cells / degenerate) ----
            int tilesJ = (n + 511) >> 9;
            int ib = bx / tilesJ;
            int jb = bx % tilesJ;
            int iBase = ib * 128, jBase = jb * 512;
            const float c0 = g_cellm[0], c1 = g_cellm[1], c2 = g_cellm[2];
            const float c3 = g_cellm[3], c4 = g_cellm[4], c5 = g_cellm[5];
            const float c6 = g_cellm[6], c7 = g_cellm[7], c8 = g_cellm[8];
            if (iBase < n && jBase + 511 > iBase) {
                for (int k = t; k < 512; k += 128) {
                    int j = jBase + k;
                    float4 v;
                    if (j < n) v = g_fracA[j];
                    else { v.x = 1e18f; v.y = 1e18f; v.z = 1e18f; v.w = 0.0f; }
                    sj[k] = v;
                }
                __syncthreads();
                int i = iBase + t;
                if (i < n) {
                    float4 pi = g_fracA[i];
                    int kmin = i - jBase + 1; if (kmin < 0) kmin = 0;
                    int kmax = n - jBase; if (kmax > 512) kmax = 512;
                    for (int k = kmin; k < kmax; k++) {
                        float4 pj = sj[k];
                        float fx = pi.x - pj.x; fx -= rintf(fx);
                        float fy = pi.y - pj.y; fy -= rintf(fy);
                        float fz = pi.z - pj.z; fz -= rintf(fz);
                        float dx = fx*c0 + fy*c3 + fz*c6;
                        float dy = fx*c1 + fy*c4 + fz*c7;
                        float dz = fx*c2 + fy*c5 + fz*c8;
                        float d2 = dx*dx + dy*dy + dz*dz;
                        if (d2 < d2max) {
                            float dist = sqrtf(d2);
                            float x  = (dist - r0) * invdr;
                            float xf = floorf(x);
                            int   b0 = (int)xf;
                            if (b0 >= 0 && b0 < nbins - 1) {
                                float f = x - xf;
                                float w = 2.0f * pi.w * pj.w;
                                atomicAdd(&shist[b0],     w * (1.0f - f));
                                atomicAdd(&shist[b0 + 1], w * f);
                            }
                        }
                    }
                }
                __syncthreads();
            }
        }
        __syncthreads();
        for (int k = t; k < nbins; k += 128)
            if (shist[k] != 0.0f) atomicAdd(&g_hist[k], (double)shist[k]);
    } else {
        // ===================== tetrahedral order parameter =====================
        int qb   = bx - pairBlocks;
        int gw   = qb * 4 + (t >> 5);
        int lane = t & 31;
        int wib  = t >> 5;
        int nSi  = g_nSi;

        const float i0v = g_inv[0], i1v = g_inv[1], i2v = g_inv[2];
        const float i3v = g_inv[3], i4v = g_inv[4], i5v = g_inv[5];
        const float i6v = g_inv[6], i7v = g_inv[7], i8v = g_inv[8];
        const float c0 = g_cellm[0], c1 = g_cellm[1], c2 = g_cellm[2];
        const float c3 = g_cellm[3], c4 = g_cellm[4], c5 = g_cellm[5];
        const float c6 = g_cellm[6], c7 = g_cellm[7], c8 = g_cellm[8];
        const float rsafe  = g_rsafe;
        const int   cellok = g_cellok;
        const float INF = 3.402823466e38f;

        float qi = 0.0f;
        int   vf = 0;

        if (gw < nSi) {
            int slot = g_siSlot[gw];
            int i    = g_sorig[slot];
            float4 ci = g_scart[slot];
            float pix = pos[3*i], piy = pos[3*i+1], piz = pos[3*i+2];
            float seld2[4]; int selj[4];
            bool valid = false;

            if (cellok) {
                int c  = g_siCell[gw];
                int cx = c & 7, cy = (c >> 3) & 7, cz = c >> 6;
                float bd2[4] = {INF, INF, INF, INF};
                int   bj [4] = {0x7fffffff, 0x7fffffff, 0x7fffffff, 0x7fffffff};
                int found = 0;
                if (lane < 27) {
                    int ox = lane % 3 - 1, oy = (lane / 3) % 3 - 1, oz = lane / 9 - 1;
                    int ucx = cx + ox, ucy = cy + oy, ucz = cz + oz;
                    int nc = (ucx & 7) | ((ucy & 7) << 3) | ((ucz & 7) << 6);
                    float wx = (float)((ucx < 0) ? -1 : (ucx >= CDIM ? 1 : 0));
                    float wy = (float)((ucy < 0) ? -1 : (ucy >= CDIM ? 1 : 0));
                    float wz = (float)((ucz < 0) ? -1 : (ucz >= CDIM ? 1 : 0));
                    float sx = wx*c0 + wy*c3 + wz*c6;
                    float sy = wx*c1 + wy*c4 + wz*c7;
                    float sz = wx*c2 + wy*c5 + wz*c8;
                    int st = g_cellStart[nc], en = g_cellStart[nc + 1];
                    for (int s = st; s < en; s++) {
                        float4 fj = g_scart[s];
                        if (fj.w == B_SI || s == slot) continue;
                        float dx = ci.x - (fj.x + sx);
                        float dy = ci.y - (fj.y + sy);
                        float dz = ci.z - (fj.z + sz);
                        float d2 = dx*dx + dy*dy + dz*dz;
                        found++;
                        insert4(bd2, bj, d2, g_sorig[s]);
                    }
                }
                int foundTot = __reduce_add_sync(0xffffffffu, found);
                warp_merge_top4(bd2, bj, lane, seld2, selj);
                valid = (foundTot >= 4) && (seld2[3] < rsafe * rsafe);
            }

            if (!valid) {
                // exact full scan fallback
                float bd2[4] = {INF, INF, INF, INF};
                int   bj [4] = {0x7fffffff, 0x7fffffff, 0x7fffffff, 0x7fffffff};
                for (int j = lane; j < n; j += 32) {
                    if (j == i || species[j] == 0) continue;
                    float dx0 = pix - pos[3*j];
                    float dy0 = piy - pos[3*j+1];
                    float dz0 = piz - pos[3*j+2];
                    float fx = dx0*i0v + dy0*i3v + dz0*i6v;
                    float fy = dx0*i1v + dy0*i4v + dz0*i7v;
                    float fz = dx0*i2v + dy0*i5v + dz0*i8v;
                    fx -= rintf(fx); fy -= rintf(fy); fz -= rintf(fz);
                    float dx = fx*c0 + fy*c3 + fz*c6;
                    float dy = fx*c1 + fy*c4 + fz*c7;
                    float dz = fx*c2 + fy*c5 + fz*c8;
                    float d2 = dx*dx + dy*dy + dz*dz;
                    insert4(bd2, bj, d2, j);
                }
                warp_merge_top4(bd2, bj, lane, seld2, selj);
            }

            if (lane == 0 && selj[3] < n) {
                float ux[4], uy[4], uz[4], dmax = 0.0f;
                #pragma unroll
                for (int k = 0; k < 4; k++) {
                    int j = selj[k];
                    float dx0 = pix - pos[3*j];
                    float dy0 = piy - pos[3*j+1];
                    float dz0 = piz - pos[3*j+2];
                    float fx = dx0*i0v + dy0*i3v + dz0*i6v;
                    float fy = dx0*i1v + dy0*i4v + dz0*i7v;
                    float fz = dx0*i2v + dy0*i5v + dz0*i8v;
                    fx -= rintf(fx); fy -= rintf(fy); fz -= rintf(fz);
                    float dx = fx*c0 + fy*c3 + fz*c6;
                    float dy = fx*c1 + fy*c4 + fz*c7;
                    float dz = fx*c2 + fy*c5 + fz*c8;
                    float dist = sqrtf(seld2[k]);
                    dmax = fmaxf(dmax, dist);
                    ux[k] = dx / dist; uy[k] = dy / dist; uz[k] = dz / dist;
                }
                float s = 0.0f;
                #pragma unroll
                for (int k = 0; k < 4; k++)
                    #pragma unroll
                    for (int l = k + 1; l < 4; l++) {
                        float cc = ux[k]*ux[l] + uy[k]*uy[l] + uz[k]*uz[l];
                        float tt = cc + (1.0f / 3.0f);
                        s += tt * tt;
                    }
                if (dmax < CUTOFF) { qi = 1.0f - 0.375f * s; vf = 1; }
            }
        }

        __shared__ double s_q[4];
        __shared__ int    s_v[4];
        if (lane == 0) { s_q[wib] = (double)qi; s_v[wib] = vf; }
        __syncthreads();
        if (t == 0) {
            double qs = 0.0; int vs = 0;
            #pragma unroll
            for (int k = 0; k < 4; k++) { qs += s_q[k]; vs += s_v[k]; }
            if (vs > 0) {
                atomicAdd(&g_qsum, qs);
                atomicAdd(&g_vfsum, (double)vs);
            }
        }
    }
}

// ---------------- final: G(r), T(r), q_tet (block 0) + S(Q) (all blocks) -----------
__global__ void __launch_bounds__(256)
final_kernel(const float* __restrict__ rbins, const float* __restrict__ qbins,
             float* __restrict__ out, int n, int nbins, int nq) {
    __shared__ float integ[256];
    int t = threadIdx.x;
    float rho = g_rho, dr = g_dr, mb = g_meanb;
    if (t < nbins) {
        float r     = rbins[t];
        float shell = 4.0f * PI_F * r * r * dr;
        float hv    = (float)g_hist[t] / (mb * mb);
        float G     = hv / ((float)n * rho * shell);
        integ[t] = r * r * (G - 1.0f);
        if (blockIdx.x == 0) {
            out[t]         = G;
            out[nbins + t] = 4.0f * PI_F * rho * r * G;
        }
    }
    if (blockIdx.x == 0 && t == 0) {
        double denom = g_vfsum > 1.0 ? g_vfsum : 1.0;
        out[2 * nbins + nq] = (float)(g_qsum / denom);
    }
    __syncthreads();
    int warp = t >> 5, lane = t & 31;
    int qidx = blockIdx.x * 8 + warp;
    if (qidx < nq) {
        float q = qbins[qidx];
        float s = 0.0f;
        for (int k = lane; k < nbins; k += 32) {
            float qr = q * rbins[k];
            float x  = qr / PI_F;              // mimic jnp.sinc(qr/pi)
            float px = PI_F * x;
            float sc = (px == 0.0f) ? 1.0f : (sinf(px) / px);
            s += integ[k] * sc;
        }
        #pragma unroll
        for (int o = 16; o > 0; o >>= 1) s += __shfl_down_sync(0xffffffffu, s, o);
        if (lane == 0) out[2 * nbins + qidx] = 1.0f + 4.0f * PI_F * rho * dr * s;
    }
}

// ---------------- launch ------------------------------------------------------------
extern "C" void kernel_launch(void* const* d_in, const int* in_sizes, int n_in,
                              void* d_out, int out_size) {
    const float* pos     = (const float*)d_in[0];
    const float* cell    = (const float*)d_in[1];
    const float* rbins   = (const float*)d_in[2];
    const float* qbins   = (const float*)d_in[3];
    const int*   species = (const int*)  d_in[4];
    int n     = in_sizes[0] / 3;
    int nbins = in_sizes[2];
    int nq    = in_sizes[3];

    build_kernel<<<1, 512>>>(pos, cell, rbins, species, n, nbins);

    int tilesI = (n + 127) / 128, tilesJ = (n + 511) / 512;
    int pairBlocks = tilesI * tilesJ;
    if (pairBlocks < NCELLS) pairBlocks = NCELLS;
    int qtetBlocks = (n + 3) / 4;             // 4 warps per block, worst case all Si
    main_kernel<<<pairBlocks + qtetBlocks, 128>>>(pos, species, n, nbins, pairBlocks);

    final_kernel<<<(nq + 7) / 8, 256>>>(rbins, qbins, (float*)d_out, n, nbins, nq);
}

// round 7
// speedup vs baseline: 4.2390x; 1.0375x over previous
#include <cuda_runtime.h>
#include <math.h>

#define B_SI 4.1491f
#define B_O  5.803f
#define CUTOFF 3.5f
#define PI_F 3.14159274101257324f   // (float)M_PI

#define CDIM   8
#define NCELLS 512                  // CDIM^3
#define NMAX   8192

// ---------------- device globals (scratch; no allocations allowed) ----------------
__device__ float  g_inv[9];
__device__ float  g_cellm[9];
__device__ float  g_rho, g_meanb, g_r0, g_dr, g_rsafe;
__device__ int    g_cellok;
__device__ double g_hist[256];       // zeroed initially; re-zeroed by final_kernel
__device__ double g_qsum, g_vfsum;   // same invariant
__device__ float  g_bsum;            // reset by assign's scan phase
__device__ int    g_arriveA, g_arriveF;   // arrival counters, self-resetting

__device__ float4 g_fracA[NMAX];     // per ORIGINAL atom: wrapped frac xyz + b
__device__ int    g_cellOf[NMAX];
__device__ float4 g_scart[NMAX];     // cell-sorted cartesian (wrapped) + b
__device__ int    g_sorig[NMAX];
__device__ int    g_scellOf[NMAX];   // cell id per sorted slot
__device__ int    g_cellCnt[NCELLS]; // zero before assign; re-zeroed in scan phase
__device__ int    g_cellStart[NCELLS + 1];
__device__ int    g_cellFill[NCELLS];

// ---------------- helpers ----------------------------------------------------------
__device__ __forceinline__ void insert4(float bd2[4], int bj[4], float dd, int jj) {
    if (dd < bd2[3]) {
        #pragma unroll
        for (int k = 0; k < 4; k++) {
            if (dd < bd2[k]) {
                float td = bd2[k]; bd2[k] = dd; dd = td;
                int   tj = bj[k];  bj[k]  = jj; jj = tj;
            }
        }
    }
}

__device__ __forceinline__ void warp_merge_top4(float bd2[4], int bj[4], int lane,
                                                float seld2[4], int selj[4]) {
    const float INF = 3.402823466e38f;
    int ptr = 0;
    #pragma unroll
    for (int r = 0; r < 4; r++) {
        float mv = (ptr < 4) ? bd2[ptr] : INF;
        int   mj = (ptr < 4) ? bj[ptr]  : 0x7fffffff;
        int   ml = lane;
        #pragma unroll
        for (int o = 16; o > 0; o >>= 1) {
            float ov = __shfl_down_sync(0xffffffffu, mv, o);
            int   oj = __shfl_down_sync(0xffffffffu, mj, o);
            int   ol = __shfl_down_sync(0xffffffffu, ml, o);
            if (ov < mv || (ov == mv && oj < mj)) { mv = ov; mj = oj; ml = ol; }
        }
        mv = __shfl_sync(0xffffffffu, mv, 0);
        mj = __shfl_sync(0xffffffffu, mj, 0);
        ml = __shfl_sync(0xffffffffu, ml, 0);
        if (lane == ml) ptr++;
        seld2[r] = mv; selj[r] = mj;
    }
}

__device__ __forceinline__ void compute_inv(const float a[9], float iv[9], float* det_out) {
    float c00 = a[4]*a[8] - a[5]*a[7];
    float c01 = a[5]*a[6] - a[3]*a[8];
    float c02 = a[3]*a[7] - a[4]*a[6];
    float det = a[0]*c00 + a[1]*c01 + a[2]*c02;
    float id  = 1.0f / det;
    iv[0] = c00*id;  iv[3] = c01*id;  iv[6] = c02*id;
    iv[1] = (a[2]*a[7] - a[1]*a[8])*id;
    iv[4] = (a[0]*a[8] - a[2]*a[6])*id;
    iv[7] = (a[1]*a[6] - a[0]*a[7])*id;
    iv[2] = (a[1]*a[5] - a[2]*a[4])*id;
    iv[5] = (a[2]*a[3] - a[0]*a[5])*id;
    iv[8] = (a[0]*a[4] - a[1]*a[3])*id;
    *det_out = det;
}

// ---------------- assign: frac coords + cell counts; last block scans ---------------
__global__ void __launch_bounds__(128)
assign_kernel(const float* __restrict__ pos, const float* __restrict__ cell,
              const float* __restrict__ rbins, const int* __restrict__ species,
              int n, int nbins) {
    __shared__ float s_inv[9];
    __shared__ float sred[128];
    __shared__ int   sLast;

    int t = threadIdx.x;
    if (t == 0) {
        float a[9], iv[9], det;
        #pragma unroll
        for (int k = 0; k < 9; k++) a[k] = cell[k];
        compute_inv(a, iv, &det);
        #pragma unroll
        for (int k = 0; k < 9; k++) s_inv[k] = iv[k];
    }
    __syncthreads();

    int i = blockIdx.x * 128 + t;
    float b = 0.0f;
    if (i < n) {
        float px = pos[3*i], py = pos[3*i+1], pz = pos[3*i+2];
        float fx = px*s_inv[0] + py*s_inv[3] + pz*s_inv[6];
        float fy = px*s_inv[1] + py*s_inv[4] + pz*s_inv[7];
        float fz = px*s_inv[2] + py*s_inv[5] + pz*s_inv[8];
        fx -= floorf(fx); fy -= floorf(fy); fz -= floorf(fz);
        int cx = min((int)(fx * (float)CDIM), CDIM - 1);
        int cy = min((int)(fy * (float)CDIM), CDIM - 1);
        int cz = min((int)(fz * (float)CDIM), CDIM - 1);
        int c  = cx | (cy << 3) | (cz << 6);
        b = (species[i] == 0) ? B_SI : B_O;
        float4 fr; fr.x = fx; fr.y = fy; fr.z = fz; fr.w = b;
        g_fracA[i]  = fr;
        g_cellOf[i] = c;
        atomicAdd(&g_cellCnt[c], 1);
    }
    sred[t] = b; __syncthreads();
    for (int o = 64; o > 0; o >>= 1) { if (t < o) sred[t] += sred[t + o]; __syncthreads(); }
    if (t == 0) {
        if (sred[0] != 0.0f) atomicAdd(&g_bsum, sred[0]);
        __threadfence();
        int v = atomicAdd(&g_arriveA, 1);
        sLast = (v == (int)gridDim.x - 1) ? 1 : 0;
    }
    __syncthreads();
    if (!sLast) return;

    // ---------- scan phase (winner block only, 128 threads x 4 cells) ----------
    __shared__ int hs[128];
    int base4 = t * 4;
    int c4[4];
    #pragma unroll
    for (int k = 0; k < 4; k++) c4[k] = g_cellCnt[base4 + k];
    int sum = c4[0] + c4[1] + c4[2] + c4[3];
    hs[t] = sum; __syncthreads();
    for (int off = 1; off < 128; off <<= 1) {
        int v = (t >= off) ? hs[t - off] : 0;
        __syncthreads();
        hs[t] += v;
        __syncthreads();
    }
    int run = hs[t] - sum;
    #pragma unroll
    for (int k = 0; k < 4; k++) {
        g_cellStart[base4 + k] = run;
        g_cellFill[base4 + k]  = run;
        run += c4[k];
        g_cellCnt[base4 + k] = 0;           // re-zero for next replay
    }
    if (t == 127) g_cellStart[NCELLS] = run;
    __syncthreads();
    int mx = max(max(c4[0], c4[1]), max(c4[2], c4[3]));
    hs[t] = mx; __syncthreads();
    for (int o = 64; o > 0; o >>= 1) { if (t < o) hs[t] = max(hs[t], hs[t + o]); __syncthreads(); }

    if (t == 0) {
        float a[9], iv[9], det;
        #pragma unroll
        for (int k = 0; k < 9; k++) { a[k] = cell[k]; g_cellm[k] = a[k]; }
        compute_inv(a, iv, &det);
        #pragma unroll
        for (int k = 0; k < 9; k++) g_inv[k] = iv[k];
        float adet = fabsf(det);
        g_rho = (float)n / adet;
        float r0 = rbins[0], dr = rbins[1] - rbins[0];
        g_r0 = r0; g_dr = dr;
        // perpendicular widths
        float c00 = a[4]*a[8]-a[5]*a[7], c10 = a[5]*a[6]-a[3]*a[8], c20 = a[3]*a[7]-a[4]*a[6];
        float n1 = sqrtf(c00*c00 + c10*c10 + c20*c20);
        float x31x = a[7]*a[2]-a[8]*a[1], x31y = a[8]*a[0]-a[6]*a[2], x31z = a[6]*a[1]-a[7]*a[0];
        float n2 = sqrtf(x31x*x31x + x31y*x31y + x31z*x31z);
        float x12x = a[1]*a[5]-a[2]*a[4], x12y = a[2]*a[3]-a[0]*a[5], x12z = a[0]*a[4]-a[1]*a[3];
        float n3 = sqrtf(x12x*x12x + x12y*x12y + x12z*x12z);
        float pmin = fminf(adet/n1, fminf(adet/n2, adet/n3));
        float rmax = r0 + (float)(nbins - 1) * dr;
        g_cellok = (rmax * (float)CDIM * 0.5f <= pmin && hs[0] <= 256) ? 1 : 0;
        g_rsafe  = pmin / (float)CDIM;
        g_meanb  = g_bsum / (float)n;
        g_bsum   = 0.0f;                     // reset for next replay
        g_arriveA = 0;
    }
}

// ---------------- scatter into cell-sorted order ------------------------------------
__global__ void __launch_bounds__(128)
scatter_kernel(int n) {
    __shared__ float s_cell[9];
    int t = threadIdx.x;
    if (t == 0) {
        #pragma unroll
        for (int k = 0; k < 9; k++) s_cell[k] = g_cellm[k];
    }
    __syncthreads();
    int i = blockIdx.x * 128 + t;
    if (i >= n) return;
    int c = g_cellOf[i];
    int s = atomicAdd(&g_cellFill[c], 1);
    float4 fr = g_fracA[i];
    float4 cc;
    cc.x = fr.x*s_cell[0] + fr.y*s_cell[3] + fr.z*s_cell[6];
    cc.y = fr.x*s_cell[1] + fr.y*s_cell[4] + fr.z*s_cell[7];
    cc.z = fr.x*s_cell[2] + fr.y*s_cell[5] + fr.z*s_cell[8];
    cc.w = fr.w;
    g_scart[s]   = cc;
    g_sorig[s]   = i;
    g_scellOf[s] = c;
}

// ---------------- main: pair histogram (blocks < pairBlocks) + qtet (rest) ---------
__global__ void __launch_bounds__(128)
main_kernel(const float* __restrict__ pos, const int* __restrict__ species,
            int n, int nbins, int pairBlocks) {
    int bx = blockIdx.x;
    int t  = threadIdx.x;

    if (bx < pairBlocks) {
        // ===================== pair histogram =====================
        const int cellok = g_cellok;
        if (cellok && bx >= NCELLS) return;

        __shared__ float4 scen[256];
        __shared__ float4 sj[512];
        __shared__ float  shist[256];
        __shared__ int    nbS[63];
        __shared__ int    nbCum[64];
        __shared__ float  shx[63], shy[63], shz[63];

        shist[t] = 0.0f; shist[t + 128] = 0.0f;

        const float r0 = g_r0, dr = g_dr;
        const float rmax  = r0 + (float)(nbins - 1) * dr;
        const float d2max = rmax * rmax + 0.01f;
        const float invdr = 1.0f / dr;
        const float binoff = -r0 * invdr;

        if (cellok) {
            int c  = bx;
            int cx = c & 7, cy = (c >> 3) & 7, cz = c >> 6;
            if (t < 63) {
                int tt = 62 + t;                    // t=0 -> self, t>0 -> positive half
                int ox = tt % 5 - 2, oy = (tt / 5) % 5 - 2, oz = tt / 25 - 2;
                int ucx = cx + ox, ucy = cy + oy, ucz = cz + oz;
                int nc = (ucx & 7) | ((ucy & 7) << 3) | ((ucz & 7) << 6);
                int st = g_cellStart[nc];
                nbS[t] = st;
                int myCnt = g_cellStart[nc + 1] - st;
                float wx = (float)((ucx < 0) ? -1 : (ucx >= CDIM ? 1 : 0));
                float wy = (float)((ucy < 0) ? -1 : (ucy >= CDIM ? 1 : 0));
                float wz = (float)((ucz < 0) ? -1 : (ucz >= CDIM ? 1 : 0));
                shx[t] = wx*g_cellm[0] + wy*g_cellm[3] + wz*g_cellm[6];
                shy[t] = wx*g_cellm[1] + wy*g_cellm[4] + wz*g_cellm[7];
                shz[t] = wx*g_cellm[2] + wy*g_cellm[5] + wz*g_cellm[8];
                nbCum[t] = myCnt;       // temp: counts
            }
            __syncthreads();
            if (t == 0) {
                int cum = 0;
                #pragma unroll 1
                for (int k = 0; k < 63; k++) { int v = nbCum[k]; nbCum[k] = cum; cum += v; }
                nbCum[63] = cum;
            }
            __syncthreads();
            int total     = nbCum[63];
            int selfStart = nbS[0];
            int nC        = nbCum[1] - nbCum[0];   // self count

            // stage center atoms (shift 0), pre-double weight
            for (int k = t; k < nC; k += 128) {
                float4 v = g_scart[selfStart + k];
                v.w *= 2.0f;
                scen[k] = v;
            }

            for (int base = 0; base < total; base += 512) {
                int lim = min(512, total - base);
                // stage chunk of neighborhood with wrap shifts applied
                for (int k = t; k < lim; k += 128) {
                    int gj = base + k;
                    int lo = 0;
                    if (nbCum[lo + 32] <= gj) lo += 32;
                    if (nbCum[lo + 16] <= gj) lo += 16;
                    if (nbCum[lo +  8] <= gj) lo +=  8;
                    if (nbCum[lo +  4] <= gj) lo +=  4;
                    if (nbCum[lo +  2] <= gj) lo +=  2;
                    if (nbCum[lo +  1] <= gj) lo +=  1;
                    float4 p = g_scart[nbS[lo] + (gj - nbCum[lo])];
                    p.x += shx[lo]; p.y += shy[lo]; p.z += shz[lo];
                    sj[k] = p;
                }
                __syncthreads();
                // evaluate: center ii vs neighborhood gj, ii < min(gj, nC)
                for (int k = t; k < lim; k += 128) {
                    float4 pj = sj[k];
                    int gj = base + k;
                    int ilim = min(gj, nC);
                    #pragma unroll 2
                    for (int ii = 0; ii < ilim; ii++) {
                        float4 pi = scen[ii];
                        float dx = pi.x - pj.x;
                        float dy = pi.y - pj.y;
                        float dz = pi.z - pj.z;
                        float d2 = dx*dx + dy*dy + dz*dz;
                        if (d2 < d2max) {
                            float dist;
                            asm("sqrt.approx.f32 %0, %1;" : "=f"(dist) : "f"(d2));
                            float x  = fmaf(dist, invdr, binoff);
                            int   b0 = __float2int_rd(x);
                            if ((unsigned)b0 < (unsigned)(nbins - 1)) {
                                float f = x - (float)b0;
                                float w = pi.w * pj.w;      // pi.w pre-doubled
                                atomicAdd(&shist[b0],     w * (1.0f - f));
                                atomicAdd(&shist[b0 + 1], w * f);
                            }
                        }
                    }
                }
                __syncthreads();
            }
        } else {
            // ---- brute fallback (general cells / degenerate) ----
            int tilesJ = (n + 511) >> 9;
            int ib = bx / tilesJ;
            int jb = bx % tilesJ;
            int iBase = ib * 128, jBase = jb * 512;
            const float c0 = g_cellm[0], c1 = g_cellm[1], c2 = g_cellm[2];
            const float c3 = g_cellm[3], c4 = g_cellm[4], c5 = g_cellm[5];
            const float c6 = g_cellm[6], c7 = g_cellm[7], c8 = g_cellm[8];
            if (iBase < n && jBase + 511 > iBase) {
                for (int k = t; k < 512; k += 128) {
                    int j = jBase + k;
                    float4 v;
                    if (j < n) v = g_fracA[j];
                    else { v.x = 1e18f; v.y = 1e18f; v.z = 1e18f; v.w = 0.0f; }
                    sj[k] = v;
                }
                __syncthreads();
                int i = iBase + t;
                if (i < n) {
                    float4 pi = g_fracA[i];
                    int kmin = i - jBase + 1; if (kmin < 0) kmin = 0;
                    int kmax = n - jBase; if (kmax > 512) kmax = 512;
                    for (int k = kmin; k < kmax; k++) {
                        float4 pj = sj[k];
                        float fx = pi.x - pj.x; fx -= rintf(fx);
                        float fy = pi.y - pj.y; fy -= rintf(fy);
                        float fz = pi.z - pj.z; fz -= rintf(fz);
                        float dx = fx*c0 + fy*c3 + fz*c6;
                        float dy = fx*c1 + fy*c4 + fz*c7;
                        float dz = fx*c2 + fy*c5 + fz*c8;
                        float d2 = dx*dx + dy*dy + dz*dz;
                        if (d2 < d2max) {
                            float dist = sqrtf(d2);
                            float x  = fmaf(dist, invdr, binoff);
                            int   b0 = __float2int_rd(x);
                            if ((unsigned)b0 < (unsigned)(nbins - 1)) {
                                float f = x - (float)b0;
                                float w = 2.0f * pi.w * pj.w;
                                atomicAdd(&shist[b0],     w * (1.0f - f));
                                atomicAdd(&shist[b0 + 1], w * f);
                            }
                        }
                    }
                }
                __syncthreads();
            }
        }
        __syncthreads();
        for (int k = t; k < nbins; k += 128)
            if (shist[k] != 0.0f) atomicAdd(&g_hist[k], (double)shist[k]);
    } else {
        // ===================== tetrahedral order parameter =====================
        int qb   = bx - pairBlocks;
        int gw   = qb * 4 + (t >> 5);       // sorted slot index
        int lane = t & 31;
        int wib  = t >> 5;

        const float i0v = g_inv[0], i1v = g_inv[1], i2v = g_inv[2];
        const float i3v = g_inv[3], i4v = g_inv[4], i5v = g_inv[5];
        const float i6v = g_inv[6], i7v = g_inv[7], i8v = g_inv[8];
        const float c0 = g_cellm[0], c1 = g_cellm[1], c2 = g_cellm[2];
        const float c3 = g_cellm[3], c4 = g_cellm[4], c5 = g_cellm[5];
        const float c6 = g_cellm[6], c7 = g_cellm[7], c8 = g_cellm[8];
        const float rsafe  = g_rsafe;
        const int   cellok = g_cellok;
        const float INF = 3.402823466e38f;

        float qi = 0.0f;
        int   vf = 0;

        float4 ci;
        bool active = false;
        if (gw < n) {
            ci = g_scart[gw];
            active = (ci.w == B_SI);         // Si centres only
        }

        if (active) {
            int slot = gw;
            int i    = g_sorig[slot];
            float pix = pos[3*i], piy = pos[3*i+1], piz = pos[3*i+2];
            float seld2[4]; int selj[4];
            bool valid = false;

            if (cellok) {
                int c  = g_scellOf[slot];
                int cx = c & 7, cy = (c >> 3) & 7, cz = c >> 6;
                float bd2[4] = {INF, INF, INF, INF};
                int   bj [4] = {0x7fffffff, 0x7fffffff, 0x7fffffff, 0x7fffffff};
                int found = 0;
                if (lane < 27) {
                    int ox = lane % 3 - 1, oy = (lane / 3) % 3 - 1, oz = lane / 9 - 1;
                    int ucx = cx + ox, ucy = cy + oy, ucz = cz + oz;
                    int nc = (ucx & 7) | ((ucy & 7) << 3) | ((ucz & 7) << 6);
                    float wx = (float)((ucx < 0) ? -1 : (ucx >= CDIM ? 1 : 0));
                    float wy = (float)((ucy < 0) ? -1 : (ucy >= CDIM ? 1 : 0));
                    float wz = (float)((ucz < 0) ? -1 : (ucz >= CDIM ? 1 : 0));
                    float sx = wx*c0 + wy*c3 + wz*c6;
                    float sy = wx*c1 + wy*c4 + wz*c7;
                    float sz = wx*c2 + wy*c5 + wz*c8;
                    int st = g_cellStart[nc], en = g_cellStart[nc + 1];
                    for (int s = st; s < en; s++) {
                        float4 fj = g_scart[s];
                        if (fj.w == B_SI || s == slot) continue;
                        float dx = ci.x - (fj.x + sx);
                        float dy = ci.y - (fj.y + sy);
                        float dz = ci.z - (fj.z + sz);
                        float d2 = dx*dx + dy*dy + dz*dz;
                        found++;
                        insert4(bd2, bj, d2, g_sorig[s]);
                    }
                }
                int foundTot = __reduce_add_sync(0xffffffffu, found);
                warp_merge_top4(bd2, bj, lane, seld2, selj);
                valid = (foundTot >= 4) && (seld2[3] < rsafe * rsafe);
            }

            if (!valid) {
                // exact full-scan fallback
                float bd2[4] = {INF, INF, INF, INF};
                int   bj [4] = {0x7fffffff, 0x7fffffff, 0x7fffffff, 0x7fffffff};
                for (int j = lane; j < n; j += 32) {
                    if (j == i || species[j] == 0) continue;
                    float dx0 = pix - pos[3*j];
                    float dy0 = piy - pos[3*j+1];
                    float dz0 = piz - pos[3*j+2];
                    float fx = dx0*i0v + dy0*i3v + dz0*i6v;
                    float fy = dx0*i1v + dy0*i4v + dz0*i7v;
                    float fz = dx0*i2v + dy0*i5v + dz0*i8v;
                    fx -= rintf(fx); fy -= rintf(fy); fz -= rintf(fz);
                    float dx = fx*c0 + fy*c3 + fz*c6;
                    float dy = fx*c1 + fy*c4 + fz*c7;
                    float dz = fx*c2 + fy*c5 + fz*c8;
                    float d2 = dx*dx + dy*dy + dz*dz;
                    insert4(bd2, bj, d2, j);
                }
                warp_merge_top4(bd2, bj, lane, seld2, selj);
            }

            if (lane == 0 && selj[3] < n) {
                float ux[4], uy[4], uz[4], dmax = 0.0f;
                #pragma unroll
                for (int k = 0; k < 4; k++) {
                    int j = selj[k];
                    float dx0 = pix - pos[3*j];
                    float dy0 = piy - pos[3*j+1];
                    float dz0 = piz - pos[3*j+2];
                    float fx = dx0*i0v + dy0*i3v + dz0*i6v;
                    float fy = dx0*i1v + dy0*i4v + dz0*i7v;
                    float fz = dx0*i2v + dy0*i5v + dz0*i8v;
                    fx -= rintf(fx); fy -= rintf(fy); fz -= rintf(fz);
                    float dx = fx*c0 + fy*c3 + fz*c6;
                    float dy = fx*c1 + fy*c4 + fz*c7;
                    float dz = fx*c2 + fy*c5 + fz*c8;
                    float dist = sqrtf(seld2[k]);
                    dmax = fmaxf(dmax, dist);
                    ux[k] = dx / dist; uy[k] = dy / dist; uz[k] = dz / dist;
                }
                float s = 0.0f;
                #pragma unroll
                for (int k = 0; k < 4; k++)
                    #pragma unroll
                    for (int l = k + 1; l < 4; l++) {
                        float cc = ux[k]*ux[l] + uy[k]*uy[l] + uz[k]*uz[l];
                        float tt = cc + (1.0f / 3.0f);
                        s += tt * tt;
                    }
                if (dmax < CUTOFF) { qi = 1.0f - 0.375f * s; vf = 1; }
            }
        }

        __shared__ double s_q[4];
        __shared__ int    s_v[4];
        if (lane == 0) { s_q[wib] = (double)qi; s_v[wib] = vf; }
        __syncthreads();
        if (t == 0) {
            double qs = 0.0; int vs = 0;
            #pragma unroll
            for (int k = 0; k < 4; k++) { qs += s_q[k]; vs += s_v[k]; }
            if (vs > 0) {
                atomicAdd(&g_qsum, qs);
                atomicAdd(&g_vfsum, (double)vs);
            }
        }
    }
}

// ---------------- final: G/T/q_tet (block 0) + S(Q) (all); last block resets --------
__global__ void __launch_bounds__(256)
final_kernel(const float* __restrict__ rbins, const float* __restrict__ qbins,
             float* __restrict__ out, int n, int nbins, int nq) {
    __shared__ float integ[256];
    __shared__ int   sLast;
    int t = threadIdx.x;
    float rho = g_rho, dr = g_dr, mb = g_meanb;
    if (t < nbins) {
        float r     = rbins[t];
        float shell = 4.0f * PI_F * r * r * dr;
        float hv    = (float)g_hist[t] / (mb * mb);
        float G     = hv / ((float)n * rho * shell);
        integ[t] = r * r * (G - 1.0f);
        if (blockIdx.x == 0) {
            out[t]         = G;
            out[nbins + t] = 4.0f * PI_F * rho * r * G;
        }
    }
    if (blockIdx.x == 0 && t == 0) {
        double denom = g_vfsum > 1.0 ? g_vfsum : 1.0;
        out[2 * nbins + nq] = (float)(g_qsum / denom);
    }
    __syncthreads();
    int warp = t >> 5, lane = t & 31;
    int qidx = blockIdx.x * 8 + warp;
    if (qidx < nq) {
        float q = qbins[qidx];
        float s = 0.0f;
        for (int k = lane; k < nbins; k += 32) {
            float qr = q * rbins[k];
            float x  = qr / PI_F;              // mimic jnp.sinc(qr/pi)
            float px = PI_F * x;
            float sc = (px == 0.0f) ? 1.0f : (sinf(px) / px);
            s += integ[k] * sc;
        }
        #pragma unroll
        for (int o = 16; o > 0; o >>= 1) s += __shfl_down_sync(0xffffffffu, s, o);
        if (lane == 0) out[2 * nbins + qidx] = 1.0f + 4.0f * PI_F * rho * dr * s;
    }
    // last-arriving block resets replay-invariant accumulators
    __syncthreads();
    if (t == 0) {
        __threadfence();
        int v = atomicAdd(&g_arriveF, 1);
        sLast = (v == (int)gridDim.x - 1) ? 1 : 0;
    }
    __syncthreads();
    if (sLast) {
        if (t < 256) g_hist[t] = 0.0;
        if (t == 0) { g_qsum = 0.0; g_vfsum = 0.0; g_arriveF = 0; }
    }
}

// ---------------- launch ------------------------------------------------------------
extern "C" void kernel_launch(void* const* d_in, const int* in_sizes, int n_in,
                              void* d_out, int out_size) {
    const float* pos     = (const float*)d_in[0];
    const float* cell    = (const float*)d_in[1];
    const float* rbins   = (const float*)d_in[2];
    const float* qbins   = (const float*)d_in[3];
    const int*   species = (const int*)  d_in[4];
    int n     = in_sizes[0] / 3;
    int nbins = in_sizes[2];
    int nq    = in_sizes[3];

    int ablocks = (n + 127) / 128;
    assign_kernel<<<ablocks, 128>>>(pos, cell, rbins, species, n, nbins);
    scatter_kernel<<<ablocks, 128>>>(n);

    int tilesI = (n + 127) / 128, tilesJ = (n + 511) / 512;
    int pairBlocks = tilesI * tilesJ;
    if (pairBlocks < NCELLS) pairBlocks = NCELLS;
    int qtetBlocks = (n + 3) / 4;
    main_kernel<<<pairBlocks + qtetBlocks, 128>>>(pos, species, n, nbins, pairBlocks);

    final_kernel<<<(nq + 7) / 8, 256>>>(rbins, qbins, (float*)d_out, n, nbins, nq);
}

// round 8
// speedup vs baseline: 4.8980x; 1.1555x over previous
#include <cuda_runtime.h>
#include <math.h>

#define B_SI 4.1491f
#define B_O  5.803f
#define CUTOFF 3.5f
#define PI_F 3.14159274101257324f   // (float)M_PI

#define CDIM   8
#define NCELLS 512                  // CDIM^3
#define NMAX   8192

// ---------------- f32x2 packed helpers (sm_100+) -----------------------------------
#define PK2(out, lo, hi) asm("mov.b64 %0, {%1, %2};" : "=l"(out) : "f"(lo), "f"(hi))
#define UNPK2(lo, hi, in) asm("mov.b64 {%0, %1}, %2;" : "=f"(lo), "=f"(hi) : "l"(in))
#define ADD2(d, a, b) asm("add.rn.f32x2 %0, %1, %2;" : "=l"(d) : "l"(a), "l"(b))
#define MUL2(d, a, b) asm("mul.rn.f32x2 %0, %1, %2;" : "=l"(d) : "l"(a), "l"(b))
#define FMA2(d, a, b, c) asm("fma.rn.f32x2 %0, %1, %2, %3;" : "=l"(d) : "l"(a), "l"(b), "l"(c))

// ---------------- device globals (scratch; no allocations allowed) ----------------
__device__ float  g_inv[9];
__device__ float  g_cellm[9];
__device__ float  g_rho, g_meanb, g_r0, g_dr, g_rsafe;
__device__ int    g_cellok;
__device__ double g_hist[256];        // zero at start; re-zeroed by final_kernel
__device__ double g_qsum, g_vfsum;    // same invariant
__device__ float  g_bsum;             // reset by build's scan phase
__device__ int    g_arriveA, g_arriveF, g_scanDone, g_nSi;

__device__ float4 g_fracA[NMAX];      // per ORIGINAL atom: wrapped frac xyz + b
__device__ float4 g_scart[NMAX];      // cell-sorted cartesian (wrapped) + b
__device__ int    g_sorig[NMAX];
__device__ int    g_siSlot[NMAX];     // sorted slots of Si atoms
__device__ int    g_siCell[NMAX];
__device__ int    g_cellCnt[NCELLS];  // zero at start; re-zeroed in scan phase
__device__ int    g_cellStart[NCELLS + 1];
__device__ int    g_cellFill[NCELLS];

// ---------------- helpers ----------------------------------------------------------
__device__ __forceinline__ void insert4(float bd2[4], int bj[4], float dd, int jj) {
    if (dd < bd2[3]) {
        #pragma unroll
        for (int k = 0; k < 4; k++) {
            if (dd < bd2[k]) {
                float td = bd2[k]; bd2[k] = dd; dd = td;
                int   tj = bj[k];  bj[k]  = jj; jj = tj;
            }
        }
    }
}

__device__ __forceinline__ void warp_merge_top4(float bd2[4], int bj[4], int lane,
                                                float seld2[4], int selj[4]) {
    const float INF = 3.402823466e38f;
    int ptr = 0;
    #pragma unroll
    for (int r = 0; r < 4; r++) {
        float mv = (ptr < 4) ? bd2[ptr] : INF;
        int   mj = (ptr < 4) ? bj[ptr]  : 0x7fffffff;
        int   ml = lane;
        #pragma unroll
        for (int o = 16; o > 0; o >>= 1) {
            float ov = __shfl_down_sync(0xffffffffu, mv, o);
            int   oj = __shfl_down_sync(0xffffffffu, mj, o);
            int   ol = __shfl_down_sync(0xffffffffu, ml, o);
            if (ov < mv || (ov == mv && oj < mj)) { mv = ov; mj = oj; ml = ol; }
        }
        mv = __shfl_sync(0xffffffffu, mv, 0);
        mj = __shfl_sync(0xffffffffu, mj, 0);
        ml = __shfl_sync(0xffffffffu, ml, 0);
        if (lane == ml) ptr++;
        seld2[r] = mv; selj[r] = mj;
    }
}

__device__ __forceinline__ void compute_inv(const float a[9], float iv[9], float* det_out) {
    float c00 = a[4]*a[8] - a[5]*a[7];
    float c01 = a[5]*a[6] - a[3]*a[8];
    float c02 = a[3]*a[7] - a[4]*a[6];
    float det = a[0]*c00 + a[1]*c01 + a[2]*c02;
    float id  = 1.0f / det;
    iv[0] = c00*id;  iv[3] = c01*id;  iv[6] = c02*id;
    iv[1] = (a[2]*a[7] - a[1]*a[8])*id;
    iv[4] = (a[0]*a[8] - a[2]*a[6])*id;
    iv[7] = (a[1]*a[6] - a[0]*a[7])*id;
    iv[2] = (a[1]*a[5] - a[2]*a[4])*id;
    iv[5] = (a[2]*a[3] - a[0]*a[5])*id;
    iv[8] = (a[0]*a[4] - a[1]*a[3])*id;
    *det_out = det;
}

// ---------------- build: assign + (last block) scan + spin-release + scatter --------
__global__ void __launch_bounds__(128)
build_kernel(const float* __restrict__ pos, const float* __restrict__ cell,
             const float* __restrict__ rbins, const int* __restrict__ species,
             int n, int nbins) {
    __shared__ float s_inv[9], s_cell[9];
    __shared__ float sred[128];
    __shared__ int   sLast;

    int t = threadIdx.x;
    if (t == 0) {
        float a[9], iv[9], det;
        #pragma unroll
        for (int k = 0; k < 9; k++) { a[k] = cell[k]; s_cell[k] = a[k]; }
        compute_inv(a, iv, &det);
        #pragma unroll
        for (int k = 0; k < 9; k++) s_inv[k] = iv[k];
    }
    __syncthreads();

    int i = blockIdx.x * 128 + t;
    float b = 0.0f;
    int   c = 0;
    float4 fr = {0.f, 0.f, 0.f, 0.f};
    bool ok = (i < n);
    if (ok) {
        float px = pos[3*i], py = pos[3*i+1], pz = pos[3*i+2];
        float fx = px*s_inv[0] + py*s_inv[3] + pz*s_inv[6];
        float fy = px*s_inv[1] + py*s_inv[4] + pz*s_inv[7];
        float fz = px*s_inv[2] + py*s_inv[5] + pz*s_inv[8];
        fx -= floorf(fx); fy -= floorf(fy); fz -= floorf(fz);
        int cx = min((int)(fx * (float)CDIM), CDIM - 1);
        int cy = min((int)(fy * (float)CDIM), CDIM - 1);
        int cz = min((int)(fz * (float)CDIM), CDIM - 1);
        c = cx | (cy << 3) | (cz << 6);
        b = (species[i] == 0) ? B_SI : B_O;
        fr.x = fx; fr.y = fy; fr.z = fz; fr.w = b;
        g_fracA[i] = fr;
        atomicAdd(&g_cellCnt[c], 1);
    }
    sred[t] = b; __syncthreads();
    for (int o = 64; o > 0; o >>= 1) { if (t < o) sred[t] += sred[t + o]; __syncthreads(); }
    if (t == 0) {
        if (sred[0] != 0.0f) atomicAdd(&g_bsum, sred[0]);
        __threadfence();
        int v = atomicAdd(&g_arriveA, 1);
        sLast = (v == (int)gridDim.x - 1) ? 1 : 0;
    }
    __syncthreads();

    if (sLast) {
        // ---------- scan phase (winner block, 128 threads x 4 cells) ----------
        __shared__ int hs[128];
        int base4 = t * 4;
        int c4[4];
        #pragma unroll
        for (int k = 0; k < 4; k++) c4[k] = g_cellCnt[base4 + k];
        int sum = c4[0] + c4[1] + c4[2] + c4[3];
        hs[t] = sum; __syncthreads();
        for (int off = 1; off < 128; off <<= 1) {
            int v = (t >= off) ? hs[t - off] : 0;
            __syncthreads();
            hs[t] += v;
            __syncthreads();
        }
        int run = hs[t] - sum;
        #pragma unroll
        for (int k = 0; k < 4; k++) {
            g_cellStart[base4 + k] = run;
            g_cellFill[base4 + k]  = run;
            run += c4[k];
            g_cellCnt[base4 + k] = 0;       // re-zero for next replay
        }
        if (t == 127) g_cellStart[NCELLS] = run;
        __syncthreads();
        int mx = max(max(c4[0], c4[1]), max(c4[2], c4[3]));
        hs[t] = mx; __syncthreads();
        for (int o = 64; o > 0; o >>= 1) { if (t < o) hs[t] = max(hs[t], hs[t + o]); __syncthreads(); }

        if (t == 0) {
            float a[9], iv[9], det;
            #pragma unroll
            for (int k = 0; k < 9; k++) { a[k] = cell[k]; g_cellm[k] = a[k]; }
            compute_inv(a, iv, &det);
            #pragma unroll
            for (int k = 0; k < 9; k++) g_inv[k] = iv[k];
            float adet = fabsf(det);
            g_rho = (float)n / adet;
            float r0 = rbins[0], dr = rbins[1] - rbins[0];
            g_r0 = r0; g_dr = dr;
            float c00 = a[4]*a[8]-a[5]*a[7], c10 = a[5]*a[6]-a[3]*a[8], c20 = a[3]*a[7]-a[4]*a[6];
            float n1 = sqrtf(c00*c00 + c10*c10 + c20*c20);
            float x31x = a[7]*a[2]-a[8]*a[1], x31y = a[8]*a[0]-a[6]*a[2], x31z = a[6]*a[1]-a[7]*a[0];
            float n2 = sqrtf(x31x*x31x + x31y*x31y + x31z*x31z);
            float x12x = a[1]*a[5]-a[2]*a[4], x12y = a[2]*a[3]-a[0]*a[5], x12z = a[0]*a[4]-a[1]*a[3];
            float n3 = sqrtf(x12x*x12x + x12y*x12y + x12z*x12z);
            float pmin = fminf(adet/n1, fminf(adet/n2, adet/n3));
            float rmax = r0 + (float)(nbins - 1) * dr;
            g_cellok = (rmax * (float)CDIM * 0.5f <= pmin && hs[0] <= 256) ? 1 : 0;
            g_rsafe  = pmin / (float)CDIM;
            g_meanb  = g_bsum / (float)n;
            g_bsum   = 0.0f;
            g_arriveA = 0;
            __threadfence();
            atomicExch(&g_scanDone, 1);
        }
        __syncthreads();
    } else {
        if (t == 0) {
            while (atomicAdd(&g_scanDone, 0) == 0) { }
        }
        __syncthreads();
        __threadfence();
    }

    // ---------- scatter phase (all blocks) ----------
    if (ok) {
        int s = atomicAdd(&g_cellFill[c], 1);
        float4 cc;
        cc.x = fr.x*s_cell[0] + fr.y*s_cell[3] + fr.z*s_cell[6];
        cc.y = fr.x*s_cell[1] + fr.y*s_cell[4] + fr.z*s_cell[7];
        cc.z = fr.x*s_cell[2] + fr.y*s_cell[5] + fr.z*s_cell[8];
        cc.w = fr.w;
        g_scart[s] = cc;
        g_sorig[s] = i;
        if (fr.w == B_SI) {
            int k = atomicAdd(&g_nSi, 1);
            g_siSlot[k] = s;
            g_siCell[k] = c;
        }
    }
}

// ---------------- main: pair histogram (bx < pairBlocks) + qtet (rest) -------------
__global__ void __launch_bounds__(128)
main_kernel(const float* __restrict__ pos, const int* __restrict__ species,
            int n, int nbins, int pairBlocks) {
    int bx = blockIdx.x;
    int t  = threadIdx.x;

    if (bx < pairBlocks) {
        // ===================== pair histogram =====================
        const int cellok = g_cellok;
        if (cellok && bx >= NCELLS) return;

        __shared__ unsigned long long scx[128], scy[128], scz[128];
        __shared__ float  scw[256];
        __shared__ float4 sjn[512];
        __shared__ float  shist[256];
        __shared__ int    nbS[63];
        __shared__ int    nbCum[64];
        __shared__ float  shx[63], shy[63], shz[63];

        shist[t] = 0.0f; shist[t + 128] = 0.0f;

        const float r0 = g_r0, dr = g_dr;
        const float rmax  = r0 + (float)(nbins - 1) * dr;
        const float d2max = rmax * rmax + 0.01f;
        const float invdr = 1.0f / dr;
        const float binoff = -r0 * invdr;

        if (cellok) {
            int c  = bx;
            int cx = c & 7, cy = (c >> 3) & 7, cz = c >> 6;
            if (t < 63) {
                int tt = 62 + t;                    // t=0 -> self, t>0 -> positive half
                int ox = tt % 5 - 2, oy = (tt / 5) % 5 - 2, oz = tt / 25 - 2;
                int ucx = cx + ox, ucy = cy + oy, ucz = cz + oz;
                int nc = (ucx & 7) | ((ucy & 7) << 3) | ((ucz & 7) << 6);
                int st = g_cellStart[nc];
                nbS[t] = st;
                int myCnt = g_cellStart[nc + 1] - st;
                float wx = (float)((ucx < 0) ? -1 : (ucx >= CDIM ? 1 : 0));
                float wy = (float)((ucy < 0) ? -1 : (ucy >= CDIM ? 1 : 0));
                float wz = (float)((ucz < 0) ? -1 : (ucz >= CDIM ? 1 : 0));
                shx[t] = wx*g_cellm[0] + wy*g_cellm[3] + wz*g_cellm[6];
                shy[t] = wx*g_cellm[1] + wy*g_cellm[4] + wz*g_cellm[7];
                shz[t] = wx*g_cellm[2] + wy*g_cellm[5] + wz*g_cellm[8];
                nbCum[t] = myCnt;       // temp: counts
            }
            __syncthreads();
            if (t == 0) {
                int cum = 0;
                #pragma unroll 1
                for (int k = 0; k < 63; k++) { int v = nbCum[k]; nbCum[k] = cum; cum += v; }
                nbCum[63] = cum;
            }
            __syncthreads();
            int total     = nbCum[63];
            int selfStart = nbS[0];
            int nC        = nbCum[1] - nbCum[0];   // self count
            int nCp       = (nC + 1) >> 1;

            // stage centers as packed SoA (pad odd with far sentinel, weight 0)
            for (int p = t; p < nCp; p += 128) {
                float4 a = g_scart[selfStart + 2*p];
                float4 bb;
                if (2*p + 1 < nC) bb = g_scart[selfStart + 2*p + 1];
                else { bb.x = 1e9f; bb.y = 1e9f; bb.z = 1e9f; bb.w = 0.0f; }
                unsigned long long ux, uy, uz;
                PK2(ux, a.x, bb.x); PK2(uy, a.y, bb.y); PK2(uz, a.z, bb.z);
                scx[p] = ux; scy[p] = uy; scz[p] = uz;
                scw[2*p]     = 2.0f * a.w;
                scw[2*p + 1] = 2.0f * bb.w;
            }
            __syncthreads();

            // ---- self-cell triangle (scalar, tiny) ----
            int npairs = nC * (nC - 1) / 2;
            for (int idx = t; idx < npairs; idx += 128) {
                int gj = (int)((1.0f + sqrtf(1.0f + 8.0f * (float)idx)) * 0.5f);
                while (gj * (gj - 1) / 2 > idx) gj--;
                while ((gj + 1) * gj / 2 <= idx) gj++;
                int ii = idx - gj * (gj - 1) / 2;
                float4 pi = g_scart[selfStart + ii];
                float4 pj = g_scart[selfStart + gj];
                float dx = pi.x - pj.x, dy = pi.y - pj.y, dz = pi.z - pj.z;
                float d2 = dx*dx + dy*dy + dz*dz;
                if (d2 < d2max) {
                    float dist;
                    asm("sqrt.approx.f32 %0, %1;" : "=f"(dist) : "f"(d2));
                    float x  = fmaf(dist, invdr, binoff);
                    int   b0 = __float2int_rd(x);
                    if ((unsigned)b0 < (unsigned)(nbins - 1)) {
                        float f = x - (float)b0;
                        float w = 2.0f * pi.w * pj.w;
                        atomicAdd(&shist[b0],     w * (1.0f - f));
                        atomicAdd(&shist[b0 + 1], w * f);
                    }
                }
            }

            // ---- main loop: centers (packed) vs 62 half-neighborhood cells ----
            for (int base = nC; base < total; base += 512) {
                int lim = min(512, total - base);
                // stage chunk of neighborhood NEGATED with wrap shifts applied
                for (int k = t; k < lim; k += 128) {
                    int gj = base + k;
                    int lo = 0;
                    if (nbCum[lo + 32] <= gj) lo += 32;
                    if (nbCum[lo + 16] <= gj) lo += 16;
                    if (nbCum[lo +  8] <= gj) lo +=  8;
                    if (nbCum[lo +  4] <= gj) lo +=  4;
                    if (nbCum[lo +  2] <= gj) lo +=  2;
                    if (nbCum[lo +  1] <= gj) lo +=  1;
                    float4 p = g_scart[nbS[lo] + (gj - nbCum[lo])];
                    float4 q;
                    q.x = -(p.x + shx[lo]);
                    q.y = -(p.y + shy[lo]);
                    q.z = -(p.z + shz[lo]);
                    q.w = p.w;
                    sjn[k] = q;
                }
                __syncthreads();
                for (int k = t; k < lim; k += 128) {
                    float4 pj = sjn[k];
                    unsigned long long px2, py2, pz2;
                    PK2(px2, pj.x, pj.x);
                    PK2(py2, pj.y, pj.y);
                    PK2(pz2, pj.z, pj.z);
                    float pjw = pj.w;
                    for (int p = 0; p < nCp; p++) {
                        unsigned long long dx2, dy2, dz2, d2p;
                        ADD2(dx2, scx[p], px2);      // cen + (-pj) = cen - pj
                        ADD2(dy2, scy[p], py2);
                        ADD2(dz2, scz[p], pz2);
                        MUL2(d2p, dz2, dz2);
                        FMA2(d2p, dy2, dy2, d2p);
                        FMA2(d2p, dx2, dx2, d2p);
                        float d2lo, d2hi;
                        UNPK2(d2lo, d2hi, d2p);
                        if (d2lo < d2max) {
                            float dist;
                            asm("sqrt.approx.f32 %0, %1;" : "=f"(dist) : "f"(d2lo));
                            float x  = fmaf(dist, invdr, binoff);
                            int   b0 = __float2int_rd(x);
                            if ((unsigned)b0 < (unsigned)(nbins - 1)) {
                                float f = x - (float)b0;
                                float w = scw[2*p] * pjw;
                                atomicAdd(&shist[b0],     w * (1.0f - f));
                                atomicAdd(&shist[b0 + 1], w * f);
                            }
                        }
                        if (d2hi < d2max) {
                            float dist;
                            asm("sqrt.approx.f32 %0, %1;" : "=f"(dist) : "f"(d2hi));
                            float x  = fmaf(dist, invdr, binoff);
                            int   b0 = __float2int_rd(x);
                            if ((unsigned)b0 < (unsigned)(nbins - 1)) {
                                float f = x - (float)b0;
                                float w = scw[2*p + 1] * pjw;
                                atomicAdd(&shist[b0],     w * (1.0f - f));
                                atomicAdd(&shist[b0 + 1], w * f);
                            }
                        }
                    }
                }
                __syncthreads();
            }
        } else {
            // ---- brute fallback (general cells / degenerate) ----
            int tilesJ = (n + 511) >> 9;
            int ib = bx / tilesJ;
            int jb = bx % tilesJ;
            int iBase = ib * 128, jBase = jb * 512;
            const float c0 = g_cellm[0], c1 = g_cellm[1], c2 = g_cellm[2];
            const float c3 = g_cellm[3], c4 = g_cellm[4], c5 = g_cellm[5];
            const float c6 = g_cellm[6], c7 = g_cellm[7], c8 = g_cellm[8];
            if (iBase < n && jBase + 511 > iBase) {
                for (int k = t; k < 512; k += 128) {
                    int j = jBase + k;
                    float4 v;
                    if (j < n) v = g_fracA[j];
                    else { v.x = 1e18f; v.y = 1e18f; v.z = 1e18f; v.w = 0.0f; }
                    sjn[k] = v;
                }
                __syncthreads();
                int i = iBase + t;
                if (i < n) {
                    float4 pi = g_fracA[i];
                    int kmin = i - jBase + 1; if (kmin < 0) kmin = 0;
                    int kmax = n - jBase; if (kmax > 512) kmax = 512;
                    for (int k = kmin; k < kmax; k++) {
                        float4 pj = sjn[k];
                        float fx = pi.x - pj.x; fx -= rintf(fx);
                        float fy = pi.y - pj.y; fy -= rintf(fy);
                        float fz = pi.z - pj.z; fz -= rintf(fz);
                        float dx = fx*c0 + fy*c3 + fz*c6;
                        float dy = fx*c1 + fy*c4 + fz*c7;
                        float dz = fx*c2 + fy*c5 + fz*c8;
                        float d2 = dx*dx + dy*dy + dz*dz;
                        if (d2 < d2max) {
                            float dist = sqrtf(d2);
                            float x  = fmaf(dist, invdr, binoff);
                            int   b0 = __float2int_rd(x);
                            if ((unsigned)b0 < (unsigned)(nbins - 1)) {
                                float f = x - (float)b0;
                                float w = 2.0f * pi.w * pj.w;
                                atomicAdd(&shist[b0],     w * (1.0f - f));
                                atomicAdd(&shist[b0 + 1], w * f);
                            }
                        }
                    }
                }
                __syncthreads();
            }
        }
        __syncthreads();
        for (int k = t; k < nbins; k += 128)
            if (shist[k] != 0.0f) atomicAdd(&g_hist[k], (double)shist[k]);
    } else {
        // ===================== tetrahedral order parameter =====================
        int qb   = bx - pairBlocks;
        int gw   = qb * 4 + (t >> 5);       // Si-list index
        int lane = t & 31;
        int wib  = t >> 5;
        int nSi  = g_nSi;

        const float i0v = g_inv[0], i1v = g_inv[1], i2v = g_inv[2];
        const float i3v = g_inv[3], i4v = g_inv[4], i5v = g_inv[5];
        const float i6v = g_inv[6], i7v = g_inv[7], i8v = g_inv[8];
        const float c0 = g_cellm[0], c1 = g_cellm[1], c2 = g_cellm[2];
        const float c3 = g_cellm[3], c4 = g_cellm[4], c5 = g_cellm[5];
        const float c6 = g_cellm[6], c7 = g_cellm[7], c8 = g_cellm[8];
        const float rsafe  = g_rsafe;
        const int   cellok = g_cellok;
        const float INF = 3.402823466e38f;

        float qi = 0.0f;
        int   vf = 0;

        if (gw < nSi) {
            int slot = g_siSlot[gw];
            int i    = g_sorig[slot];
            float4 ci = g_scart[slot];
            float pix = pos[3*i], piy = pos[3*i+1], piz = pos[3*i+2];
            float seld2[4]; int selj[4];
            bool valid = false;

            if (cellok) {
                int c  = g_siCell[gw];
                int cx = c & 7, cy = (c >> 3) & 7, cz = c >> 6;
                float bd2[4] = {INF, INF, INF, INF};
                int   bj [4] = {0x7fffffff, 0x7fffffff, 0x7fffffff, 0x7fffffff};
                int found = 0;
                if (lane < 27) {
                    int ox = lane % 3 - 1, oy = (lane / 3) % 3 - 1, oz = lane / 9 - 1;
                    int ucx = cx + ox, ucy = cy + oy, ucz = cz + oz;
                    int nc = (ucx & 7) | ((ucy & 7) << 3) | ((ucz & 7) << 6);
                    float wx = (float)((ucx < 0) ? -1 : (ucx >= CDIM ? 1 : 0));
                    float wy = (float)((ucy < 0) ? -1 : (ucy >= CDIM ? 1 : 0));
                    float wz = (float)((ucz < 0) ? -1 : (ucz >= CDIM ? 1 : 0));
                    float sx = wx*c0 + wy*c3 + wz*c6;
                    float sy = wx*c1 + wy*c4 + wz*c7;
                    float sz = wx*c2 + wy*c5 + wz*c8;
                    int st = g_cellStart[nc], en = g_cellStart[nc + 1];
                    for (int s = st; s < en; s++) {
                        float4 fj = g_scart[s];
                        if (fj.w == B_SI || s == slot) continue;
                        float dx = ci.x - (fj.x + sx);
                        float dy = ci.y - (fj.y + sy);
                        float dz = ci.z - (fj.z + sz);
                        float d2 = dx*dx + dy*dy + dz*dz;
                        found++;
                        insert4(bd2, bj, d2, g_sorig[s]);
                    }
                }
                int foundTot = __reduce_add_sync(0xffffffffu, found);
                warp_merge_top4(bd2, bj, lane, seld2, selj);
                valid = (foundTot >= 4) && (seld2[3] < rsafe * rsafe);
            }

            if (!valid) {
                // exact full-scan fallback
                float bd2[4] = {INF, INF, INF, INF};
                int   bj [4] = {0x7fffffff, 0x7fffffff, 0x7fffffff, 0x7fffffff};
                for (int j = lane; j < n; j += 32) {
                    if (j == i || species[j] == 0) continue;
                    float dx0 = pix - pos[3*j];
                    float dy0 = piy - pos[3*j+1];
                    float dz0 = piz - pos[3*j+2];
                    float fx = dx0*i0v + dy0*i3v + dz0*i6v;
                    float fy = dx0*i1v + dy0*i4v + dz0*i7v;
                    float fz = dx0*i2v + dy0*i5v + dz0*i8v;
                    fx -= rintf(fx); fy -= rintf(fy); fz -= rintf(fz);
                    float dx = fx*c0 + fy*c3 + fz*c6;
                    float dy = fx*c1 + fy*c4 + fz*c7;
                    float dz = fx*c2 + fy*c5 + fz*c8;
                    float d2 = dx*dx + dy*dy + dz*dz;
                    insert4(bd2, bj, d2, j);
                }
                warp_merge_top4(bd2, bj, lane, seld2, selj);
            }

            if (lane == 0 && selj[3] < n) {
                float ux[4], uy[4], uz[4], dmax = 0.0f;
                #pragma unroll
                for (int k = 0; k < 4; k++) {
                    int j = selj[k];
                    float dx0 = pix - pos[3*j];
                    float dy0 = piy - pos[3*j+1];
                    float dz0 = piz - pos[3*j+2];
                    float fx = dx0*i0v + dy0*i3v + dz0*i6v;
                    float fy = dx0*i1v + dy0*i4v + dz0*i7v;
                    float fz = dx0*i2v + dy0*i5v + dz0*i8v;
                    fx -= rintf(fx); fy -= rintf(fy); fz -= rintf(fz);
                    float dx = fx*c0 + fy*c3 + fz*c6;
                    float dy = fx*c1 + fy*c4 + fz*c7;
                    float dz = fx*c2 + fy*c5 + fz*c8;
                    float dist = sqrtf(seld2[k]);
                    dmax = fmaxf(dmax, dist);
                    ux[k] = dx / dist; uy[k] = dy / dist; uz[k] = dz / dist;
                }
                float s = 0.0f;
                #pragma unroll
                for (int k = 0; k < 4; k++)
                    #pragma unroll
                    for (int l = k + 1; l < 4; l++) {
                        float cc = ux[k]*ux[l] + uy[k]*uy[l] + uz[k]*uz[l];
                        float tt = cc + (1.0f / 3.0f);
                        s += tt * tt;
                    }
                if (dmax < CUTOFF) { qi = 1.0f - 0.375f * s; vf = 1; }
            }
        }

        __shared__ double s_q[4];
        __shared__ int    s_v[4];
        if (lane == 0) { s_q[wib] = (double)qi; s_v[wib] = vf; }
        __syncthreads();
        if (t == 0) {
            double qs = 0.0; int vs = 0;
            #pragma unroll
            for (int k = 0; k < 4; k++) { qs += s_q[k]; vs += s_v[k]; }
            if (vs > 0) {
                atomicAdd(&g_qsum, qs);
                atomicAdd(&g_vfsum, (double)vs);
            }
        }
    }
}

// ---------------- final: G/T/q_tet (block 0) + S(Q) (all); last block resets --------
__global__ void __launch_bounds__(256)
final_kernel(const float* __restrict__ rbins, const float* __restrict__ qbins,
             float* __restrict__ out, int n, int nbins, int nq) {
    __shared__ float integ[256];
    __shared__ int   sLast;
    int t = threadIdx.x;
    float rho = g_rho, dr = g_dr, mb = g_meanb;
    if (t < nbins) {
        float r     = rbins[t];
        float shell = 4.0f * PI_F * r * r * dr;
        float hv    = (float)g_hist[t] / (mb * mb);
        float G     = hv / ((float)n * rho * shell);
        integ[t] = r * r * (G - 1.0f);
        if (blockIdx.x == 0) {
            out[t]         = G;
            out[nbins + t] = 4.0f * PI_F * rho * r * G;
        }
    }
    if (blockIdx.x == 0 && t == 0) {
        double denom = g_vfsum > 1.0 ? g_vfsum : 1.0;
        out[2 * nbins + nq] = (float)(g_qsum / denom);
    }
    __syncthreads();
    int warp = t >> 5, lane = t & 31;
    int qidx = blockIdx.x * 8 + warp;
    if (qidx < nq) {
        float q = qbins[qidx];
        float s = 0.0f;
        for (int k = lane; k < nbins; k += 32) {
            float px = q * rbins[k];               // sinc(qr/pi) = sin(qr)/(qr)
            float sc = (px == 0.0f) ? 1.0f : (__sinf(px) / px);
            s += integ[k] * sc;
        }
        #pragma unroll
        for (int o = 16; o > 0; o >>= 1) s += __shfl_down_sync(0xffffffffu, s, o);
        if (lane == 0) out[2 * nbins + qidx] = 1.0f + 4.0f * PI_F * rho * dr * s;
    }
    // last-arriving block resets replay-invariant accumulators
    __syncthreads();
    if (t == 0) {
        __threadfence();
        int v = atomicAdd(&g_arriveF, 1);
        sLast = (v == (int)gridDim.x - 1) ? 1 : 0;
    }
    __syncthreads();
    if (sLast) {
        if (t < 256) g_hist[t] = 0.0;
        if (t == 0) {
            g_qsum = 0.0; g_vfsum = 0.0;
            g_arriveF = 0; g_nSi = 0; g_scanDone = 0;
        }
    }
}

// ---------------- launch ------------------------------------------------------------
extern "C" void kernel_launch(void* const* d_in, const int* in_sizes, int n_in,
                              void* d_out, int out_size) {
    const float* pos     = (const float*)d_in[0];
    const float* cell    = (const float*)d_in[1];
    const float* rbins   = (const float*)d_in[2];
    const float* qbins   = (const float*)d_in[3];
    const int*   species = (const int*)  d_in[4];
    int n     = in_sizes[0] / 3;
    int nbins = in_sizes[2];
    int nq    = in_sizes[3];

    int ablocks = (n + 127) / 128;      // 32 blocks for n=4096: all resident, spin-safe
    build_kernel<<<ablocks, 128>>>(pos, cell, rbins, species, n, nbins);

    int tilesI = (n + 127) / 128, tilesJ = (n + 511) / 512;
    int pairBlocks = tilesI * tilesJ;
    if (pairBlocks < NCELLS) pairBlocks = NCELLS;
    int qtetBlocks = (n + 3) / 4;       // worst case all Si; extra warps exit on g_nSi
    main_kernel<<<pairBlocks + qtetBlocks, 128>>>(pos, species, n, nbins, pairBlocks);

    final_kernel<<<(nq + 7) / 8, 256>>>(rbins, qbins, (float*)d_out, n, nbins, nq);
}

// round 9
// speedup vs baseline: 5.5433x; 1.1317x over previous
#include <cuda_runtime.h>
#include <math.h>

#define B_SI 4.1491f
#define B_O  5.803f
#define CUTOFF 3.5f
#define PI_F 3.14159274101257324f   // (float)M_PI

#define CDIM   8
#define NCELLS 512                  // CDIM^3
#define NMAX   8192

// ---------------- f32x2 packed helpers (sm_100+) -----------------------------------
#define PK2(out, lo, hi) asm("mov.b64 %0, {%1, %2};" : "=l"(out) : "f"(lo), "f"(hi))
#define UNPK2(lo, hi, in) asm("mov.b64 {%0, %1}, %2;" : "=f"(lo), "=f"(hi) : "l"(in))
#define ADD2(d, a, b) asm("add.rn.f32x2 %0, %1, %2;" : "=l"(d) : "l"(a), "l"(b))
#define MUL2(d, a, b) asm("mul.rn.f32x2 %0, %1, %2;" : "=l"(d) : "l"(a), "l"(b))
#define FMA2(d, a, b, c) asm("fma.rn.f32x2 %0, %1, %2, %3;" : "=l"(d) : "l"(a), "l"(b), "l"(c))

// ---------------- device globals (scratch; no allocations allowed) ----------------
__device__ float  g_inv[9];
__device__ float  g_cellm[9];
__device__ float  g_rho, g_meanb, g_r0, g_dr, g_rsafe;
__device__ int    g_cellok;
__device__ double g_hist[256];        // zero at start; re-zeroed by final_kernel
__device__ double g_qsum, g_vfsum;    // same invariant
__device__ float  g_bsum;             // reset by assign's scan phase
__device__ int    g_arriveA, g_arriveF, g_nSi;

__device__ float4 g_fracA[NMAX];      // per ORIGINAL atom: wrapped frac xyz + b
__device__ int    g_cellOf[NMAX];
__device__ float4 g_scart[NMAX];      // cell-sorted cartesian (wrapped) + b
__device__ int    g_sorig[NMAX];
__device__ int    g_siSlot[NMAX];     // sorted slots of Si atoms
__device__ int    g_siCell[NMAX];
__device__ int    g_cellCnt[NCELLS];  // zero at start; re-zeroed in scan phase
__device__ int    g_cellStart[NCELLS + 1];
__device__ int    g_cellFill[NCELLS];

// ---------------- helpers ----------------------------------------------------------
__device__ __forceinline__ void insert4(float bd2[4], int bj[4], float dd, int jj) {
    if (dd < bd2[3]) {
        #pragma unroll
        for (int k = 0; k < 4; k++) {
            if (dd < bd2[k]) {
                float td = bd2[k]; bd2[k] = dd; dd = td;
                int   tj = bj[k];  bj[k]  = jj; jj = tj;
            }
        }
    }
}

__device__ __forceinline__ void warp_merge_top4(float bd2[4], int bj[4], int lane,
                                                float seld2[4], int selj[4]) {
    const float INF = 3.402823466e38f;
    int ptr = 0;
    #pragma unroll
    for (int r = 0; r < 4; r++) {
        float mv = (ptr < 4) ? bd2[ptr] : INF;
        int   mj = (ptr < 4) ? bj[ptr]  : 0x7fffffff;
        int   ml = lane;
        #pragma unroll
        for (int o = 16; o > 0; o >>= 1) {
            float ov = __shfl_down_sync(0xffffffffu, mv, o);
            int   oj = __shfl_down_sync(0xffffffffu, mj, o);
            int   ol = __shfl_down_sync(0xffffffffu, ml, o);
            if (ov < mv || (ov == mv && oj < mj)) { mv = ov; mj = oj; ml = ol; }
        }
        mv = __shfl_sync(0xffffffffu, mv, 0);
        mj = __shfl_sync(0xffffffffu, mj, 0);
        ml = __shfl_sync(0xffffffffu, ml, 0);
        if (lane == ml) ptr++;
        seld2[r] = mv; selj[r] = mj;
    }
}

__device__ __forceinline__ void compute_inv(const float a[9], float iv[9], float* det_out) {
    float c00 = a[4]*a[8] - a[5]*a[7];
    float c01 = a[5]*a[6] - a[3]*a[8];
    float c02 = a[3]*a[7] - a[4]*a[6];
    float det = a[0]*c00 + a[1]*c01 + a[2]*c02;
    float id  = 1.0f / det;
    iv[0] = c00*id;  iv[3] = c01*id;  iv[6] = c02*id;
    iv[1] = (a[2]*a[7] - a[1]*a[8])*id;
    iv[4] = (a[0]*a[8] - a[2]*a[6])*id;
    iv[7] = (a[1]*a[6] - a[0]*a[7])*id;
    iv[2] = (a[1]*a[5] - a[2]*a[4])*id;
    iv[5] = (a[2]*a[3] - a[0]*a[5])*id;
    iv[8] = (a[0]*a[4] - a[1]*a[3])*id;
    *det_out = det;
}

// ---------------- assign: frac coords + cell counts; last block scans ---------------
__global__ void __launch_bounds__(128)
assign_kernel(const float* __restrict__ pos, const float* __restrict__ cell,
              const float* __restrict__ rbins, const int* __restrict__ species,
              int n, int nbins) {
    __shared__ float s_inv[9];
    __shared__ float sred[128];
    __shared__ int   sLast;

    int t = threadIdx.x;
    if (t == 0) {
        float a[9], iv[9], det;
        #pragma unroll
        for (int k = 0; k < 9; k++) a[k] = cell[k];
        compute_inv(a, iv, &det);
        #pragma unroll
        for (int k = 0; k < 9; k++) s_inv[k] = iv[k];
    }
    __syncthreads();

    int i = blockIdx.x * 128 + t;
    float b = 0.0f;
    if (i < n) {
        float px = pos[3*i], py = pos[3*i+1], pz = pos[3*i+2];
        float fx = px*s_inv[0] + py*s_inv[3] + pz*s_inv[6];
        float fy = px*s_inv[1] + py*s_inv[4] + pz*s_inv[7];
        float fz = px*s_inv[2] + py*s_inv[5] + pz*s_inv[8];
        fx -= floorf(fx); fy -= floorf(fy); fz -= floorf(fz);
        int cx = min((int)(fx * (float)CDIM), CDIM - 1);
        int cy = min((int)(fy * (float)CDIM), CDIM - 1);
        int cz = min((int)(fz * (float)CDIM), CDIM - 1);
        int c  = cx | (cy << 3) | (cz << 6);
        b = (species[i] == 0) ? B_SI : B_O;
        float4 fr; fr.x = fx; fr.y = fy; fr.z = fz; fr.w = b;
        g_fracA[i]  = fr;
        g_cellOf[i] = c;
        atomicAdd(&g_cellCnt[c], 1);
    }
    sred[t] = b; __syncthreads();
    for (int o = 64; o > 0; o >>= 1) { if (t < o) sred[t] += sred[t + o]; __syncthreads(); }
    if (t == 0) {
        if (sred[0] != 0.0f) atomicAdd(&g_bsum, sred[0]);
        __threadfence();
        int v = atomicAdd(&g_arriveA, 1);
        sLast = (v == (int)gridDim.x - 1) ? 1 : 0;
    }
    __syncthreads();
    if (!sLast) return;

    // ---------- scan phase (winner block, 128 threads x 4 cells) ----------
    __shared__ int hs[128];
    int base4 = t * 4;
    int c4[4];
    #pragma unroll
    for (int k = 0; k < 4; k++) c4[k] = g_cellCnt[base4 + k];
    int sum = c4[0] + c4[1] + c4[2] + c4[3];
    hs[t] = sum; __syncthreads();
    for (int off = 1; off < 128; off <<= 1) {
        int v = (t >= off) ? hs[t - off] : 0;
        __syncthreads();
        hs[t] += v;
        __syncthreads();
    }
    int run = hs[t] - sum;
    #pragma unroll
    for (int k = 0; k < 4; k++) {
        g_cellStart[base4 + k] = run;
        g_cellFill[base4 + k]  = run;
        run += c4[k];
        g_cellCnt[base4 + k] = 0;           // re-zero for next replay
    }
    if (t == 127) g_cellStart[NCELLS] = run;
    __syncthreads();
    int mx = max(max(c4[0], c4[1]), max(c4[2], c4[3]));
    hs[t] = mx; __syncthreads();
    for (int o = 64; o > 0; o >>= 1) { if (t < o) hs[t] = max(hs[t], hs[t + o]); __syncthreads(); }

    if (t == 0) {
        float a[9], iv[9], det;
        #pragma unroll
        for (int k = 0; k < 9; k++) { a[k] = cell[k]; g_cellm[k] = a[k]; }
        compute_inv(a, iv, &det);
        #pragma unroll
        for (int k = 0; k < 9; k++) g_inv[k] = iv[k];
        float adet = fabsf(det);
        g_rho = (float)n / adet;
        float r0 = rbins[0], dr = rbins[1] - rbins[0];
        g_r0 = r0; g_dr = dr;
        float c00 = a[4]*a[8]-a[5]*a[7], c10 = a[5]*a[6]-a[3]*a[8], c20 = a[3]*a[7]-a[4]*a[6];
        float n1 = sqrtf(c00*c00 + c10*c10 + c20*c20);
        float x31x = a[7]*a[2]-a[8]*a[1], x31y = a[8]*a[0]-a[6]*a[2], x31z = a[6]*a[1]-a[7]*a[0];
        float n2 = sqrtf(x31x*x31x + x31y*x31y + x31z*x31z);
        float x12x = a[1]*a[5]-a[2]*a[4], x12y = a[2]*a[3]-a[0]*a[5], x12z = a[0]*a[4]-a[1]*a[3];
        float n3 = sqrtf(x12x*x12x + x12y*x12y + x12z*x12z);
        float pmin = fminf(adet/n1, fminf(adet/n2, adet/n3));
        float rmax = r0 + (float)(nbins - 1) * dr;
        g_cellok = (rmax * (float)CDIM * 0.5f <= pmin && hs[0] <= 256) ? 1 : 0;
        g_rsafe  = pmin / (float)CDIM;
        g_meanb  = g_bsum / (float)n;
        g_bsum   = 0.0f;
        g_arriveA = 0;
    }
}

// ---------------- scatter into cell-sorted order + Si list --------------------------
__global__ void __launch_bounds__(128)
scatter_kernel(int n) {
    __shared__ float s_cell[9];
    int t = threadIdx.x;
    if (t == 0) {
        #pragma unroll
        for (int k = 0; k < 9; k++) s_cell[k] = g_cellm[k];
    }
    __syncthreads();
    int i = blockIdx.x * 128 + t;
    if (i >= n) return;
    int c = g_cellOf[i];
    int s = atomicAdd(&g_cellFill[c], 1);
    float4 fr = g_fracA[i];
    float4 cc;
    cc.x = fr.x*s_cell[0] + fr.y*s_cell[3] + fr.z*s_cell[6];
    cc.y = fr.x*s_cell[1] + fr.y*s_cell[4] + fr.z*s_cell[7];
    cc.z = fr.x*s_cell[2] + fr.y*s_cell[5] + fr.z*s_cell[8];
    cc.w = fr.w;
    g_scart[s] = cc;
    g_sorig[s] = i;
    if (fr.w == B_SI) {
        int k = atomicAdd(&g_nSi, 1);
        g_siSlot[k] = s;
        g_siCell[k] = c;
    }
}

// ---------------- main: pair histogram (bx < pairBlocks) + qtet (rest) -------------
__global__ void __launch_bounds__(256)
main_kernel(const float* __restrict__ pos, const int* __restrict__ species,
            int n, int nbins, int pairBlocks) {
    int bx = blockIdx.x;
    int t  = threadIdx.x;

    if (bx < pairBlocks) {
        // ===================== pair histogram =====================
        const int cellok = g_cellok;
        if (cellok && bx >= NCELLS) return;

        __shared__ unsigned long long scx[128], scy[128], scz[128];
        __shared__ float  scw[256];
        __shared__ float4 sjn[512];
        __shared__ float  shist[256];
        __shared__ int    nbS[63];
        __shared__ int    nbCum[64];
        __shared__ float  shx[63], shy[63], shz[63];

        shist[t] = 0.0f;

        const float r0 = g_r0, dr = g_dr;
        const float rmax  = r0 + (float)(nbins - 1) * dr;
        const float d2max = rmax * rmax + 0.01f;
        const float invdr = 1.0f / dr;
        const float binoff = -r0 * invdr;

        if (cellok) {
            int c  = bx;
            int cx = c & 7, cy = (c >> 3) & 7, cz = c >> 6;
            if (t < 63) {
                int tt = 62 + t;                    // t=0 -> self, t>0 -> positive half
                int ox = tt % 5 - 2, oy = (tt / 5) % 5 - 2, oz = tt / 25 - 2;
                int ucx = cx + ox, ucy = cy + oy, ucz = cz + oz;
                int nc = (ucx & 7) | ((ucy & 7) << 3) | ((ucz & 7) << 6);
                int st = g_cellStart[nc];
                nbS[t] = st;
                int myCnt = g_cellStart[nc + 1] - st;
                float wx = (float)((ucx < 0) ? -1 : (ucx >= CDIM ? 1 : 0));
                float wy = (float)((ucy < 0) ? -1 : (ucy >= CDIM ? 1 : 0));
                float wz = (float)((ucz < 0) ? -1 : (ucz >= CDIM ? 1 : 0));
                shx[t] = wx*g_cellm[0] + wy*g_cellm[3] + wz*g_cellm[6];
                shy[t] = wx*g_cellm[1] + wy*g_cellm[4] + wz*g_cellm[7];
                shz[t] = wx*g_cellm[2] + wy*g_cellm[5] + wz*g_cellm[8];
                nbCum[t] = myCnt;       // temp: counts
            }
            __syncthreads();
            if (t == 0) {
                int cum = 0;
                #pragma unroll 1
                for (int k = 0; k < 63; k++) { int v = nbCum[k]; nbCum[k] = cum; cum += v; }
                nbCum[63] = cum;
            }
            __syncthreads();
            int total     = nbCum[63];
            int selfStart = nbS[0];
            int nC        = nbCum[1] - nbCum[0];   // self count
            int nCp       = (nC + 1) >> 1;

            // stage centers as packed SoA (pad odd with far sentinel, weight 0)
            for (int p = t; p < nCp; p += 256) {
                float4 a = g_scart[selfStart + 2*p];
                float4 bb;
                if (2*p + 1 < nC) bb = g_scart[selfStart + 2*p + 1];
                else { bb.x = 1e9f; bb.y = 1e9f; bb.z = 1e9f; bb.w = 0.0f; }
                unsigned long long ux, uy, uz;
                PK2(ux, a.x, bb.x); PK2(uy, a.y, bb.y); PK2(uz, a.z, bb.z);
                scx[p] = ux; scy[p] = uy; scz[p] = uz;
                scw[2*p]     = 2.0f * a.w;
                scw[2*p + 1] = 2.0f * bb.w;
            }
            __syncthreads();

            // ---- self-cell triangle (scalar, tiny) ----
            int npairs = nC * (nC - 1) / 2;
            for (int idx = t; idx < npairs; idx += 256) {
                int gj = (int)((1.0f + sqrtf(1.0f + 8.0f * (float)idx)) * 0.5f);
                while (gj * (gj - 1) / 2 > idx) gj--;
                while ((gj + 1) * gj / 2 <= idx) gj++;
                int ii = idx - gj * (gj - 1) / 2;
                float4 pi = g_scart[selfStart + ii];
                float4 pj = g_scart[selfStart + gj];
                float dx = pi.x - pj.x, dy = pi.y - pj.y, dz = pi.z - pj.z;
                float d2 = dx*dx + dy*dy + dz*dz;
                if (d2 < d2max) {
                    float dist;
                    asm("sqrt.approx.f32 %0, %1;" : "=f"(dist) : "f"(d2));
                    float x  = fmaf(dist, invdr, binoff);
                    int   b0 = __float2int_rd(x);
                    if ((unsigned)b0 < (unsigned)(nbins - 1)) {
                        float f = x - (float)b0;
                        float w = 2.0f * pi.w * pj.w;
                        atomicAdd(&shist[b0],     w * (1.0f - f));
                        atomicAdd(&shist[b0 + 1], w * f);
                    }
                }
            }

            // ---- main loop: centers (packed) vs 62 half-neighborhood cells ----
            for (int base = nC; base < total; base += 512) {
                int lim = min(512, total - base);
                // stage chunk of neighborhood NEGATED with wrap shifts applied
                for (int k = t; k < lim; k += 256) {
                    int gj = base + k;
                    int lo = 0;
                    if (nbCum[lo + 32] <= gj) lo += 32;
                    if (nbCum[lo + 16] <= gj) lo += 16;
                    if (nbCum[lo +  8] <= gj) lo +=  8;
                    if (nbCum[lo +  4] <= gj) lo +=  4;
                    if (nbCum[lo +  2] <= gj) lo +=  2;
                    if (nbCum[lo +  1] <= gj) lo +=  1;
                    float4 p = g_scart[nbS[lo] + (gj - nbCum[lo])];
                    float4 q;
                    q.x = -(p.x + shx[lo]);
                    q.y = -(p.y + shy[lo]);
                    q.z = -(p.z + shz[lo]);
                    q.w = p.w;
                    sjn[k] = q;
                }
                __syncthreads();
                for (int k = t; k < lim; k += 256) {
                    float4 pj = sjn[k];
                    unsigned long long px2, py2, pz2;
                    PK2(px2, pj.x, pj.x);
                    PK2(py2, pj.y, pj.y);
                    PK2(pz2, pj.z, pj.z);
                    float pjw = pj.w;
                    #pragma unroll 2
                    for (int p = 0; p < nCp; p++) {
                        unsigned long long dx2, dy2, dz2, d2p;
                        ADD2(dx2, scx[p], px2);      // cen + (-pj) = cen - pj
                        ADD2(dy2, scy[p], py2);
                        ADD2(dz2, scz[p], pz2);
                        MUL2(d2p, dz2, dz2);
                        FMA2(d2p, dy2, dy2, d2p);
                        FMA2(d2p, dx2, dx2, d2p);
                        float d2lo, d2hi;
                        UNPK2(d2lo, d2hi, d2p);
                        if (d2lo < d2max) {
                            float dist;
                            asm("sqrt.approx.f32 %0, %1;" : "=f"(dist) : "f"(d2lo));
                            float x  = fmaf(dist, invdr, binoff);
                            int   b0 = __float2int_rd(x);
                            if ((unsigned)b0 < (unsigned)(nbins - 1)) {
                                float f = x - (float)b0;
                                float w = scw[2*p] * pjw;
                                atomicAdd(&shist[b0],     w * (1.0f - f));
                                atomicAdd(&shist[b0 + 1], w * f);
                            }
                        }
                        if (d2hi < d2max) {
                            float dist;
                            asm("sqrt.approx.f32 %0, %1;" : "=f"(dist) : "f"(d2hi));
                            float x  = fmaf(dist, invdr, binoff);
                            int   b0 = __float2int_rd(x);
                            if ((unsigned)b0 < (unsigned)(nbins - 1)) {
                                float f = x - (float)b0;
                                float w = scw[2*p + 1] * pjw;
                                atomicAdd(&shist[b0],     w * (1.0f - f));
                                atomicAdd(&shist[b0 + 1], w * f);
                            }
                        }
                    }
                }
                __syncthreads();
            }
        } else {
            // ---- brute fallback (general cells / degenerate) ----
            int tilesJ = (n + 511) >> 9;
            int ib = bx / tilesJ;
            int jb = bx % tilesJ;
            int iBase = ib * 256, jBase = jb * 512;
            const float c0 = g_cellm[0], c1 = g_cellm[1], c2 = g_cellm[2];
            const float c3 = g_cellm[3], c4 = g_cellm[4], c5 = g_cellm[5];
            const float c6 = g_cellm[6], c7 = g_cellm[7], c8 = g_cellm[8];
            if (iBase < n && jBase + 511 > iBase) {
                for (int k = t; k < 512; k += 256) {
                    int j = jBase + k;
                    float4 v;
                    if (j < n) v = g_fracA[j];
                    else { v.x = 1e18f; v.y = 1e18f; v.z = 1e18f; v.w = 0.0f; }
                    sjn[k] = v;
                }
                __syncthreads();
                int i = iBase + t;
                if (i < n) {
                    float4 pi = g_fracA[i];
                    int kmin = i - jBase + 1; if (kmin < 0) kmin = 0;
                    int kmax = n - jBase; if (kmax > 512) kmax = 512;
                    for (int k = kmin; k < kmax; k++) {
                        float4 pj = sjn[k];
                        float fx = pi.x - pj.x; fx -= rintf(fx);
                        float fy = pi.y - pj.y; fy -= rintf(fy);
                        float fz = pi.z - pj.z; fz -= rintf(fz);
                        float dx = fx*c0 + fy*c3 + fz*c6;
                        float dy = fx*c1 + fy*c4 + fz*c7;
                        float dz = fx*c2 + fy*c5 + fz*c8;
                        float d2 = dx*dx + dy*dy + dz*dz;
                        if (d2 < d2max) {
                            float dist = sqrtf(d2);
                            float x  = fmaf(dist, invdr, binoff);
                            int   b0 = __float2int_rd(x);
                            if ((unsigned)b0 < (unsigned)(nbins - 1)) {
                                float f = x - (float)b0;
                                float w = 2.0f * pi.w * pj.w;
                                atomicAdd(&shist[b0],     w * (1.0f - f));
                                atomicAdd(&shist[b0 + 1], w * f);
                            }
                        }
                    }
                }
                __syncthreads();
            }
        }
        __syncthreads();
        if (t < nbins && shist[t] != 0.0f) atomicAdd(&g_hist[t], (double)shist[t]);
    } else {
        // ===================== tetrahedral order parameter =====================
        int qb   = bx - pairBlocks;
        int gw   = qb * 8 + (t >> 5);       // Si-list index
        int lane = t & 31;
        int wib  = t >> 5;
        int nSi  = g_nSi;

        const float i0v = g_inv[0], i1v = g_inv[1], i2v = g_inv[2];
        const float i3v = g_inv[3], i4v = g_inv[4], i5v = g_inv[5];
        const float i6v = g_inv[6], i7v = g_inv[7], i8v = g_inv[8];
        const float c0 = g_cellm[0], c1 = g_cellm[1], c2 = g_cellm[2];
        const float c3 = g_cellm[3], c4 = g_cellm[4], c5 = g_cellm[5];
        const float c6 = g_cellm[6], c7 = g_cellm[7], c8 = g_cellm[8];
        const float rsafe  = g_rsafe;
        const int   cellok = g_cellok;
        const float INF = 3.402823466e38f;

        float qi = 0.0f;
        int   vf = 0;

        if (gw < nSi) {
            int slot = g_siSlot[gw];
            int i    = g_sorig[slot];
            float4 ci = g_scart[slot];
            float pix = pos[3*i], piy = pos[3*i+1], piz = pos[3*i+2];
            float seld2[4]; int selj[4];
            bool valid = false;

            if (cellok) {
                int c  = g_siCell[gw];
                int cx = c & 7, cy = (c >> 3) & 7, cz = c >> 6;
                float bd2[4] = {INF, INF, INF, INF};
                int   bj [4] = {0x7fffffff, 0x7fffffff, 0x7fffffff, 0x7fffffff};
                int found = 0;
                if (lane < 27) {
                    int ox = lane % 3 - 1, oy = (lane / 3) % 3 - 1, oz = lane / 9 - 1;
                    int ucx = cx + ox, ucy = cy + oy, ucz = cz + oz;
                    int nc = (ucx & 7) | ((ucy & 7) << 3) | ((ucz & 7) << 6);
                    float wx = (float)((ucx < 0) ? -1 : (ucx >= CDIM ? 1 : 0));
                    float wy = (float)((ucy < 0) ? -1 : (ucy >= CDIM ? 1 : 0));
                    float wz = (float)((ucz < 0) ? -1 : (ucz >= CDIM ? 1 : 0));
                    float sx = wx*c0 + wy*c3 + wz*c6;
                    float sy = wx*c1 + wy*c4 + wz*c7;
                    float sz = wx*c2 + wy*c5 + wz*c8;
                    int st = g_cellStart[nc], en = g_cellStart[nc + 1];
                    for (int s = st; s < en; s++) {
                        float4 fj = g_scart[s];
                        if (fj.w == B_SI || s == slot) continue;
                        float dx = ci.x - (fj.x + sx);
                        float dy = ci.y - (fj.y + sy);
                        float dz = ci.z - (fj.z + sz);
                        float d2 = dx*dx + dy*dy + dz*dz;
                        found++;
                        insert4(bd2, bj, d2, g_sorig[s]);
                    }
                }
                int foundTot = __reduce_add_sync(0xffffffffu, found);
                warp_merge_top4(bd2, bj, lane, seld2, selj);
                valid = (foundTot >= 4) && (seld2[3] < rsafe * rsafe);
            }

            if (!valid) {
                // exact full-scan fallback
                float bd2[4] = {INF, INF, INF, INF};
                int   bj [4] = {0x7fffffff, 0x7fffffff, 0x7fffffff, 0x7fffffff};
                for (int j = lane; j < n; j += 32) {
                    if (j == i || species[j] == 0) continue;
                    float dx0 = pix - pos[3*j];
                    float dy0 = piy - pos[3*j+1];
                    float dz0 = piz - pos[3*j+2];
                    float fx = dx0*i0v + dy0*i3v + dz0*i6v;
                    float fy = dx0*i1v + dy0*i4v + dz0*i7v;
                    float fz = dx0*i2v + dy0*i5v + dz0*i8v;
                    fx -= rintf(fx); fy -= rintf(fy); fz -= rintf(fz);
                    float dx = fx*c0 + fy*c3 + fz*c6;
                    float dy = fx*c1 + fy*c4 + fz*c7;
                    float dz = fx*c2 + fy*c5 + fz*c8;
                    float d2 = dx*dx + dy*dy + dz*dz;
                    insert4(bd2, bj, d2, j);
                }
                warp_merge_top4(bd2, bj, lane, seld2, selj);
            }

            if (lane == 0 && selj[3] < n) {
                float ux[4], uy[4], uz[4], dmax = 0.0f;
                #pragma unroll
                for (int k = 0; k < 4; k++) {
                    int j = selj[k];
                    float dx0 = pix - pos[3*j];
                    float dy0 = piy - pos[3*j+1];
                    float dz0 = piz - pos[3*j+2];
                    float fx = dx0*i0v + dy0*i3v + dz0*i6v;
                    float fy = dx0*i1v + dy0*i4v + dz0*i7v;
                    float fz = dx0*i2v + dy0*i5v + dz0*i8v;
                    fx -= rintf(fx); fy -= rintf(fy); fz -= rintf(fz);
                    float dx = fx*c0 + fy*c3 + fz*c6;
                    float dy = fx*c1 + fy*c4 + fz*c7;
                    float dz = fx*c2 + fy*c5 + fz*c8;
                    float dist = sqrtf(seld2[k]);
                    dmax = fmaxf(dmax, dist);
                    ux[k] = dx / dist; uy[k] = dy / dist; uz[k] = dz / dist;
                }
                float s = 0.0f;
                #pragma unroll
                for (int k = 0; k < 4; k++)
                    #pragma unroll
                    for (int l = k + 1; l < 4; l++) {
                        float cc = ux[k]*ux[l] + uy[k]*uy[l] + uz[k]*uz[l];
                        float tt = cc + (1.0f / 3.0f);
                        s += tt * tt;
                    }
                if (dmax < CUTOFF) { qi = 1.0f - 0.375f * s; vf = 1; }
            }
        }

        __shared__ double s_q[8];
        __shared__ int    s_v[8];
        if (lane == 0) { s_q[wib] = (double)qi; s_v[wib] = vf; }
        __syncthreads();
        if (t == 0) {
            double qs = 0.0; int vs = 0;
            #pragma unroll
            for (int k = 0; k < 8; k++) { qs += s_q[k]; vs += s_v[k]; }
            if (vs > 0) {
                atomicAdd(&g_qsum, qs);
                atomicAdd(&g_vfsum, (double)vs);
            }
        }
    }
}

// ---------------- final: G/T/q_tet (block 0) + S(Q) (all); last block resets --------
__global__ void __launch_bounds__(256)
final_kernel(const float* __restrict__ rbins, const float* __restrict__ qbins,
             float* __restrict__ out, int n, int nbins, int nq) {
    __shared__ float integ[256];
    __shared__ int   sLast;
    int t = threadIdx.x;
    float rho = g_rho, dr = g_dr, mb = g_meanb;
    if (t < nbins) {
        float r     = rbins[t];
        float shell = 4.0f * PI_F * r * r * dr;
        float hv    = (float)g_hist[t] / (mb * mb);
        float G     = hv / ((float)n * rho * shell);
        integ[t] = r * r * (G - 1.0f);
        if (blockIdx.x == 0) {
            out[t]         = G;
            out[nbins + t] = 4.0f * PI_F * rho * r * G;
        }
    }
    if (blockIdx.x == 0 && t == 0) {
        double denom = g_vfsum > 1.0 ? g_vfsum : 1.0;
        out[2 * nbins + nq] = (float)(g_qsum / denom);
    }
    __syncthreads();
    int warp = t >> 5, lane = t & 31;
    int qidx = blockIdx.x * 8 + warp;
    if (qidx < nq) {
        float q = qbins[qidx];
        float s = 0.0f;
        for (int k = lane; k < nbins; k += 32) {
            float px = q * rbins[k];               // sinc(qr/pi) = sin(qr)/(qr)
            float sc = (px == 0.0f) ? 1.0f : __fdividef(__sinf(px), px);
            s += integ[k] * sc;
        }
        #pragma unroll
        for (int o = 16; o > 0; o >>= 1) s += __shfl_down_sync(0xffffffffu, s, o);
        if (lane == 0) out[2 * nbins + qidx] = 1.0f + 4.0f * PI_F * rho * dr * s;
    }
    // last-arriving block resets replay-invariant accumulators
    __syncthreads();
    if (t == 0) {
        __threadfence();
        int v = atomicAdd(&g_arriveF, 1);
        sLast = (v == (int)gridDim.x - 1) ? 1 : 0;
    }
    __syncthreads();
    if (sLast) {
        if (t < 256) g_hist[t] = 0.0;
        if (t == 0) {
            g_qsum = 0.0; g_vfsum = 0.0;
            g_arriveF = 0; g_nSi = 0;
        }
    }
}

// ---------------- launch ------------------------------------------------------------
extern "C" void kernel_launch(void* const* d_in, const int* in_sizes, int n_in,
                              void* d_out, int out_size) {
    const float* pos     = (const float*)d_in[0];
    const float* cell    = (const float*)d_in[1];
    const float* rbins   = (const float*)d_in[2];
    const float* qbins   = (const float*)d_in[3];
    const int*   species = (const int*)  d_in[4];
    int n     = in_sizes[0] / 3;
    int nbins = in_sizes[2];
    int nq    = in_sizes[3];

    int ablocks = (n + 127) / 128;
    assign_kernel<<<ablocks, 128>>>(pos, cell, rbins, species, n, nbins);
    scatter_kernel<<<ablocks, 128>>>(n);

    int tilesI = (n + 255) / 256, tilesJ = (n + 511) / 512;
    int pairBlocks = tilesI * tilesJ;
    if (pairBlocks < NCELLS) pairBlocks = NCELLS;
    int qtetBlocks = (n + 7) / 8;       // 8 warps/block; extra warps exit on g_nSi
    main_kernel<<<pairBlocks + qtetBlocks, 256>>>(pos, species, n, nbins, pairBlocks);

    final_kernel<<<(nq + 7) / 8, 256>>>(rbins, qbins, (float*)d_out, n, nbins, nq);
}

// round 10
// speedup vs baseline: 5.9068x; 1.0656x over previous
#include <cuda_runtime.h>
#include <math.h>

#define B_SI 4.1491f
#define B_O  5.803f
#define CUTOFF 3.5f
#define PI_F 3.14159274101257324f   // (float)M_PI

#define CDIM   8
#define NCELLS 512                  // CDIM^3
#define CCAP   32                   // fixed capacity per cell
#define NMAX   8192

// ---------------- f32x2 packed helpers (sm_100+) -----------------------------------
#define PK2(out, lo, hi) asm("mov.b64 %0, {%1, %2};" : "=l"(out) : "f"(lo), "f"(hi))
#define UNPK2(lo, hi, in) asm("mov.b64 {%0, %1}, %2;" : "=f"(lo), "=f"(hi) : "l"(in))
#define ADD2(d, a, b) asm("add.rn.f32x2 %0, %1, %2;" : "=l"(d) : "l"(a), "l"(b))
#define MUL2(d, a, b) asm("mul.rn.f32x2 %0, %1, %2;" : "=l"(d) : "l"(a), "l"(b))
#define FMA2(d, a, b, c) asm("fma.rn.f32x2 %0, %1, %2, %3;" : "=l"(d) : "l"(a), "l"(b), "l"(c))

// ---------------- device globals (scratch; no allocations allowed) ----------------
__device__ float  g_inv[9];
__device__ float  g_cellm[9];
__device__ float  g_rho, g_meanb, g_r0, g_dr, g_rsafe;
__device__ int    g_cellok;
__device__ double g_hist[256];        // zero at start; re-zeroed by final_kernel
__device__ double g_qsum, g_vfsum;    // same invariant
__device__ int    g_arriveA, g_arriveF, g_nSi, g_nSiTot, g_overflow;

__device__ float4 g_fracA[NMAX];                 // per ORIGINAL atom (brute fallback)
__device__ float4 g_scart[NCELLS * CCAP];        // slotted cartesian (wrapped) + b
__device__ int    g_sorig[NCELLS * CCAP];
__device__ int    g_siSlot[NMAX];                // slots of Si atoms
__device__ int    g_siCell[NMAX];
__device__ int    g_cellCnt[NCELLS];             // zero at start; re-zeroed by final

// ---------------- helpers ----------------------------------------------------------
__device__ __forceinline__ void insert4(float bd2[4], int bj[4], float dd, int jj) {
    if (dd < bd2[3]) {
        #pragma unroll
        for (int k = 0; k < 4; k++) {
            if (dd < bd2[k]) {
                float td = bd2[k]; bd2[k] = dd; dd = td;
                int   tj = bj[k];  bj[k]  = jj; jj = tj;
            }
        }
    }
}

__device__ __forceinline__ void warp_merge_top4(float bd2[4], int bj[4], int lane,
                                                float seld2[4], int selj[4]) {
    const float INF = 3.402823466e38f;
    int ptr = 0;
    #pragma unroll
    for (int r = 0; r < 4; r++) {
        float mv = (ptr < 4) ? bd2[ptr] : INF;
        int   mj = (ptr < 4) ? bj[ptr]  : 0x7fffffff;
        int   ml = lane;
        #pragma unroll
        for (int o = 16; o > 0; o >>= 1) {
            float ov = __shfl_down_sync(0xffffffffu, mv, o);
            int   oj = __shfl_down_sync(0xffffffffu, mj, o);
            int   ol = __shfl_down_sync(0xffffffffu, ml, o);
            if (ov < mv || (ov == mv && oj < mj)) { mv = ov; mj = oj; ml = ol; }
        }
        mv = __shfl_sync(0xffffffffu, mv, 0);
        mj = __shfl_sync(0xffffffffu, mj, 0);
        ml = __shfl_sync(0xffffffffu, ml, 0);
        if (lane == ml) ptr++;
        seld2[r] = mv; selj[r] = mj;
    }
}

__device__ __forceinline__ void compute_inv(const float a[9], float iv[9], float* det_out) {
    float c00 = a[4]*a[8] - a[5]*a[7];
    float c01 = a[5]*a[6] - a[3]*a[8];
    float c02 = a[3]*a[7] - a[4]*a[6];
    float det = a[0]*c00 + a[1]*c01 + a[2]*c02;
    float id  = 1.0f / det;
    iv[0] = c00*id;  iv[3] = c01*id;  iv[6] = c02*id;
    iv[1] = (a[2]*a[7] - a[1]*a[8])*id;
    iv[4] = (a[0]*a[8] - a[2]*a[6])*id;
    iv[7] = (a[1]*a[6] - a[0]*a[7])*id;
    iv[2] = (a[1]*a[5] - a[2]*a[4])*id;
    iv[5] = (a[2]*a[3] - a[0]*a[5])*id;
    iv[8] = (a[0]*a[4] - a[1]*a[3])*id;
    *det_out = det;
}

// ---------------- assign: frac + DIRECT slotted scatter; last block does scalars ----
__global__ void __launch_bounds__(128)
assign_kernel(const float* __restrict__ pos, const float* __restrict__ cell,
              const float* __restrict__ rbins, const int* __restrict__ species,
              int n, int nbins) {
    __shared__ float s_inv[9], s_cell[9];
    __shared__ int   sLast;

    int t = threadIdx.x;
    if (t == 0) {
        float a[9], iv[9], det;
        #pragma unroll
        for (int k = 0; k < 9; k++) { a[k] = cell[k]; s_cell[k] = a[k]; }
        compute_inv(a, iv, &det);
        #pragma unroll
        for (int k = 0; k < 9; k++) s_inv[k] = iv[k];
    }
    __syncthreads();

    int i = blockIdx.x * 128 + t;
    if (i < n) {
        float px = pos[3*i], py = pos[3*i+1], pz = pos[3*i+2];
        float fx = px*s_inv[0] + py*s_inv[3] + pz*s_inv[6];
        float fy = px*s_inv[1] + py*s_inv[4] + pz*s_inv[7];
        float fz = px*s_inv[2] + py*s_inv[5] + pz*s_inv[8];
        fx -= floorf(fx); fy -= floorf(fy); fz -= floorf(fz);
        int cx = min((int)(fx * (float)CDIM), CDIM - 1);
        int cy = min((int)(fy * (float)CDIM), CDIM - 1);
        int cz = min((int)(fz * (float)CDIM), CDIM - 1);
        int c  = cx | (cy << 3) | (cz << 6);
        int isSi = (species[i] == 0);
        float b = isSi ? B_SI : B_O;
        float4 fr; fr.x = fx; fr.y = fy; fr.z = fz; fr.w = b;
        g_fracA[i] = fr;                    // brute-path copy
        if (isSi) atomicAdd(&g_nSiTot, 1);
        int rank = atomicAdd(&g_cellCnt[c], 1);
        if (rank < CCAP) {
            int s = c * CCAP + rank;
            float4 cc;
            cc.x = fr.x*s_cell[0] + fr.y*s_cell[3] + fr.z*s_cell[6];
            cc.y = fr.x*s_cell[1] + fr.y*s_cell[4] + fr.z*s_cell[7];
            cc.z = fr.x*s_cell[2] + fr.y*s_cell[5] + fr.z*s_cell[8];
            cc.w = b;
            g_scart[s] = cc;
            g_sorig[s] = i;
            if (isSi) {
                int k = atomicAdd(&g_nSi, 1);
                g_siSlot[k] = s;
                g_siCell[k] = c;
            }
        } else {
            atomicExch(&g_overflow, 1);     // degenerate density -> brute path
        }
    }
    __syncthreads();
    if (t == 0) {
        __threadfence();
        int v = atomicAdd(&g_arriveA, 1);
        sLast = (v == (int)gridDim.x - 1) ? 1 : 0;
    }
    __syncthreads();
    if (!sLast || t != 0) return;

    // ---------- scalar prep (one thread; everything else already in place) ----------
    float a[9], iv[9], det;
    #pragma unroll
    for (int k = 0; k < 9; k++) { a[k] = cell[k]; g_cellm[k] = a[k]; }
    compute_inv(a, iv, &det);
    #pragma unroll
    for (int k = 0; k < 9; k++) g_inv[k] = iv[k];
    float adet = fabsf(det);
    g_rho = (float)n / adet;
    float r0 = rbins[0], dr = rbins[1] - rbins[0];
    g_r0 = r0; g_dr = dr;
    float c00 = a[4]*a[8]-a[5]*a[7], c10 = a[5]*a[6]-a[3]*a[8], c20 = a[3]*a[7]-a[4]*a[6];
    float n1 = sqrtf(c00*c00 + c10*c10 + c20*c20);
    float x31x = a[7]*a[2]-a[8]*a[1], x31y = a[8]*a[0]-a[6]*a[2], x31z = a[6]*a[1]-a[7]*a[0];
    float n2 = sqrtf(x31x*x31x + x31y*x31y + x31z*x31z);
    float x12x = a[1]*a[5]-a[2]*a[4], x12y = a[2]*a[3]-a[0]*a[5], x12z = a[0]*a[4]-a[1]*a[3];
    float n3 = sqrtf(x12x*x12x + x12y*x12y + x12z*x12z);
    float pmin = fminf(adet/n1, fminf(adet/n2, adet/n3));
    float rmax = r0 + (float)(nbins - 1) * dr;
    g_cellok = (rmax * (float)CDIM * 0.5f <= pmin && g_overflow == 0) ? 1 : 0;
    g_rsafe  = pmin / (float)CDIM;
    int nSiT = g_nSiTot;
    g_meanb  = ((float)nSiT * B_SI + (float)(n - nSiT) * B_O) / (float)n;
    g_arriveA = 0;
}

// ---------------- main: pair histogram (bx < pairBlocks) + qtet (rest) -------------
__global__ void __launch_bounds__(256)
main_kernel(const float* __restrict__ pos, const int* __restrict__ species,
            int n, int nbins, int pairBlocks) {
    int bx = blockIdx.x;
    int t  = threadIdx.x;

    if (bx < pairBlocks) {
        // ===================== pair histogram =====================
        const int cellok = g_cellok;
        if (cellok && bx >= NCELLS) return;

        __shared__ unsigned long long scx[128], scy[128], scz[128];
        __shared__ float  scw[256];
        __shared__ float4 sjn[512];
        __shared__ float  shist[256];
        __shared__ int    nbS[63], nbCnt[63];
        __shared__ int    nbCum[64];
        __shared__ float  shx[63], shy[63], shz[63];

        shist[t] = 0.0f;

        const float r0 = g_r0, dr = g_dr;
        const float rmax  = r0 + (float)(nbins - 1) * dr;
        const float d2max = rmax * rmax + 0.01f;
        const float invdr = 1.0f / dr;
        const float binoff = -r0 * invdr;

        if (cellok) {
            int c  = bx;
            int cx = c & 7, cy = (c >> 3) & 7, cz = c >> 6;
            if (t < 63) {
                int tt = 62 + t;                    // t=0 -> self, t>0 -> positive half
                int ox = tt % 5 - 2, oy = (tt / 5) % 5 - 2, oz = tt / 25 - 2;
                int ucx = cx + ox, ucy = cy + oy, ucz = cz + oz;
                int nc = (ucx & 7) | ((ucy & 7) << 3) | ((ucz & 7) << 6);
                nbS[t]   = nc * CCAP;
                nbCnt[t] = g_cellCnt[nc];
                float wx = (float)((ucx < 0) ? -1 : (ucx >= CDIM ? 1 : 0));
                float wy = (float)((ucy < 0) ? -1 : (ucy >= CDIM ? 1 : 0));
                float wz = (float)((ucz < 0) ? -1 : (ucz >= CDIM ? 1 : 0));
                shx[t] = wx*g_cellm[0] + wy*g_cellm[3] + wz*g_cellm[6];
                shy[t] = wx*g_cellm[1] + wy*g_cellm[4] + wz*g_cellm[7];
                shz[t] = wx*g_cellm[2] + wy*g_cellm[5] + wz*g_cellm[8];
            }
            __syncthreads();
            // warp-shuffle exclusive scan over 63 counts (lane k -> cells 2k, 2k+1)
            if (t < 32) {
                int a  = nbCnt[2*t];
                int bb = (2*t + 1 < 63) ? nbCnt[2*t + 1] : 0;
                int s  = a + bb;
                int v  = s;
                #pragma unroll
                for (int o = 1; o < 32; o <<= 1) {
                    int u = __shfl_up_sync(0xffffffffu, v, o);
                    if (t >= o) v += u;
                }
                int ex = v - s;
                nbCum[2*t] = ex;
                if (2*t + 1 < 63) nbCum[2*t + 1] = ex + a;
                if (t == 31) nbCum[63] = ex + a;    // total (lane 31 owns cell 62 only)
            }
            __syncthreads();
            int total     = nbCum[63];
            int selfStart = nbS[0];
            int nC        = nbCnt[0];              // self count
            int nCp       = (nC + 1) >> 1;

            // stage centers as packed SoA (pad odd with far sentinel, weight 0)
            for (int p = t; p < nCp; p += 256) {
                float4 a = g_scart[selfStart + 2*p];
                float4 bb;
                if (2*p + 1 < nC) bb = g_scart[selfStart + 2*p + 1];
                else { bb.x = 1e9f; bb.y = 1e9f; bb.z = 1e9f; bb.w = 0.0f; }
                unsigned long long ux, uy, uz;
                PK2(ux, a.x, bb.x); PK2(uy, a.y, bb.y); PK2(uz, a.z, bb.z);
                scx[p] = ux; scy[p] = uy; scz[p] = uz;
                scw[2*p]     = 2.0f * a.w;
                scw[2*p + 1] = 2.0f * bb.w;
            }
            __syncthreads();

            // ---- self-cell triangle (scalar, tiny) ----
            int npairs = nC * (nC - 1) / 2;
            for (int idx = t; idx < npairs; idx += 256) {
                int gj = (int)((1.0f + sqrtf(1.0f + 8.0f * (float)idx)) * 0.5f);
                while (gj * (gj - 1) / 2 > idx) gj--;
                while ((gj + 1) * gj / 2 <= idx) gj++;
                int ii = idx - gj * (gj - 1) / 2;
                float4 pi = g_scart[selfStart + ii];
                float4 pj = g_scart[selfStart + gj];
                float dx = pi.x - pj.x, dy = pi.y - pj.y, dz = pi.z - pj.z;
                float d2 = dx*dx + dy*dy + dz*dz;
                if (d2 < d2max) {
                    float dist;
                    asm("sqrt.approx.f32 %0, %1;" : "=f"(dist) : "f"(d2));
                    float x  = fmaf(dist, invdr, binoff);
                    int   b0 = __float2int_rd(x);
                    if ((unsigned)b0 < (unsigned)(nbins - 1)) {
                        float f = x - (float)b0;
                        float w = 2.0f * pi.w * pj.w;
                        atomicAdd(&shist[b0],     w * (1.0f - f));
                        atomicAdd(&shist[b0 + 1], w * f);
                    }
                }
            }

            // ---- main loop: centers (packed) vs 62 half-neighborhood cells ----
            for (int base = nC; base < total; base += 512) {
                int lim = min(512, total - base);
                // stage chunk of neighborhood NEGATED with wrap shifts applied
                for (int k = t; k < lim; k += 256) {
                    int gj = base + k;
                    int lo = 0;
                    if (nbCum[lo + 32] <= gj) lo += 32;
                    if (nbCum[lo + 16] <= gj) lo += 16;
                    if (nbCum[lo +  8] <= gj) lo +=  8;
                    if (nbCum[lo +  4] <= gj) lo +=  4;
                    if (nbCum[lo +  2] <= gj) lo +=  2;
                    if (nbCum[lo +  1] <= gj) lo +=  1;
                    float4 p = g_scart[nbS[lo] + (gj - nbCum[lo])];
                    float4 q;
                    q.x = -(p.x + shx[lo]);
                    q.y = -(p.y + shy[lo]);
                    q.z = -(p.z + shz[lo]);
                    q.w = p.w;
                    sjn[k] = q;
                }
                __syncthreads();
                for (int k = t; k < lim; k += 256) {
                    float4 pj = sjn[k];
                    unsigned long long px2, py2, pz2;
                    PK2(px2, pj.x, pj.x);
                    PK2(py2, pj.y, pj.y);
                    PK2(pz2, pj.z, pj.z);
                    float pjw = pj.w;
                    #pragma unroll 2
                    for (int p = 0; p < nCp; p++) {
                        unsigned long long dx2, dy2, dz2, d2p;
                        ADD2(dx2, scx[p], px2);      // cen + (-pj) = cen - pj
                        ADD2(dy2, scy[p], py2);
                        ADD2(dz2, scz[p], pz2);
                        MUL2(d2p, dz2, dz2);
                        FMA2(d2p, dy2, dy2, d2p);
                        FMA2(d2p, dx2, dx2, d2p);
                        float d2lo, d2hi;
                        UNPK2(d2lo, d2hi, d2p);
                        if (d2lo < d2max) {
                            float dist;
                            asm("sqrt.approx.f32 %0, %1;" : "=f"(dist) : "f"(d2lo));
                            float x  = fmaf(dist, invdr, binoff);
                            int   b0 = __float2int_rd(x);
                            if ((unsigned)b0 < (unsigned)(nbins - 1)) {
                                float f = x - (float)b0;
                                float w = scw[2*p] * pjw;
                                atomicAdd(&shist[b0],     w * (1.0f - f));
                                atomicAdd(&shist[b0 + 1], w * f);
                            }
                        }
                        if (d2hi < d2max) {
                            float dist;
                            asm("sqrt.approx.f32 %0, %1;" : "=f"(dist) : "f"(d2hi));
                            float x  = fmaf(dist, invdr, binoff);
                            int   b0 = __float2int_rd(x);
                            if ((unsigned)b0 < (unsigned)(nbins - 1)) {
                                float f = x - (float)b0;
                                float w = scw[2*p + 1] * pjw;
                                atomicAdd(&shist[b0],     w * (1.0f - f));
                                atomicAdd(&shist[b0 + 1], w * f);
                            }
                        }
                    }
                }
                __syncthreads();
            }
        } else {
            // ---- brute fallback (general cells / degenerate) ----
            int tilesJ = (n + 511) >> 9;
            int ib = bx / tilesJ;
            int jb = bx % tilesJ;
            int iBase = ib * 256, jBase = jb * 512;
            const float c0 = g_cellm[0], c1 = g_cellm[1], c2 = g_cellm[2];
            const float c3 = g_cellm[3], c4 = g_cellm[4], c5 = g_cellm[5];
            const float c6 = g_cellm[6], c7 = g_cellm[7], c8 = g_cellm[8];
            if (iBase < n && jBase + 511 > iBase) {
                for (int k = t; k < 512; k += 256) {
                    int j = jBase + k;
                    float4 v;
                    if (j < n) v = g_fracA[j];
                    else { v.x = 1e18f; v.y = 1e18f; v.z = 1e18f; v.w = 0.0f; }
                    sjn[k] = v;
                }
                __syncthreads();
                int i = iBase + t;
                if (i < n) {
                    float4 pi = g_fracA[i];
                    int kmin = i - jBase + 1; if (kmin < 0) kmin = 0;
                    int kmax = n - jBase; if (kmax > 512) kmax = 512;
                    for (int k = kmin; k < kmax; k++) {
                        float4 pj = sjn[k];
                        float fx = pi.x - pj.x; fx -= rintf(fx);
                        float fy = pi.y - pj.y; fy -= rintf(fy);
                        float fz = pi.z - pj.z; fz -= rintf(fz);
                        float dx = fx*c0 + fy*c3 + fz*c6;
                        float dy = fx*c1 + fy*c4 + fz*c7;
                        float dz = fx*c2 + fy*c5 + fz*c8;
                        float d2 = dx*dx + dy*dy + dz*dz;
                        if (d2 < d2max) {
                            float dist = sqrtf(d2);
                            float x  = fmaf(dist, invdr, binoff);
                            int   b0 = __float2int_rd(x);
                            if ((unsigned)b0 < (unsigned)(nbins - 1)) {
                                float f = x - (float)b0;
                                float w = 2.0f * pi.w * pj.w;
                                atomicAdd(&shist[b0],     w * (1.0f - f));
                                atomicAdd(&shist[b0 + 1], w * f);
                            }
                        }
                    }
                }
                __syncthreads();
            }
        }
        __syncthreads();
        if (t < nbins && shist[t] != 0.0f) atomicAdd(&g_hist[t], (double)shist[t]);
    } else {
        // ===================== tetrahedral order parameter =====================
        int qb   = bx - pairBlocks;
        int gw   = qb * 8 + (t >> 5);
        int lane = t & 31;
        int wib  = t >> 5;

        const float i0v = g_inv[0], i1v = g_inv[1], i2v = g_inv[2];
        const float i3v = g_inv[3], i4v = g_inv[4], i5v = g_inv[5];
        const float i6v = g_inv[6], i7v = g_inv[7], i8v = g_inv[8];
        const float c0 = g_cellm[0], c1 = g_cellm[1], c2 = g_cellm[2];
        const float c3 = g_cellm[3], c4 = g_cellm[4], c5 = g_cellm[5];
        const float c6 = g_cellm[6], c7 = g_cellm[7], c8 = g_cellm[8];
        const float rsafe  = g_rsafe;
        const int   cellok = g_cellok;
        const float INF = 3.402823466e38f;

        float qi = 0.0f;
        int   vf = 0;

        int i = -1, slot = -1, ccell = -1;
        float4 ci = {0.f, 0.f, 0.f, 0.f};
        if (cellok) {
            if (gw < g_nSi) {
                slot  = g_siSlot[gw];
                ccell = g_siCell[gw];
                i     = g_sorig[slot];
                ci    = g_scart[slot];
            }
        } else {
            if (gw < n && species[gw] == 0) i = gw;
        }

        if (i >= 0) {
            float pix = pos[3*i], piy = pos[3*i+1], piz = pos[3*i+2];
            float seld2[4]; int selj[4];
            bool valid = false;

            if (cellok) {
                int cx = ccell & 7, cy = (ccell >> 3) & 7, cz = ccell >> 6;
                float bd2[4] = {INF, INF, INF, INF};
                int   bj [4] = {0x7fffffff, 0x7fffffff, 0x7fffffff, 0x7fffffff};
                int found = 0;
                if (lane < 27) {
                    int ox = lane % 3 - 1, oy = (lane / 3) % 3 - 1, oz = lane / 9 - 1;
                    int ucx = cx + ox, ucy = cy + oy, ucz = cz + oz;
                    int nc = (ucx & 7) | ((ucy & 7) << 3) | ((ucz & 7) << 6);
                    float wx = (float)((ucx < 0) ? -1 : (ucx >= CDIM ? 1 : 0));
                    float wy = (float)((ucy < 0) ? -1 : (ucy >= CDIM ? 1 : 0));
                    float wz = (float)((ucz < 0) ? -1 : (ucz >= CDIM ? 1 : 0));
                    float sx = wx*c0 + wy*c3 + wz*c6;
                    float sy = wx*c1 + wy*c4 + wz*c7;
                    float sz = wx*c2 + wy*c5 + wz*c8;
                    int st = nc * CCAP, en = st + g_cellCnt[nc];
                    for (int s = st; s < en; s++) {
                        float4 fj = g_scart[s];
                        if (fj.w == B_SI || s == slot) continue;
                        float dx = ci.x - (fj.x + sx);
                        float dy = ci.y - (fj.y + sy);
                        float dz = ci.z - (fj.z + sz);
                        float d2 = dx*dx + dy*dy + dz*dz;
                        found++;
                        insert4(bd2, bj, d2, g_sorig[s]);
                    }
                }
                int foundTot = __reduce_add_sync(0xffffffffu, found);
                warp_merge_top4(bd2, bj, lane, seld2, selj);
                valid = (foundTot >= 4) && (seld2[3] < rsafe * rsafe);
            }

            if (!valid) {
                // exact full-scan fallback
                float bd2[4] = {INF, INF, INF, INF};
                int   bj [4] = {0x7fffffff, 0x7fffffff, 0x7fffffff, 0x7fffffff};
                for (int j = lane; j < n; j += 32) {
                    if (j == i || species[j] == 0) continue;
                    float dx0 = pix - pos[3*j];
                    float dy0 = piy - pos[3*j+1];
                    float dz0 = piz - pos[3*j+2];
                    float fx = dx0*i0v + dy0*i3v + dz0*i6v;
                    float fy = dx0*i1v + dy0*i4v + dz0*i7v;
                    float fz = dx0*i2v + dy0*i5v + dz0*i8v;
                    fx -= rintf(fx); fy -= rintf(fy); fz -= rintf(fz);
                    float dx = fx*c0 + fy*c3 + fz*c6;
                    float dy = fx*c1 + fy*c4 + fz*c7;
                    float dz = fx*c2 + fy*c5 + fz*c8;
                    float d2 = dx*dx + dy*dy + dz*dz;
                    insert4(bd2, bj, d2, j);
                }
                warp_merge_top4(bd2, bj, lane, seld2, selj);
            }

            if (lane == 0 && selj[3] < n) {
                float ux[4], uy[4], uz[4], dmax = 0.0f;
                #pragma unroll
                for (int k = 0; k < 4; k++) {
                    int j = selj[k];
                    float dx0 = pix - pos[3*j];
                    float dy0 = piy - pos[3*j+1];
                    float dz0 = piz - pos[3*j+2];
                    float fx = dx0*i0v + dy0*i3v + dz0*i6v;
                    float fy = dx0*i1v + dy0*i4v + dz0*i7v;
                    float fz = dx0*i2v + dy0*i5v + dz0*i8v;
                    fx -= rintf(fx); fy -= rintf(fy); fz -= rintf(fz);
                    float dx = fx*c0 + fy*c3 + fz*c6;
                    float dy = fx*c1 + fy*c4 + fz*c7;
                    float dz = fx*c2 + fy*c5 + fz*c8;
                    float dist = sqrtf(seld2[k]);
                    dmax = fmaxf(dmax, dist);
                    ux[k] = dx / dist; uy[k] = dy / dist; uz[k] = dz / dist;
                }
                float s = 0.0f;
                #pragma unroll
                for (int k = 0; k < 4; k++)
                    #pragma unroll
                    for (int l = k + 1; l < 4; l++) {
                        float cc = ux[k]*ux[l] + uy[k]*uy[l] + uz[k]*uz[l];
                        float tt = cc + (1.0f / 3.0f);
                        s += tt * tt;
                    }
                if (dmax < CUTOFF) { qi = 1.0f - 0.375f * s; vf = 1; }
            }
        }

        __shared__ double s_q[8];
        __shared__ int    s_v[8];
        if (lane == 0) { s_q[wib] = (double)qi; s_v[wib] = vf; }
        __syncthreads();
        if (t == 0) {
            double qs = 0.0; int vs = 0;
            #pragma unroll
            for (int k = 0; k < 8; k++) { qs += s_q[k]; vs += s_v[k]; }
            if (vs > 0) {
                atomicAdd(&g_qsum, qs);
                atomicAdd(&g_vfsum, (double)vs);
            }
        }
    }
}

// ---------------- final: G/T/q_tet (block 0) + S(Q) (all); last block resets --------
__global__ void __launch_bounds__(256)
final_kernel(const float* __restrict__ rbins, const float* __restrict__ qbins,
             float* __restrict__ out, int n, int nbins, int nq) {
    __shared__ float integ[256];
    __shared__ int   sLast;
    int t = threadIdx.x;
    float rho = g_rho, dr = g_dr, mb = g_meanb;
    if (t < nbins) {
        float r     = rbins[t];
        float shell = 4.0f * PI_F * r * r * dr;
        float hv    = (float)g_hist[t] / (mb * mb);
        float G     = hv / ((float)n * rho * shell);
        integ[t] = r * r * (G - 1.0f);
        if (blockIdx.x == 0) {
            out[t]         = G;
            out[nbins + t] = 4.0f * PI_F * rho * r * G;
        }
    }
    if (blockIdx.x == 0 && t == 0) {
        double denom = g_vfsum > 1.0 ? g_vfsum : 1.0;
        out[2 * nbins + nq] = (float)(g_qsum / denom);
    }
    __syncthreads();
    int warp = t >> 5, lane = t & 31;
    int qidx = blockIdx.x * 8 + warp;
    if (qidx < nq) {
        float q = qbins[qidx];
        float s = 0.0f;
        for (int k = lane; k < nbins; k += 32) {
            float px = q * rbins[k];               // sinc(qr/pi) = sin(qr)/(qr)
            float sc = (px == 0.0f) ? 1.0f : __fdividef(__sinf(px), px);
            s += integ[k] * sc;
        }
        #pragma unroll
        for (int o = 16; o > 0; o >>= 1) s += __shfl_down_sync(0xffffffffu, s, o);
        if (lane == 0) out[2 * nbins + qidx] = 1.0f + 4.0f * PI_F * rho * dr * s;
    }
    // last-arriving block resets replay-invariant accumulators
    __syncthreads();
    if (t == 0) {
        __threadfence();
        int v = atomicAdd(&g_arriveF, 1);
        sLast = (v == (int)gridDim.x - 1) ? 1 : 0;
    }
    __syncthreads();
    if (sLast) {
        if (t < 256) g_hist[t] = 0.0;
        g_cellCnt[t] = 0;
        g_cellCnt[t + 256] = 0;
        if (t == 0) {
            g_qsum = 0.0; g_vfsum = 0.0;
            g_arriveF = 0; g_nSi = 0; g_nSiTot = 0; g_overflow = 0;
        }
    }
}

// ---------------- launch ------------------------------------------------------------
extern "C" void kernel_launch(void* const* d_in, const int* in_sizes, int n_in,
                              void* d_out, int out_size) {
    const float* pos     = (const float*)d_in[0];
    const float* cell    = (const float*)d_in[1];
    const float* rbins   = (const float*)d_in[2];
    const float* qbins   = (const float*)d_in[3];
    const int*   species = (const int*)  d_in[4];
    int n     = in_sizes[0] / 3;
    int nbins = in_sizes[2];
    int nq    = in_sizes[3];

    int ablocks = (n + 127) / 128;
    assign_kernel<<<ablocks, 128>>>(pos, cell, rbins, species, n, nbins);

    int tilesI = (n + 255) / 256, tilesJ = (n + 511) / 512;
    int pairBlocks = tilesI * tilesJ;
    if (pairBlocks < NCELLS) pairBlocks = NCELLS;
    int qtetBlocks = (n + 7) / 8;       // 8 warps/block; extra warps exit early
    main_kernel<<<pairBlocks + qtetBlocks, 256>>>(pos, species, n, nbins, pairBlocks);

    final_kernel<<<(nq + 7) / 8, 256>>>(rbins, qbins, (float*)d_out, n, nbins, nq);
}